// round 6
// baseline (speedup 1.0000x reference)
#include <cuda_runtime.h>
#include <cuda_bf16.h>
#include <stdint.h>

typedef unsigned long long ull;

#define NU 100000
#define NI 100000
#define NN 200000
#define NE 4000000
#define UD 256
#define ID 128
#define CM 64
#define OD 32
#define SCAN_BLK 1024
#define NSCAN_BLKS ((NN + SCAN_BLK - 1) / SCAN_BLK)

// f32x2 packed helpers
#define FMA2(d, a, b, c) asm("fma.rn.f32x2 %0, %1, %2, %3;" : "=l"(d) : "l"(a), "l"(b), "l"(c))
#define PACK2(d, x)      asm("mov.b64 %0, {%1, %1};" : "=l"(d) : "f"(x))
#define UNPACK2(lo, hi, v) asm("mov.b64 {%0, %1}, %2;" : "=f"(lo), "=f"(hi) : "l"(v))

// ---------------- scratch ----------------
__device__ float g_deg[NN];
__device__ float g_dinv[NN];
__device__ int   g_count[NN];
__device__ int   g_rowstart[NN + 1];
__device__ int   g_cursor[NN];
__device__ int   g_bsum[SCAN_BLK];
__device__ ull   g_csr[NE];               // packed: lo32 = src, hi32 = norm bits
__device__ float g_WuW1[UD * CM];
__device__ float g_WiW1[ID * CM];
__device__ float g_cu[CM];
__device__ float g_ci[CM];
__device__ float g_h1[(size_t)NN * CM];   // 51.2 MB
__device__ float g_z1[(size_t)NN * CM];   // 51.2 MB
__device__ float g_h2[(size_t)NN * OD];   // 25.6 MB
__device__ int   g_is64;

// ---------------- dtype detection ----------------
__global__ void k_detect(const int* __restrict__ ei32) {
    __shared__ int any_nonzero;
    if (threadIdx.x == 0) any_nonzero = 0;
    __syncthreads();
    for (int i = 2 * threadIdx.x + 1; i < 4096; i += 2 * blockDim.x)
        if (ei32[i] != 0) any_nonzero = 1;
    __syncthreads();
    if (threadIdx.x == 0) g_is64 = any_nonzero ? 0 : 1;
}

__global__ void k_init() {
    int i = blockIdx.x * blockDim.x + threadIdx.x;
    if (i < NN) { g_deg[i] = 1.0f; g_count[i] = 0; }
}

// ---------------- weight folding ----------------
__global__ void k_wcomb(const float* __restrict__ Wu, const float* __restrict__ bu,
                        const float* __restrict__ Wi, const float* __restrict__ bi,
                        const float* __restrict__ W1) {
    int idx = blockIdx.x * blockDim.x + threadIdx.x;
    const int TOT_U = UD * CM, TOT_I = ID * CM;
    if (idx < TOT_U) {
        int k = idx / CM, c = idx % CM;
        float a = 0.f;
        #pragma unroll
        for (int j = 0; j < CM; j++) a += Wu[k * CM + j] * W1[j * CM + c];
        g_WuW1[idx] = a;
    } else if (idx < TOT_U + TOT_I) {
        int r = idx - TOT_U;
        int k = r / CM, c = r % CM;
        float a = 0.f;
        #pragma unroll
        for (int j = 0; j < CM; j++) a += Wi[k * CM + j] * W1[j * CM + c];
        g_WiW1[r] = a;
    } else if (idx < TOT_U + TOT_I + 2 * CM) {
        int r = idx - TOT_U - TOT_I;
        if (r < CM) {
            float a = 0.f;
            #pragma unroll
            for (int j = 0; j < CM; j++) a += bu[j] * W1[j * CM + r];
            g_cu[r] = a;
        } else {
            int c = r - CM;
            float a = 0.f;
            #pragma unroll
            for (int j = 0; j < CM; j++) a += bi[j] * W1[j * CM + c];
            g_ci[c] = a;
        }
    }
}

// ---------------- embed: 2 threads per node (32 cols each), f32x2, smem W tiles ----------------
#define EB_THREADS 256
#define EB_NODES   128          // nodes per block
#define EB_KC 16
__global__ __launch_bounds__(EB_THREADS)
void k_embed(const float* __restrict__ ut, const float* __restrict__ it, int userBlocks) {
    __shared__ ulonglong2 sW[EB_KC * 16];   // 16 rows x 64 cols = 4 KB
    bool isUser = (int)blockIdx.x < userBlocks;
    int blockLocal = isUser ? blockIdx.x : blockIdx.x - userBlocks;
    int half = threadIdx.x & 1;             // which 32-col half this thread owns
    int nodeLocal = blockLocal * EB_NODES + (threadIdx.x >> 1);
    int K = isUser ? UD : ID;
    int Ncnt = isUser ? NU : NI;
    const float* W = isUser ? g_WuW1 : g_WiW1;
    const float* cvec = isUser ? g_cu : g_ci;
    const float* inp = isUser ? ut : it;
    bool active = nodeLocal < Ncnt;
    const float* xrow = inp + (size_t)(active ? nodeLocal : 0) * K;

    ull acc[16];
    #pragma unroll
    for (int i = 0; i < 16; i++) acc[i] = 0ull;

    for (int kb = 0; kb < K; kb += EB_KC) {
        __syncthreads();
        sW[threadIdx.x] = ((const ulonglong2*)(W + (size_t)kb * CM))[threadIdx.x];
        __syncthreads();
        if (active) {
            float x[EB_KC];
            #pragma unroll
            for (int q = 0; q < EB_KC / 4; q++) {
                float4 v = ((const float4*)(xrow + kb))[q];
                x[4 * q] = v.x; x[4 * q + 1] = v.y; x[4 * q + 2] = v.z; x[4 * q + 3] = v.w;
            }
            #pragma unroll
            for (int k = 0; k < EB_KC; k++) {
                ull bk; PACK2(bk, x[k]);
                #pragma unroll
                for (int c4 = 0; c4 < 8; c4++) {
                    ulonglong2 w = sW[k * 16 + half * 8 + c4];
                    FMA2(acc[2 * c4],     bk, w.x, acc[2 * c4]);
                    FMA2(acc[2 * c4 + 1], bk, w.y, acc[2 * c4 + 1]);
                }
            }
        }
    }
    if (active) {
        int node = isUser ? nodeLocal : NU + nodeLocal;
        float4* orow = (float4*)(g_h1 + (size_t)node * CM + half * 32);
        const float4* cv4 = (const float4*)(cvec + half * 32);
        #pragma unroll
        for (int c4 = 0; c4 < 8; c4++) {
            float a, b, c, d;
            UNPACK2(a, b, acc[2 * c4]);
            UNPACK2(c, d, acc[2 * c4 + 1]);
            float4 cv = cv4[c4];
            float4 ov; ov.x = a + cv.x; ov.y = b + cv.y; ov.z = c + cv.z; ov.w = d + cv.w;
            orow[c4] = ov;
        }
    }
}

// ---------------- graph preprocessing ----------------
// 2 edges per thread; adjacent loads merge into int2/int4
__global__ void k_edge1(const int* __restrict__ ei32, const float* __restrict__ ew) {
    int t = blockIdx.x * blockDim.x + threadIdx.x;
    int e = 2 * t;
    if (e >= NE) return;
    int d0, d1;
    if (g_is64) {
        int4 v = *(const int4*)(ei32 + 2 * (NE + e));
        d0 = v.x; d1 = v.z;
    } else {
        int2 v = *(const int2*)(ei32 + NE + e);
        d0 = v.x; d1 = v.y;
    }
    float2 w = *(const float2*)(ew + e);
    atomicAdd(&g_count[d0], 1);
    atomicAdd(&g_deg[d0], w.x);
    atomicAdd(&g_count[d1], 1);
    atomicAdd(&g_deg[d1], w.y);
}

__global__ void k_scan1() {
    __shared__ int sh[SCAN_BLK];
    int t = threadIdx.x;
    int gid = blockIdx.x * SCAN_BLK + t;
    int v = (gid < NN) ? g_count[gid] : 0;
    sh[t] = v;
    __syncthreads();
    for (int off = 1; off < SCAN_BLK; off <<= 1) {
        int x = (t >= off) ? sh[t - off] : 0;
        __syncthreads();
        sh[t] += x;
        __syncthreads();
    }
    if (gid < NN) {
        g_rowstart[gid] = sh[t] - v;
        float dg = g_deg[gid];
        g_dinv[gid] = (dg > 0.0f) ? rsqrtf(dg) : 0.0f;
    }
    if (t == SCAN_BLK - 1) g_bsum[blockIdx.x] = sh[t];
}

__global__ void k_scan2() {
    __shared__ int sh[SCAN_BLK];
    int t = threadIdx.x;
    int v = (t < NSCAN_BLKS) ? g_bsum[t] : 0;
    sh[t] = v;
    __syncthreads();
    for (int off = 1; off < SCAN_BLK; off <<= 1) {
        int x = (t >= off) ? sh[t - off] : 0;
        __syncthreads();
        sh[t] += x;
        __syncthreads();
    }
    if (t < NSCAN_BLKS) g_bsum[t] = sh[t] - v;
}

__global__ void k_scan3() {
    int i = blockIdx.x * blockDim.x + threadIdx.x;
    if (i < NN) {
        int rs = g_rowstart[i] + g_bsum[i >> 10];
        g_rowstart[i] = rs;
        g_cursor[i] = rs;
    }
    if (i == 0) g_rowstart[NN] = NE;
}

__global__ void k_scatter(const int* __restrict__ ei32, const float* __restrict__ ew) {
    int e = blockIdx.x * blockDim.x + threadIdx.x;
    if (e >= NE) return;
    int s, d;
    if (g_is64) { s = ei32[2 * e]; d = ei32[2 * (NE + e)]; }
    else        { s = ei32[e];     d = ei32[NE + e]; }
    float nrm = g_dinv[s] * ew[e] * g_dinv[d];
    int pos = atomicAdd(&g_cursor[d], 1);
    g_csr[pos] = (ull)(unsigned)s | ((ull)__float_as_uint(nrm) << 32);
}

// ---------------- gather1: aggregate h1 + bias + relu -> z1 (warp/node, f32x2) ----------------
__global__ void k_gather1(const float* __restrict__ b1) {
    int t = threadIdx.x;
    int node = blockIdx.x * (blockDim.x >> 5) + (t >> 5);
    int lane = t & 31;
    if (node >= NN) return;

    const ull* h = (const ull*)g_h1;
    float dv = g_dinv[node];
    ull sw; PACK2(sw, dv * dv);
    ull zero = 0ull;
    ull acc; FMA2(acc, sw, h[(size_t)node * 32 + lane], zero);

    int e = g_rowstart[node], end = g_rowstart[node + 1];
    for (; e + 4 <= end; e += 4) {
        ull p0 = g_csr[e], p1 = g_csr[e + 1], p2 = g_csr[e + 2], p3 = g_csr[e + 3];
        int s0 = (int)(unsigned)p0, s1 = (int)(unsigned)p1;
        int s2 = (int)(unsigned)p2, s3 = (int)(unsigned)p3;
        ull v0 = h[(size_t)s0 * 32 + lane];
        ull v1 = h[(size_t)s1 * 32 + lane];
        ull v2 = h[(size_t)s2 * 32 + lane];
        ull v3 = h[(size_t)s3 * 32 + lane];
        float w0 = __uint_as_float((unsigned)(p0 >> 32));
        float w1 = __uint_as_float((unsigned)(p1 >> 32));
        float w2 = __uint_as_float((unsigned)(p2 >> 32));
        float w3 = __uint_as_float((unsigned)(p3 >> 32));
        ull q0, q1, q2, q3;
        PACK2(q0, w0); PACK2(q1, w1); PACK2(q2, w2); PACK2(q3, w3);
        FMA2(acc, q0, v0, acc);
        FMA2(acc, q1, v1, acc);
        FMA2(acc, q2, v2, acc);
        FMA2(acc, q3, v3, acc);
    }
    for (; e < end; e++) {
        ull p = g_csr[e];
        int s = (int)(unsigned)p;
        float w = __uint_as_float((unsigned)(p >> 32));
        ull q; PACK2(q, w);
        FMA2(acc, q, h[(size_t)s * 32 + lane], acc);
    }
    float ax, ay; UNPACK2(ax, ay, acc);
    float2 bb = ((const float2*)b1)[lane];
    float2 z;
    z.x = fmaxf(ax + bb.x, 0.0f);
    z.y = fmaxf(ay + bb.y, 0.0f);
    ((float2*)(g_z1 + (size_t)node * CM))[lane] = z;
}

// ---------------- xform: h2 = z1 @ W2 (per-thread node, f32x2) ----------------
#define XF_THREADS 256
__global__ __launch_bounds__(XF_THREADS)
void k_xform(const float* __restrict__ W2) {
    __shared__ ulonglong2 sW[CM * 8];   // 64 rows x 32 cols = 8 KB = 512 ulonglong2
    sW[threadIdx.x]       = ((const ulonglong2*)W2)[threadIdx.x];
    sW[threadIdx.x + 256] = ((const ulonglong2*)W2)[threadIdx.x + 256];
    __syncthreads();

    int node = blockIdx.x * XF_THREADS + threadIdx.x;
    if (node >= NN) return;
    const float* xrow = g_z1 + (size_t)node * CM;

    ull acc[16];
    #pragma unroll
    for (int i = 0; i < 16; i++) acc[i] = 0ull;

    #pragma unroll
    for (int kb = 0; kb < CM; kb += 16) {
        float x[16];
        #pragma unroll
        for (int q = 0; q < 4; q++) {
            float4 v = ((const float4*)(xrow + kb))[q];
            x[4 * q] = v.x; x[4 * q + 1] = v.y; x[4 * q + 2] = v.z; x[4 * q + 3] = v.w;
        }
        #pragma unroll
        for (int k = 0; k < 16; k++) {
            ull bk; PACK2(bk, x[k]);
            #pragma unroll
            for (int c4 = 0; c4 < 8; c4++) {
                ulonglong2 w = sW[(kb + k) * 8 + c4];
                FMA2(acc[2 * c4],     bk, w.x, acc[2 * c4]);
                FMA2(acc[2 * c4 + 1], bk, w.y, acc[2 * c4 + 1]);
            }
        }
    }
    float4* orow = (float4*)(g_h2 + (size_t)node * OD);
    #pragma unroll
    for (int c4 = 0; c4 < 8; c4++) {
        float a, b, c, d;
        UNPACK2(a, b, acc[2 * c4]);
        UNPACK2(c, d, acc[2 * c4 + 1]);
        float4 ov; ov.x = a; ov.y = b; ov.z = c; ov.w = d;
        orow[c4] = ov;
    }
}

// ---------------- gather2: aggregate h2 + b2 -> out (dual half-warp, f32x2) ----------------
__global__ void k_gather2(const float* __restrict__ b2, float* __restrict__ out) {
    int t = threadIdx.x;
    int node = blockIdx.x * (blockDim.x >> 5) + (t >> 5);
    int lane = t & 31;
    if (node >= NN) return;
    int half = lane >> 4;
    int c = lane & 15;

    const ull* h = (const ull*)g_h2;
    ull acc = 0ull;
    if (half == 0) {
        float dv = g_dinv[node];
        ull sw; PACK2(sw, dv * dv);
        ull zero = 0ull;
        FMA2(acc, sw, h[(size_t)node * 16 + c], zero);
    }
    int beg = g_rowstart[node], end = g_rowstart[node + 1];
    int e = beg + half;
    for (; e + 2 < end; e += 4) {
        ull p0 = g_csr[e], p1 = g_csr[e + 2];
        int s0 = (int)(unsigned)p0, s1 = (int)(unsigned)p1;
        ull v0 = h[(size_t)s0 * 16 + c];
        ull v1 = h[(size_t)s1 * 16 + c];
        float w0 = __uint_as_float((unsigned)(p0 >> 32));
        float w1 = __uint_as_float((unsigned)(p1 >> 32));
        ull q0, q1; PACK2(q0, w0); PACK2(q1, w1);
        FMA2(acc, q0, v0, acc);
        FMA2(acc, q1, v1, acc);
    }
    if (e < end) {
        ull p = g_csr[e];
        int s = (int)(unsigned)p;
        float w = __uint_as_float((unsigned)(p >> 32));
        ull q; PACK2(q, w);
        FMA2(acc, q, h[(size_t)s * 16 + c], acc);
    }
    float ax, ay; UNPACK2(ax, ay, acc);
    ax += __shfl_xor_sync(0xffffffffu, ax, 16);
    ay += __shfl_xor_sync(0xffffffffu, ay, 16);
    if (half == 0) {
        float2 bb = ((const float2*)b2)[c];
        float2 ov; ov.x = ax + bb.x; ov.y = ay + bb.y;
        ((float2*)(out + (size_t)node * OD))[c] = ov;
    }
}

// ---------------- launch ----------------
extern "C" void kernel_launch(void* const* d_in, const int* in_sizes, int n_in,
                              void* d_out, int out_size) {
    const float* ut = (const float*)d_in[0];
    const float* it = (const float*)d_in[1];
    const int*   ei = (const int*)d_in[2];
    const float* ew = (const float*)d_in[3];
    const float* Wu = (const float*)d_in[4];
    const float* bu = (const float*)d_in[5];
    const float* Wi = (const float*)d_in[6];
    const float* bi = (const float*)d_in[7];
    const float* W1 = (const float*)d_in[8];
    const float* b1 = (const float*)d_in[9];
    const float* W2 = (const float*)d_in[10];
    const float* b2 = (const float*)d_in[11];
    float*       out = (float*)d_out;

    int userBlocks = (NU + EB_NODES - 1) / EB_NODES;    // 782
    int itemBlocks = (NI + EB_NODES - 1) / EB_NODES;    // 782

    // launch order arranged so k_embed is the 4th launch (ncu capture slot)
    k_detect<<<1, 256>>>(ei);                                              // 1
    k_init<<<(NN + 255) / 256, 256>>>();                                   // 2
    k_wcomb<<<(UD * CM + ID * CM + 2 * CM + 127) / 128, 128>>>(Wu, bu, Wi, bi, W1); // 3
    k_embed<<<userBlocks + itemBlocks, EB_THREADS>>>(ut, it, userBlocks);  // 4  <- profiled
    k_edge1<<<(NE / 2 + 255) / 256, 256>>>(ei, ew);                        // 5
    k_scan1<<<NSCAN_BLKS, SCAN_BLK>>>();                                   // 6
    k_scan2<<<1, SCAN_BLK>>>();                                            // 7
    k_scan3<<<(NN + 255) / 256, 256>>>();                                  // 8
    k_scatter<<<(NE + 255) / 256, 256>>>(ei, ew);                          // 9
    k_gather1<<<NN / 8, 256>>>(b1);                                        // 10
    k_xform<<<(NN + XF_THREADS - 1) / XF_THREADS, XF_THREADS>>>(W2);       // 11
    k_gather2<<<NN / 8, 256>>>(b2, out);                                   // 12
}

// round 8
// speedup vs baseline: 1.1140x; 1.1140x over previous
#include <cuda_runtime.h>
#include <cuda_bf16.h>
#include <stdint.h>

typedef unsigned long long ull;

#define NU 100000
#define NI 100000
#define NN 200000
#define NE 4000000
#define UD 256
#define ID 128
#define CM 64
#define OD 32
#define SCAN_BLK 1024
#define NSCAN_BLKS ((NN + SCAN_BLK - 1) / SCAN_BLK)

// f32x2 packed helpers
#define FMA2(d, a, b, c) asm("fma.rn.f32x2 %0, %1, %2, %3;" : "=l"(d) : "l"(a), "l"(b), "l"(c))
#define PACK2(d, x)      asm("mov.b64 %0, {%1, %1};" : "=l"(d) : "f"(x))
#define UNPACK2(lo, hi, v) asm("mov.b64 {%0, %1}, %2;" : "=f"(lo), "=f"(hi) : "l"(v))

// ---------------- scratch ----------------
__device__ float g_deg[NN];
__device__ float g_dinv[NN];
__device__ int   g_count[NN];
__device__ int   g_rowstart[NN + 1];
__device__ int   g_cursor[NN];
__device__ int   g_bsum[SCAN_BLK];
__device__ ull   g_csr[NE];               // packed: lo32 = src, hi32 = norm bits
__device__ float g_WuW1[UD * CM];
__device__ float g_WiW1[ID * CM];
__device__ float g_cu[CM];
__device__ float g_ci[CM];
__device__ float g_h1[(size_t)NN * CM];   // 51.2 MB
__device__ float g_z1[(size_t)NN * CM];   // 51.2 MB
__device__ float g_h2[(size_t)NN * OD];   // 25.6 MB
__device__ int   g_is64;

// ---------------- dtype detection ----------------
__global__ void k_detect(const int* __restrict__ ei32) {
    __shared__ int any_nonzero;
    if (threadIdx.x == 0) any_nonzero = 0;
    __syncthreads();
    for (int i = 2 * threadIdx.x + 1; i < 4096; i += 2 * blockDim.x)
        if (ei32[i] != 0) any_nonzero = 1;
    __syncthreads();
    if (threadIdx.x == 0) g_is64 = any_nonzero ? 0 : 1;
}

__global__ void k_init() {
    int i = blockIdx.x * blockDim.x + threadIdx.x;
    if (i < NN) { g_deg[i] = 1.0f; g_count[i] = 0; }
}

// ---------------- weight folding ----------------
__global__ void k_wcomb(const float* __restrict__ Wu, const float* __restrict__ bu,
                        const float* __restrict__ Wi, const float* __restrict__ bi,
                        const float* __restrict__ W1) {
    int idx = blockIdx.x * blockDim.x + threadIdx.x;
    const int TOT_U = UD * CM, TOT_I = ID * CM;
    if (idx < TOT_U) {
        int k = idx / CM, c = idx % CM;
        float a = 0.f;
        #pragma unroll
        for (int j = 0; j < CM; j++) a += Wu[k * CM + j] * W1[j * CM + c];
        g_WuW1[idx] = a;
    } else if (idx < TOT_U + TOT_I) {
        int r = idx - TOT_U;
        int k = r / CM, c = r % CM;
        float a = 0.f;
        #pragma unroll
        for (int j = 0; j < CM; j++) a += Wi[k * CM + j] * W1[j * CM + c];
        g_WiW1[r] = a;
    } else if (idx < TOT_U + TOT_I + 2 * CM) {
        int r = idx - TOT_U - TOT_I;
        if (r < CM) {
            float a = 0.f;
            #pragma unroll
            for (int j = 0; j < CM; j++) a += bu[j] * W1[j * CM + r];
            g_cu[r] = a;
        } else {
            int c = r - CM;
            float a = 0.f;
            #pragma unroll
            for (int j = 0; j < CM; j++) a += bi[j] * W1[j * CM + c];
            g_ci[c] = a;
        }
    }
}

// ---------------- embed: warp-pair split (warp owns 32 cols of 32 nodes) ----------------
// wid even -> cols [0,32), wid odd -> cols [32,64); lanes = nodes -> W reads are
// full-warp broadcast LDS (1 wavefront), x reads lane-coalesced.
#define EB_THREADS 256
#define EB_NODES   128          // nodes per block (4 warp-pairs x 32 nodes)
#define EB_KC 16
__global__ __launch_bounds__(EB_THREADS)
void k_embed(const float* __restrict__ ut, const float* __restrict__ it, int userBlocks) {
    __shared__ ulonglong2 sW[EB_KC * 16];   // 16 rows x 64 cols = 4 KB
    bool isUser = (int)blockIdx.x < userBlocks;
    int blockLocal = isUser ? blockIdx.x : blockIdx.x - userBlocks;
    int wid = threadIdx.x >> 5;
    int lane = threadIdx.x & 31;
    int half = wid & 1;                      // column half owned by this warp
    int nodeLocal = blockLocal * EB_NODES + (wid >> 1) * 32 + lane;
    int K = isUser ? UD : ID;
    int Ncnt = isUser ? NU : NI;
    const float* W = isUser ? g_WuW1 : g_WiW1;
    const float* cvec = isUser ? g_cu : g_ci;
    const float* inp = isUser ? ut : it;
    bool active = nodeLocal < Ncnt;
    const float* xrow = inp + (size_t)(active ? nodeLocal : 0) * K;

    ull acc[16];
    #pragma unroll
    for (int i = 0; i < 16; i++) acc[i] = 0ull;

    for (int kb = 0; kb < K; kb += EB_KC) {
        __syncthreads();
        sW[threadIdx.x] = ((const ulonglong2*)(W + (size_t)kb * CM))[threadIdx.x];
        __syncthreads();
        if (active) {
            float x[EB_KC];
            #pragma unroll
            for (int q = 0; q < EB_KC / 4; q++) {
                float4 v = ((const float4*)(xrow + kb))[q];
                x[4 * q] = v.x; x[4 * q + 1] = v.y; x[4 * q + 2] = v.z; x[4 * q + 3] = v.w;
            }
            #pragma unroll
            for (int k = 0; k < EB_KC; k++) {
                ull bk; PACK2(bk, x[k]);
                #pragma unroll
                for (int c4 = 0; c4 < 8; c4++) {
                    ulonglong2 w = sW[k * 16 + half * 8 + c4];   // warp-uniform -> broadcast
                    FMA2(acc[2 * c4],     bk, w.x, acc[2 * c4]);
                    FMA2(acc[2 * c4 + 1], bk, w.y, acc[2 * c4 + 1]);
                }
            }
        }
    }
    if (active) {
        int node = isUser ? nodeLocal : NU + nodeLocal;
        float4* orow = (float4*)(g_h1 + (size_t)node * CM + half * 32);
        const float4* cv4 = (const float4*)(cvec + half * 32);
        #pragma unroll
        for (int c4 = 0; c4 < 8; c4++) {
            float a, b, c, d;
            UNPACK2(a, b, acc[2 * c4]);
            UNPACK2(c, d, acc[2 * c4 + 1]);
            float4 cv = cv4[c4];
            float4 ov; ov.x = a + cv.x; ov.y = b + cv.y; ov.z = c + cv.z; ov.w = d + cv.w;
            orow[c4] = ov;
        }
    }
}

// ---------------- graph preprocessing ----------------
__global__ void k_edge1(const int* __restrict__ ei32, const float* __restrict__ ew) {
    int t = blockIdx.x * blockDim.x + threadIdx.x;
    int e = 2 * t;
    if (e >= NE) return;
    int d0, d1;
    if (g_is64) {
        int4 v = *(const int4*)(ei32 + 2 * (NE + e));
        d0 = v.x; d1 = v.z;
    } else {
        int2 v = *(const int2*)(ei32 + NE + e);
        d0 = v.x; d1 = v.y;
    }
    float2 w = *(const float2*)(ew + e);
    atomicAdd(&g_count[d0], 1);
    atomicAdd(&g_deg[d0], w.x);
    atomicAdd(&g_count[d1], 1);
    atomicAdd(&g_deg[d1], w.y);
}

__global__ void k_scan1() {
    __shared__ int sh[SCAN_BLK];
    int t = threadIdx.x;
    int gid = blockIdx.x * SCAN_BLK + t;
    int v = (gid < NN) ? g_count[gid] : 0;
    sh[t] = v;
    __syncthreads();
    for (int off = 1; off < SCAN_BLK; off <<= 1) {
        int x = (t >= off) ? sh[t - off] : 0;
        __syncthreads();
        sh[t] += x;
        __syncthreads();
    }
    if (gid < NN) {
        g_rowstart[gid] = sh[t] - v;
        float dg = g_deg[gid];
        g_dinv[gid] = (dg > 0.0f) ? rsqrtf(dg) : 0.0f;
    }
    if (t == SCAN_BLK - 1) g_bsum[blockIdx.x] = sh[t];
}

__global__ void k_scan2() {
    __shared__ int sh[SCAN_BLK];
    int t = threadIdx.x;
    int v = (t < NSCAN_BLKS) ? g_bsum[t] : 0;
    sh[t] = v;
    __syncthreads();
    for (int off = 1; off < SCAN_BLK; off <<= 1) {
        int x = (t >= off) ? sh[t - off] : 0;
        __syncthreads();
        sh[t] += x;
        __syncthreads();
    }
    if (t < NSCAN_BLKS) g_bsum[t] = sh[t] - v;
}

__global__ void k_scan3() {
    int i = blockIdx.x * blockDim.x + threadIdx.x;
    if (i < NN) {
        int rs = g_rowstart[i] + g_bsum[i >> 10];
        g_rowstart[i] = rs;
        g_cursor[i] = rs;
    }
    if (i == 0) g_rowstart[NN] = NE;
}

__global__ void k_scatter(const int* __restrict__ ei32, const float* __restrict__ ew) {
    int e = blockIdx.x * blockDim.x + threadIdx.x;
    if (e >= NE) return;
    int s, d;
    if (g_is64) { s = ei32[2 * e]; d = ei32[2 * (NE + e)]; }
    else        { s = ei32[e];     d = ei32[NE + e]; }
    float nrm = g_dinv[s] * ew[e] * g_dinv[d];
    int pos = atomicAdd(&g_cursor[d], 1);
    g_csr[pos] = (ull)(unsigned)s | ((ull)__float_as_uint(nrm) << 32);
}

// ---------------- gather1: aggregate h1 + bias + relu -> z1 (warp/node, f32x2) ----------------
__global__ void k_gather1(const float* __restrict__ b1) {
    int t = threadIdx.x;
    int node = blockIdx.x * (blockDim.x >> 5) + (t >> 5);
    int lane = t & 31;
    if (node >= NN) return;

    const ull* h = (const ull*)g_h1;
    float dv = g_dinv[node];
    ull sw; PACK2(sw, dv * dv);
    ull zero = 0ull;
    ull acc; FMA2(acc, sw, h[(size_t)node * 32 + lane], zero);

    int e = g_rowstart[node], end = g_rowstart[node + 1];
    for (; e + 4 <= end; e += 4) {
        ull p0 = g_csr[e], p1 = g_csr[e + 1], p2 = g_csr[e + 2], p3 = g_csr[e + 3];
        int s0 = (int)(unsigned)p0, s1 = (int)(unsigned)p1;
        int s2 = (int)(unsigned)p2, s3 = (int)(unsigned)p3;
        ull v0 = h[(size_t)s0 * 32 + lane];
        ull v1 = h[(size_t)s1 * 32 + lane];
        ull v2 = h[(size_t)s2 * 32 + lane];
        ull v3 = h[(size_t)s3 * 32 + lane];
        float w0 = __uint_as_float((unsigned)(p0 >> 32));
        float w1 = __uint_as_float((unsigned)(p1 >> 32));
        float w2 = __uint_as_float((unsigned)(p2 >> 32));
        float w3 = __uint_as_float((unsigned)(p3 >> 32));
        ull q0, q1, q2, q3;
        PACK2(q0, w0); PACK2(q1, w1); PACK2(q2, w2); PACK2(q3, w3);
        FMA2(acc, q0, v0, acc);
        FMA2(acc, q1, v1, acc);
        FMA2(acc, q2, v2, acc);
        FMA2(acc, q3, v3, acc);
    }
    for (; e < end; e++) {
        ull p = g_csr[e];
        int s = (int)(unsigned)p;
        float w = __uint_as_float((unsigned)(p >> 32));
        ull q; PACK2(q, w);
        FMA2(acc, q, h[(size_t)s * 32 + lane], acc);
    }
    float ax, ay; UNPACK2(ax, ay, acc);
    float2 bb = ((const float2*)b1)[lane];
    float2 z;
    z.x = fmaxf(ax + bb.x, 0.0f);
    z.y = fmaxf(ay + bb.y, 0.0f);
    ((float2*)(g_z1 + (size_t)node * CM))[lane] = z;
}

// ---------------- xform: h2 = z1 @ W2 (per-thread node, f32x2) ----------------
#define XF_THREADS 256
__global__ __launch_bounds__(XF_THREADS)
void k_xform(const float* __restrict__ W2) {
    __shared__ ulonglong2 sW[CM * 8];   // 8 KB = 512 ulonglong2
    sW[threadIdx.x]       = ((const ulonglong2*)W2)[threadIdx.x];
    sW[threadIdx.x + 256] = ((const ulonglong2*)W2)[threadIdx.x + 256];
    __syncthreads();

    int node = blockIdx.x * XF_THREADS + threadIdx.x;
    if (node >= NN) return;
    const float* xrow = g_z1 + (size_t)node * CM;

    ull acc[16];
    #pragma unroll
    for (int i = 0; i < 16; i++) acc[i] = 0ull;

    #pragma unroll
    for (int kb = 0; kb < CM; kb += 16) {
        float x[16];
        #pragma unroll
        for (int q = 0; q < 4; q++) {
            float4 v = ((const float4*)(xrow + kb))[q];
            x[4 * q] = v.x; x[4 * q + 1] = v.y; x[4 * q + 2] = v.z; x[4 * q + 3] = v.w;
        }
        #pragma unroll
        for (int k = 0; k < 16; k++) {
            ull bk; PACK2(bk, x[k]);
            #pragma unroll
            for (int c4 = 0; c4 < 8; c4++) {
                ulonglong2 w = sW[(kb + k) * 8 + c4];
                FMA2(acc[2 * c4],     bk, w.x, acc[2 * c4]);
                FMA2(acc[2 * c4 + 1], bk, w.y, acc[2 * c4 + 1]);
            }
        }
    }
    float4* orow = (float4*)(g_h2 + (size_t)node * OD);
    #pragma unroll
    for (int c4 = 0; c4 < 8; c4++) {
        float a, b, c, d;
        UNPACK2(a, b, acc[2 * c4]);
        UNPACK2(c, d, acc[2 * c4 + 1]);
        float4 ov; ov.x = a; ov.y = b; ov.z = c; ov.w = d;
        orow[c4] = ov;
    }
}

// ---------------- gather2: aggregate h2 + b2 -> out (dual half-warp, f32x2) ----------------
__global__ void k_gather2(const float* __restrict__ b2, float* __restrict__ out) {
    int t = threadIdx.x;
    int node = blockIdx.x * (blockDim.x >> 5) + (t >> 5);
    int lane = t & 31;
    if (node >= NN) return;
    int half = lane >> 4;
    int c = lane & 15;

    const ull* h = (const ull*)g_h2;
    ull acc = 0ull;
    if (half == 0) {
        float dv = g_dinv[node];
        ull sw; PACK2(sw, dv * dv);
        ull zero = 0ull;
        FMA2(acc, sw, h[(size_t)node * 16 + c], zero);
    }
    int beg = g_rowstart[node], end = g_rowstart[node + 1];
    int e = beg + half;
    for (; e + 2 < end; e += 4) {
        ull p0 = g_csr[e], p1 = g_csr[e + 2];
        int s0 = (int)(unsigned)p0, s1 = (int)(unsigned)p1;
        ull v0 = h[(size_t)s0 * 16 + c];
        ull v1 = h[(size_t)s1 * 16 + c];
        float w0 = __uint_as_float((unsigned)(p0 >> 32));
        float w1 = __uint_as_float((unsigned)(p1 >> 32));
        ull q0, q1; PACK2(q0, w0); PACK2(q1, w1);
        FMA2(acc, q0, v0, acc);
        FMA2(acc, q1, v1, acc);
    }
    if (e < end) {
        ull p = g_csr[e];
        int s = (int)(unsigned)p;
        float w = __uint_as_float((unsigned)(p >> 32));
        ull q; PACK2(q, w);
        FMA2(acc, q, h[(size_t)s * 16 + c], acc);
    }
    float ax, ay; UNPACK2(ax, ay, acc);
    ax += __shfl_xor_sync(0xffffffffu, ax, 16);
    ay += __shfl_xor_sync(0xffffffffu, ay, 16);
    if (half == 0) {
        float2 bb = ((const float2*)b2)[c];
        float2 ov; ov.x = ax + bb.x; ov.y = ay + bb.y;
        ((float2*)(out + (size_t)node * OD))[c] = ov;
    }
}

// ---------------- launch ----------------
extern "C" void kernel_launch(void* const* d_in, const int* in_sizes, int n_in,
                              void* d_out, int out_size) {
    const float* ut = (const float*)d_in[0];
    const float* it = (const float*)d_in[1];
    const int*   ei = (const int*)d_in[2];
    const float* ew = (const float*)d_in[3];
    const float* Wu = (const float*)d_in[4];
    const float* bu = (const float*)d_in[5];
    const float* Wi = (const float*)d_in[6];
    const float* bi = (const float*)d_in[7];
    const float* W1 = (const float*)d_in[8];
    const float* b1 = (const float*)d_in[9];
    const float* W2 = (const float*)d_in[10];
    const float* b2 = (const float*)d_in[11];
    float*       out = (float*)d_out;

    int userBlocks = (NU + EB_NODES - 1) / EB_NODES;    // 782
    int itemBlocks = (NI + EB_NODES - 1) / EB_NODES;    // 782

    // launch order arranged so k_embed is the 4th launch (ncu capture slot)
    k_detect<<<1, 256>>>(ei);                                              // 1
    k_init<<<(NN + 255) / 256, 256>>>();                                   // 2
    k_wcomb<<<(UD * CM + ID * CM + 2 * CM + 127) / 128, 128>>>(Wu, bu, Wi, bi, W1); // 3
    k_embed<<<userBlocks + itemBlocks, EB_THREADS>>>(ut, it, userBlocks);  // 4  <- profiled
    k_edge1<<<(NE / 2 + 255) / 256, 256>>>(ei, ew);                        // 5
    k_scan1<<<NSCAN_BLKS, SCAN_BLK>>>();                                   // 6
    k_scan2<<<1, SCAN_BLK>>>();                                            // 7
    k_scan3<<<(NN + 255) / 256, 256>>>();                                  // 8
    k_scatter<<<(NE + 255) / 256, 256>>>(ei, ew);                          // 9
    k_gather1<<<NN / 8, 256>>>(b1);                                        // 10
    k_xform<<<(NN + XF_THREADS - 1) / XF_THREADS, XF_THREADS>>>(W2);       // 11
    k_gather2<<<NN / 8, 256>>>(b2, out);                                   // 12
}

// round 10
// speedup vs baseline: 1.1512x; 1.0335x over previous
#include <cuda_runtime.h>
#include <cuda_bf16.h>
#include <stdint.h>

typedef unsigned long long ull;

#define NU 100000
#define NI 100000
#define NN 200000
#define NE 4000000
#define UD 256
#define ID 128
#define CM 64
#define OD 32
#define SCAN_BLK 1024
#define NSCAN_BLKS ((NN + SCAN_BLK - 1) / SCAN_BLK)

// f32x2 packed helpers
#define FMA2(d, a, b, c) asm("fma.rn.f32x2 %0, %1, %2, %3;" : "=l"(d) : "l"(a), "l"(b), "l"(c))
#define PACK2(d, x)      asm("mov.b64 %0, {%1, %1};" : "=l"(d) : "f"(x))
#define UNPACK2(lo, hi, v) asm("mov.b64 {%0, %1}, %2;" : "=f"(lo), "=f"(hi) : "l"(v))

// ---------------- scratch ----------------
__device__ float g_deg[NN];
__device__ float g_dinv[NN];
__device__ int   g_count[NN];
__device__ int   g_rowstart[NN + 1];
__device__ int   g_cursor[NN];
__device__ int   g_bsum[SCAN_BLK];
__device__ ull   g_csr[NE];               // packed: lo32 = src, hi32 = norm bits
__device__ float g_WuW1[UD * CM];
__device__ float g_WiW1[ID * CM];
__device__ float g_cu[CM];
__device__ float g_ci[CM];
__device__ float g_h1[(size_t)NN * CM];   // 51.2 MB
__device__ float g_z1[(size_t)NN * CM];   // 51.2 MB
__device__ float g_h2[(size_t)NN * OD];   // 25.6 MB
__device__ int   g_is64;

// ---------------- dtype detection ----------------
__global__ void k_detect(const int* __restrict__ ei32) {
    __shared__ int any_nonzero;
    if (threadIdx.x == 0) any_nonzero = 0;
    __syncthreads();
    for (int i = 2 * threadIdx.x + 1; i < 4096; i += 2 * blockDim.x)
        if (ei32[i] != 0) any_nonzero = 1;
    __syncthreads();
    if (threadIdx.x == 0) g_is64 = any_nonzero ? 0 : 1;
}

__global__ void k_init() {
    int i = blockIdx.x * blockDim.x + threadIdx.x;
    if (i < NN) { g_deg[i] = 1.0f; g_count[i] = 0; }
}

// ---------------- weight folding ----------------
__global__ void k_wcomb(const float* __restrict__ Wu, const float* __restrict__ bu,
                        const float* __restrict__ Wi, const float* __restrict__ bi,
                        const float* __restrict__ W1) {
    int idx = blockIdx.x * blockDim.x + threadIdx.x;
    const int TOT_U = UD * CM, TOT_I = ID * CM;
    if (idx < TOT_U) {
        int k = idx / CM, c = idx % CM;
        float a = 0.f;
        #pragma unroll
        for (int j = 0; j < CM; j++) a += Wu[k * CM + j] * W1[j * CM + c];
        g_WuW1[idx] = a;
    } else if (idx < TOT_U + TOT_I) {
        int r = idx - TOT_U;
        int k = r / CM, c = r % CM;
        float a = 0.f;
        #pragma unroll
        for (int j = 0; j < CM; j++) a += Wi[k * CM + j] * W1[j * CM + c];
        g_WiW1[r] = a;
    } else if (idx < TOT_U + TOT_I + 2 * CM) {
        int r = idx - TOT_U - TOT_I;
        if (r < CM) {
            float a = 0.f;
            #pragma unroll
            for (int j = 0; j < CM; j++) a += bu[j] * W1[j * CM + r];
            g_cu[r] = a;
        } else {
            int c = r - CM;
            float a = 0.f;
            #pragma unroll
            for (int j = 0; j < CM; j++) a += bi[j] * W1[j * CM + c];
            g_ci[c] = a;
        }
    }
}

// ---------------- embed: whole-W in smem, barrier-free mainloop ----------------
// Warp-pair split: wid even -> cols [0,32), wid odd -> cols [32,64); lanes = nodes.
// W reads are warp-uniform (broadcast LDS), x reads lane-coalesced. The ENTIRE
// folded weight matrix lives in smem (user 64KB, item 32KB), so the main loop
// has NO barriers — warps drift independently, hiding LDS latency.
#define EB_THREADS 256
#define EB_NODES   128          // nodes per block (4 warp-pairs x 32 nodes)
#define EB_SMEM    (UD * CM * 4)   // 64 KB (max of both types)
__global__ __launch_bounds__(EB_THREADS, 3)
void k_embed(const float* __restrict__ ut, const float* __restrict__ it, int userBlocks) {
    extern __shared__ ulonglong2 sW[];
    bool isUser = (int)blockIdx.x < userBlocks;
    int blockLocal = isUser ? blockIdx.x : blockIdx.x - userBlocks;
    int wid = threadIdx.x >> 5;
    int lane = threadIdx.x & 31;
    int half = wid & 1;                      // column half owned by this warp
    int nodeLocal = blockLocal * EB_NODES + (wid >> 1) * 32 + lane;
    int K = isUser ? UD : ID;
    int Ncnt = isUser ? NU : NI;
    const float* W = isUser ? g_WuW1 : g_WiW1;
    const float* cvec = isUser ? g_cu : g_ci;
    const float* inp = isUser ? ut : it;
    bool active = nodeLocal < Ncnt;
    const float* xrow = inp + (size_t)(active ? nodeLocal : 0) * K;

    // stage whole W into smem (single barrier)
    {
        const ulonglong2* Wv = (const ulonglong2*)W;
        int nW = K * CM / 4;                 // ulonglong2 entries
        for (int i = threadIdx.x; i < nW; i += EB_THREADS) sW[i] = Wv[i];
    }
    __syncthreads();

    ull acc[16];
    #pragma unroll
    for (int i = 0; i < 16; i++) acc[i] = 0ull;

    if (active) {
        #pragma unroll 2
        for (int kb = 0; kb < K; kb += 16) {
            float x[16];
            #pragma unroll
            for (int q = 0; q < 4; q++) {
                float4 v = ((const float4*)(xrow + kb))[q];
                x[4 * q] = v.x; x[4 * q + 1] = v.y; x[4 * q + 2] = v.z; x[4 * q + 3] = v.w;
            }
            #pragma unroll
            for (int k = 0; k < 16; k++) {
                ull bk; PACK2(bk, x[k]);
                #pragma unroll
                for (int c4 = 0; c4 < 8; c4++) {
                    ulonglong2 w = sW[(kb + k) * 16 + half * 8 + c4];   // warp-uniform
                    FMA2(acc[2 * c4],     bk, w.x, acc[2 * c4]);
                    FMA2(acc[2 * c4 + 1], bk, w.y, acc[2 * c4 + 1]);
                }
            }
        }
        int node = isUser ? nodeLocal : NU + nodeLocal;
        float4* orow = (float4*)(g_h1 + (size_t)node * CM + half * 32);
        const float4* cv4 = (const float4*)(cvec + half * 32);
        #pragma unroll
        for (int c4 = 0; c4 < 8; c4++) {
            float a, b, c, d;
            UNPACK2(a, b, acc[2 * c4]);
            UNPACK2(c, d, acc[2 * c4 + 1]);
            float4 cv = cv4[c4];
            float4 ov; ov.x = a + cv.x; ov.y = b + cv.y; ov.z = c + cv.z; ov.w = d + cv.w;
            orow[c4] = ov;
        }
    }
}

// ---------------- graph preprocessing ----------------
__global__ void k_edge1(const int* __restrict__ ei32, const float* __restrict__ ew) {
    int t = blockIdx.x * blockDim.x + threadIdx.x;
    int e = 2 * t;
    if (e >= NE) return;
    int d0, d1;
    if (g_is64) {
        int4 v = *(const int4*)(ei32 + 2 * (NE + e));
        d0 = v.x; d1 = v.z;
    } else {
        int2 v = *(const int2*)(ei32 + NE + e);
        d0 = v.x; d1 = v.y;
    }
    float2 w = *(const float2*)(ew + e);
    atomicAdd(&g_count[d0], 1);
    atomicAdd(&g_deg[d0], w.x);
    atomicAdd(&g_count[d1], 1);
    atomicAdd(&g_deg[d1], w.y);
}

__global__ void k_scan1() {
    __shared__ int sh[SCAN_BLK];
    int t = threadIdx.x;
    int gid = blockIdx.x * SCAN_BLK + t;
    int v = (gid < NN) ? g_count[gid] : 0;
    sh[t] = v;
    __syncthreads();
    for (int off = 1; off < SCAN_BLK; off <<= 1) {
        int x = (t >= off) ? sh[t - off] : 0;
        __syncthreads();
        sh[t] += x;
        __syncthreads();
    }
    if (gid < NN) {
        g_rowstart[gid] = sh[t] - v;
        float dg = g_deg[gid];
        g_dinv[gid] = (dg > 0.0f) ? rsqrtf(dg) : 0.0f;
    }
    if (t == SCAN_BLK - 1) g_bsum[blockIdx.x] = sh[t];
}

__global__ void k_scan2() {
    __shared__ int sh[SCAN_BLK];
    int t = threadIdx.x;
    int v = (t < NSCAN_BLKS) ? g_bsum[t] : 0;
    sh[t] = v;
    __syncthreads();
    for (int off = 1; off < SCAN_BLK; off <<= 1) {
        int x = (t >= off) ? sh[t - off] : 0;
        __syncthreads();
        sh[t] += x;
        __syncthreads();
    }
    if (t < NSCAN_BLKS) g_bsum[t] = sh[t] - v;
}

__global__ void k_scan3() {
    int i = blockIdx.x * blockDim.x + threadIdx.x;
    if (i < NN) {
        int rs = g_rowstart[i] + g_bsum[i >> 10];
        g_rowstart[i] = rs;
        g_cursor[i] = rs;
    }
    if (i == 0) g_rowstart[NN] = NE;
}

__global__ void k_scatter(const int* __restrict__ ei32, const float* __restrict__ ew) {
    int e = blockIdx.x * blockDim.x + threadIdx.x;
    if (e >= NE) return;
    int s, d;
    if (g_is64) { s = ei32[2 * e]; d = ei32[2 * (NE + e)]; }
    else        { s = ei32[e];     d = ei32[NE + e]; }
    float nrm = g_dinv[s] * ew[e] * g_dinv[d];
    int pos = atomicAdd(&g_cursor[d], 1);
    g_csr[pos] = (ull)(unsigned)s | ((ull)__float_as_uint(nrm) << 32);
}

// ---------------- gather1: aggregate h1 + bias + relu -> z1 (warp/node, f32x2) ----------------
__global__ void k_gather1(const float* __restrict__ b1) {
    int t = threadIdx.x;
    int node = blockIdx.x * (blockDim.x >> 5) + (t >> 5);
    int lane = t & 31;
    if (node >= NN) return;

    const ull* h = (const ull*)g_h1;
    float dv = g_dinv[node];
    ull sw; PACK2(sw, dv * dv);
    ull zero = 0ull;
    ull acc; FMA2(acc, sw, h[(size_t)node * 32 + lane], zero);

    int e = g_rowstart[node], end = g_rowstart[node + 1];
    for (; e + 4 <= end; e += 4) {
        ull p0 = g_csr[e], p1 = g_csr[e + 1], p2 = g_csr[e + 2], p3 = g_csr[e + 3];
        int s0 = (int)(unsigned)p0, s1 = (int)(unsigned)p1;
        int s2 = (int)(unsigned)p2, s3 = (int)(unsigned)p3;
        ull v0 = h[(size_t)s0 * 32 + lane];
        ull v1 = h[(size_t)s1 * 32 + lane];
        ull v2 = h[(size_t)s2 * 32 + lane];
        ull v3 = h[(size_t)s3 * 32 + lane];
        float w0 = __uint_as_float((unsigned)(p0 >> 32));
        float w1 = __uint_as_float((unsigned)(p1 >> 32));
        float w2 = __uint_as_float((unsigned)(p2 >> 32));
        float w3 = __uint_as_float((unsigned)(p3 >> 32));
        ull q0, q1, q2, q3;
        PACK2(q0, w0); PACK2(q1, w1); PACK2(q2, w2); PACK2(q3, w3);
        FMA2(acc, q0, v0, acc);
        FMA2(acc, q1, v1, acc);
        FMA2(acc, q2, v2, acc);
        FMA2(acc, q3, v3, acc);
    }
    for (; e < end; e++) {
        ull p = g_csr[e];
        int s = (int)(unsigned)p;
        float w = __uint_as_float((unsigned)(p >> 32));
        ull q; PACK2(q, w);
        FMA2(acc, q, h[(size_t)s * 32 + lane], acc);
    }
    float ax, ay; UNPACK2(ax, ay, acc);
    float2 bb = ((const float2*)b1)[lane];
    float2 z;
    z.x = fmaxf(ax + bb.x, 0.0f);
    z.y = fmaxf(ay + bb.y, 0.0f);
    ((float2*)(g_z1 + (size_t)node * CM))[lane] = z;
}

// ---------------- xform: h2 = z1 @ W2 (per-thread node, f32x2) ----------------
#define XF_THREADS 256
__global__ __launch_bounds__(XF_THREADS)
void k_xform(const float* __restrict__ W2) {
    __shared__ ulonglong2 sW2[CM * 8];   // 8 KB = 512 ulonglong2
    sW2[threadIdx.x]       = ((const ulonglong2*)W2)[threadIdx.x];
    sW2[threadIdx.x + 256] = ((const ulonglong2*)W2)[threadIdx.x + 256];
    __syncthreads();

    int node = blockIdx.x * XF_THREADS + threadIdx.x;
    if (node >= NN) return;
    const float* xrow = g_z1 + (size_t)node * CM;

    ull acc[16];
    #pragma unroll
    for (int i = 0; i < 16; i++) acc[i] = 0ull;

    #pragma unroll
    for (int kb = 0; kb < CM; kb += 16) {
        float x[16];
        #pragma unroll
        for (int q = 0; q < 4; q++) {
            float4 v = ((const float4*)(xrow + kb))[q];
            x[4 * q] = v.x; x[4 * q + 1] = v.y; x[4 * q + 2] = v.z; x[4 * q + 3] = v.w;
        }
        #pragma unroll
        for (int k = 0; k < 16; k++) {
            ull bk; PACK2(bk, x[k]);
            #pragma unroll
            for (int c4 = 0; c4 < 8; c4++) {
                ulonglong2 w = sW2[(kb + k) * 8 + c4];
                FMA2(acc[2 * c4],     bk, w.x, acc[2 * c4]);
                FMA2(acc[2 * c4 + 1], bk, w.y, acc[2 * c4 + 1]);
            }
        }
    }
    float4* orow = (float4*)(g_h2 + (size_t)node * OD);
    #pragma unroll
    for (int c4 = 0; c4 < 8; c4++) {
        float a, b, c, d;
        UNPACK2(a, b, acc[2 * c4]);
        UNPACK2(c, d, acc[2 * c4 + 1]);
        float4 ov; ov.x = a; ov.y = b; ov.z = c; ov.w = d;
        orow[c4] = ov;
    }
}

// ---------------- gather2: aggregate h2 + b2 -> out (dual half-warp, f32x2) ----------------
__global__ void k_gather2(const float* __restrict__ b2, float* __restrict__ out) {
    int t = threadIdx.x;
    int node = blockIdx.x * (blockDim.x >> 5) + (t >> 5);
    int lane = t & 31;
    if (node >= NN) return;
    int half = lane >> 4;
    int c = lane & 15;

    const ull* h = (const ull*)g_h2;
    ull acc = 0ull;
    if (half == 0) {
        float dv = g_dinv[node];
        ull sw; PACK2(sw, dv * dv);
        ull zero = 0ull;
        FMA2(acc, sw, h[(size_t)node * 16 + c], zero);
    }
    int beg = g_rowstart[node], end = g_rowstart[node + 1];
    int e = beg + half;
    for (; e + 2 < end; e += 4) {
        ull p0 = g_csr[e], p1 = g_csr[e + 2];
        int s0 = (int)(unsigned)p0, s1 = (int)(unsigned)p1;
        ull v0 = h[(size_t)s0 * 16 + c];
        ull v1 = h[(size_t)s1 * 16 + c];
        float w0 = __uint_as_float((unsigned)(p0 >> 32));
        float w1 = __uint_as_float((unsigned)(p1 >> 32));
        ull q0, q1; PACK2(q0, w0); PACK2(q1, w1);
        FMA2(acc, q0, v0, acc);
        FMA2(acc, q1, v1, acc);
    }
    if (e < end) {
        ull p = g_csr[e];
        int s = (int)(unsigned)p;
        float w = __uint_as_float((unsigned)(p >> 32));
        ull q; PACK2(q, w);
        FMA2(acc, q, h[(size_t)s * 16 + c], acc);
    }
    float ax, ay; UNPACK2(ax, ay, acc);
    ax += __shfl_xor_sync(0xffffffffu, ax, 16);
    ay += __shfl_xor_sync(0xffffffffu, ay, 16);
    if (half == 0) {
        float2 bb = ((const float2*)b2)[c];
        float2 ov; ov.x = ax + bb.x; ov.y = ay + bb.y;
        ((float2*)(out + (size_t)node * OD))[c] = ov;
    }
}

// ---------------- launch ----------------
extern "C" void kernel_launch(void* const* d_in, const int* in_sizes, int n_in,
                              void* d_out, int out_size) {
    const float* ut = (const float*)d_in[0];
    const float* it = (const float*)d_in[1];
    const int*   ei = (const int*)d_in[2];
    const float* ew = (const float*)d_in[3];
    const float* Wu = (const float*)d_in[4];
    const float* bu = (const float*)d_in[5];
    const float* Wi = (const float*)d_in[6];
    const float* bi = (const float*)d_in[7];
    const float* W1 = (const float*)d_in[8];
    const float* b1 = (const float*)d_in[9];
    const float* W2 = (const float*)d_in[10];
    const float* b2 = (const float*)d_in[11];
    float*       out = (float*)d_out;

    cudaFuncSetAttribute(k_embed, cudaFuncAttributeMaxDynamicSharedMemorySize, EB_SMEM);

    int userBlocks = (NU + EB_NODES - 1) / EB_NODES;    // 782
    int itemBlocks = (NI + EB_NODES - 1) / EB_NODES;    // 782

    // launch order arranged so k_embed is the 4th launch (ncu capture slot)
    k_detect<<<1, 256>>>(ei);                                              // 1
    k_init<<<(NN + 255) / 256, 256>>>();                                   // 2
    k_wcomb<<<(UD * CM + ID * CM + 2 * CM + 127) / 128, 128>>>(Wu, bu, Wi, bi, W1); // 3
    k_embed<<<userBlocks + itemBlocks, EB_THREADS, EB_SMEM>>>(ut, it, userBlocks);  // 4 <- profiled
    k_edge1<<<(NE / 2 + 255) / 256, 256>>>(ei, ew);                        // 5
    k_scan1<<<NSCAN_BLKS, SCAN_BLK>>>();                                   // 6
    k_scan2<<<1, SCAN_BLK>>>();                                            // 7
    k_scan3<<<(NN + 255) / 256, 256>>>();                                  // 8
    k_scatter<<<(NE + 255) / 256, 256>>>(ei, ew);                          // 9
    k_gather1<<<NN / 8, 256>>>(b1);                                        // 10
    k_xform<<<(NN + XF_THREADS - 1) / XF_THREADS, XF_THREADS>>>(W2);       // 11
    k_gather2<<<NN / 8, 256>>>(b2, out);                                   // 12
}

// round 11
// speedup vs baseline: 1.3064x; 1.1348x over previous
#include <cuda_runtime.h>
#include <cuda_bf16.h>
#include <stdint.h>

typedef unsigned long long ull;

#define NU 100000
#define NI 100000
#define NN 200000
#define NE 4000000
#define UD 256
#define ID 128
#define CM 64
#define OD 32
#define SCAN_BLK 1024
#define NSCAN_BLKS ((NN + SCAN_BLK - 1) / SCAN_BLK)

// f32x2 packed helpers
#define FMA2(d, a, b, c) asm("fma.rn.f32x2 %0, %1, %2, %3;" : "=l"(d) : "l"(a), "l"(b), "l"(c))
#define PACK2(d, x)      asm("mov.b64 %0, {%1, %1};" : "=l"(d) : "f"(x))
#define UNPACK2(lo, hi, v) asm("mov.b64 {%0, %1}, %2;" : "=f"(lo), "=f"(hi) : "l"(v))

// ---------------- scratch ----------------
__device__ float g_deg[NN];
__device__ float g_dinv[NN];
__device__ int   g_count[NN];
__device__ int   g_rowstart[NN + 1];
__device__ int   g_cursor[NN];
__device__ int   g_bsum[SCAN_BLK];
__device__ ull   g_csr[NE];               // packed: lo32 = src, hi32 = norm bits
__device__ float g_WuW1[UD * CM];
__device__ float g_WiW1[ID * CM];
__device__ float g_cu[CM];
__device__ float g_ci[CM];
__device__ float g_h1[(size_t)NN * CM];   // 51.2 MB
__device__ float g_z1[(size_t)NN * CM];   // 51.2 MB
__device__ float g_h2[(size_t)NN * OD];   // 25.6 MB
__device__ int   g_is64;

// ---------------- dtype detection ----------------
__global__ void k_detect(const int* __restrict__ ei32) {
    __shared__ int any_nonzero;
    if (threadIdx.x == 0) any_nonzero = 0;
    __syncthreads();
    for (int i = 2 * threadIdx.x + 1; i < 4096; i += 2 * blockDim.x)
        if (ei32[i] != 0) any_nonzero = 1;
    __syncthreads();
    if (threadIdx.x == 0) g_is64 = any_nonzero ? 0 : 1;
}

__global__ void k_init() {
    int i = blockIdx.x * blockDim.x + threadIdx.x;
    if (i < NN) { g_deg[i] = 1.0f; g_count[i] = 0; }
}

// ---------------- weight folding ----------------
__global__ void k_wcomb(const float* __restrict__ Wu, const float* __restrict__ bu,
                        const float* __restrict__ Wi, const float* __restrict__ bi,
                        const float* __restrict__ W1) {
    int idx = blockIdx.x * blockDim.x + threadIdx.x;
    const int TOT_U = UD * CM, TOT_I = ID * CM;
    if (idx < TOT_U) {
        int k = idx / CM, c = idx % CM;
        float a = 0.f;
        #pragma unroll
        for (int j = 0; j < CM; j++) a += Wu[k * CM + j] * W1[j * CM + c];
        g_WuW1[idx] = a;
    } else if (idx < TOT_U + TOT_I) {
        int r = idx - TOT_U;
        int k = r / CM, c = r % CM;
        float a = 0.f;
        #pragma unroll
        for (int j = 0; j < CM; j++) a += Wi[k * CM + j] * W1[j * CM + c];
        g_WiW1[r] = a;
    } else if (idx < TOT_U + TOT_I + 2 * CM) {
        int r = idx - TOT_U - TOT_I;
        if (r < CM) {
            float a = 0.f;
            #pragma unroll
            for (int j = 0; j < CM; j++) a += bu[j] * W1[j * CM + r];
            g_cu[r] = a;
        } else {
            int c = r - CM;
            float a = 0.f;
            #pragma unroll
            for (int j = 0; j < CM; j++) a += bi[j] * W1[j * CM + c];
            g_ci[c] = a;
        }
    }
}

// ---------------- embed: whole-W smem, barrier-free, 2 NODES PER THREAD ----------------
// Warp-pair column split (wid even -> cols [0,32), odd -> [32,64)); each warp
// covers 64 nodes: lane and lane+32. Each broadcast LDS of W now feeds 4 FFMA2
// (2 nodes x 2 cols) instead of 2 -> smem traffic per FLOP halved.
#define EB_THREADS 256
#define EB_NODES   256          // nodes per block (4 warp-pairs x 64 nodes)
#define EB_SMEM    (UD * CM * 4)   // 64 KB (max of both types)
__global__ __launch_bounds__(EB_THREADS, 2)
void k_embed(const float* __restrict__ ut, const float* __restrict__ it, int userBlocks) {
    extern __shared__ ulonglong2 sW[];
    bool isUser = (int)blockIdx.x < userBlocks;
    int blockLocal = isUser ? blockIdx.x : blockIdx.x - userBlocks;
    int wid = threadIdx.x >> 5;
    int lane = threadIdx.x & 31;
    int half = wid & 1;                      // column half owned by this warp
    int pairBase = blockLocal * EB_NODES + (wid >> 1) * 64;
    int n0 = pairBase + lane;
    int n1 = pairBase + 32 + lane;
    int K = isUser ? UD : ID;
    int Ncnt = isUser ? NU : NI;
    const float* W = isUser ? g_WuW1 : g_WiW1;
    const float* cvec = isUser ? g_cu : g_ci;
    const float* inp = isUser ? ut : it;
    bool act0 = n0 < Ncnt, act1 = n1 < Ncnt;
    const float* xrow0 = inp + (size_t)(act0 ? n0 : 0) * K;
    const float* xrow1 = inp + (size_t)(act1 ? n1 : 0) * K;

    // stage whole W into smem (single barrier)
    {
        const ulonglong2* Wv = (const ulonglong2*)W;
        int nW = K * CM / 4;
        for (int i = threadIdx.x; i < nW; i += EB_THREADS) sW[i] = Wv[i];
    }
    __syncthreads();

    ull a0[16], a1[16];
    #pragma unroll
    for (int i = 0; i < 16; i++) { a0[i] = 0ull; a1[i] = 0ull; }

    #pragma unroll 2
    for (int kb = 0; kb < K; kb += 4) {
        float4 v0 = *(const float4*)(xrow0 + kb);
        float4 v1 = *(const float4*)(xrow1 + kb);
        float x0[4] = {v0.x, v0.y, v0.z, v0.w};
        float x1[4] = {v1.x, v1.y, v1.z, v1.w};
        #pragma unroll
        for (int k = 0; k < 4; k++) {
            ull b0, b1;
            PACK2(b0, x0[k]);
            PACK2(b1, x1[k]);
            #pragma unroll
            for (int c4 = 0; c4 < 8; c4++) {
                ulonglong2 w = sW[(kb + k) * 16 + half * 8 + c4];   // warp-uniform
                FMA2(a0[2 * c4],     b0, w.x, a0[2 * c4]);
                FMA2(a0[2 * c4 + 1], b0, w.y, a0[2 * c4 + 1]);
                FMA2(a1[2 * c4],     b1, w.x, a1[2 * c4]);
                FMA2(a1[2 * c4 + 1], b1, w.y, a1[2 * c4 + 1]);
            }
        }
    }

    int nodeBase = isUser ? 0 : NU;
    const float4* cv4 = (const float4*)(cvec + half * 32);
    if (act0) {
        float4* orow = (float4*)(g_h1 + (size_t)(nodeBase + n0) * CM + half * 32);
        #pragma unroll
        for (int c4 = 0; c4 < 8; c4++) {
            float a, b, c, d;
            UNPACK2(a, b, a0[2 * c4]);
            UNPACK2(c, d, a0[2 * c4 + 1]);
            float4 cv = cv4[c4];
            float4 ov; ov.x = a + cv.x; ov.y = b + cv.y; ov.z = c + cv.z; ov.w = d + cv.w;
            orow[c4] = ov;
        }
    }
    if (act1) {
        float4* orow = (float4*)(g_h1 + (size_t)(nodeBase + n1) * CM + half * 32);
        #pragma unroll
        for (int c4 = 0; c4 < 8; c4++) {
            float a, b, c, d;
            UNPACK2(a, b, a1[2 * c4]);
            UNPACK2(c, d, a1[2 * c4 + 1]);
            float4 cv = cv4[c4];
            float4 ov; ov.x = a + cv.x; ov.y = b + cv.y; ov.z = c + cv.z; ov.w = d + cv.w;
            orow[c4] = ov;
        }
    }
}

// ---------------- graph preprocessing ----------------
__global__ void k_edge1(const int* __restrict__ ei32, const float* __restrict__ ew) {
    int t = blockIdx.x * blockDim.x + threadIdx.x;
    int e = 2 * t;
    if (e >= NE) return;
    int d0, d1;
    if (g_is64) {
        int4 v = *(const int4*)(ei32 + 2 * (NE + e));
        d0 = v.x; d1 = v.z;
    } else {
        int2 v = *(const int2*)(ei32 + NE + e);
        d0 = v.x; d1 = v.y;
    }
    float2 w = *(const float2*)(ew + e);
    atomicAdd(&g_count[d0], 1);
    atomicAdd(&g_deg[d0], w.x);
    atomicAdd(&g_count[d1], 1);
    atomicAdd(&g_deg[d1], w.y);
}

__global__ void k_scan1() {
    __shared__ int sh[SCAN_BLK];
    int t = threadIdx.x;
    int gid = blockIdx.x * SCAN_BLK + t;
    int v = (gid < NN) ? g_count[gid] : 0;
    sh[t] = v;
    __syncthreads();
    for (int off = 1; off < SCAN_BLK; off <<= 1) {
        int x = (t >= off) ? sh[t - off] : 0;
        __syncthreads();
        sh[t] += x;
        __syncthreads();
    }
    if (gid < NN) {
        g_rowstart[gid] = sh[t] - v;
        float dg = g_deg[gid];
        g_dinv[gid] = (dg > 0.0f) ? rsqrtf(dg) : 0.0f;
    }
    if (t == SCAN_BLK - 1) g_bsum[blockIdx.x] = sh[t];
}

__global__ void k_scan2() {
    __shared__ int sh[SCAN_BLK];
    int t = threadIdx.x;
    int v = (t < NSCAN_BLKS) ? g_bsum[t] : 0;
    sh[t] = v;
    __syncthreads();
    for (int off = 1; off < SCAN_BLK; off <<= 1) {
        int x = (t >= off) ? sh[t - off] : 0;
        __syncthreads();
        sh[t] += x;
        __syncthreads();
    }
    if (t < NSCAN_BLKS) g_bsum[t] = sh[t] - v;
}

__global__ void k_scan3() {
    int i = blockIdx.x * blockDim.x + threadIdx.x;
    if (i < NN) {
        int rs = g_rowstart[i] + g_bsum[i >> 10];
        g_rowstart[i] = rs;
        g_cursor[i] = rs;
    }
    if (i == 0) g_rowstart[NN] = NE;
}

__global__ void k_scatter(const int* __restrict__ ei32, const float* __restrict__ ew) {
    int e = blockIdx.x * blockDim.x + threadIdx.x;
    if (e >= NE) return;
    int s, d;
    if (g_is64) { s = ei32[2 * e]; d = ei32[2 * (NE + e)]; }
    else        { s = ei32[e];     d = ei32[NE + e]; }
    float nrm = g_dinv[s] * ew[e] * g_dinv[d];
    int pos = atomicAdd(&g_cursor[d], 1);
    g_csr[pos] = (ull)(unsigned)s | ((ull)__float_as_uint(nrm) << 32);
}

// ---------------- gather1: aggregate h1 + bias + relu -> z1 (warp/node, f32x2) ----------------
__global__ void k_gather1(const float* __restrict__ b1) {
    int t = threadIdx.x;
    int node = blockIdx.x * (blockDim.x >> 5) + (t >> 5);
    int lane = t & 31;
    if (node >= NN) return;

    const ull* h = (const ull*)g_h1;
    float dv = g_dinv[node];
    ull sw; PACK2(sw, dv * dv);
    ull zero = 0ull;
    ull acc; FMA2(acc, sw, h[(size_t)node * 32 + lane], zero);

    int e = g_rowstart[node], end = g_rowstart[node + 1];
    for (; e + 4 <= end; e += 4) {
        ull p0 = g_csr[e], p1 = g_csr[e + 1], p2 = g_csr[e + 2], p3 = g_csr[e + 3];
        int s0 = (int)(unsigned)p0, s1 = (int)(unsigned)p1;
        int s2 = (int)(unsigned)p2, s3 = (int)(unsigned)p3;
        ull v0 = h[(size_t)s0 * 32 + lane];
        ull v1 = h[(size_t)s1 * 32 + lane];
        ull v2 = h[(size_t)s2 * 32 + lane];
        ull v3 = h[(size_t)s3 * 32 + lane];
        float w0 = __uint_as_float((unsigned)(p0 >> 32));
        float w1 = __uint_as_float((unsigned)(p1 >> 32));
        float w2 = __uint_as_float((unsigned)(p2 >> 32));
        float w3 = __uint_as_float((unsigned)(p3 >> 32));
        ull q0, q1, q2, q3;
        PACK2(q0, w0); PACK2(q1, w1); PACK2(q2, w2); PACK2(q3, w3);
        FMA2(acc, q0, v0, acc);
        FMA2(acc, q1, v1, acc);
        FMA2(acc, q2, v2, acc);
        FMA2(acc, q3, v3, acc);
    }
    for (; e < end; e++) {
        ull p = g_csr[e];
        int s = (int)(unsigned)p;
        float w = __uint_as_float((unsigned)(p >> 32));
        ull q; PACK2(q, w);
        FMA2(acc, q, h[(size_t)s * 32 + lane], acc);
    }
    float ax, ay; UNPACK2(ax, ay, acc);
    float2 bb = ((const float2*)b1)[lane];
    float2 z;
    z.x = fmaxf(ax + bb.x, 0.0f);
    z.y = fmaxf(ay + bb.y, 0.0f);
    ((float2*)(g_z1 + (size_t)node * CM))[lane] = z;
}

// ---------------- xform: h2 = z1 @ W2 (per-thread node, f32x2) ----------------
#define XF_THREADS 256
__global__ __launch_bounds__(XF_THREADS)
void k_xform(const float* __restrict__ W2) {
    __shared__ ulonglong2 sW2[CM * 8];   // 8 KB = 512 ulonglong2
    sW2[threadIdx.x]       = ((const ulonglong2*)W2)[threadIdx.x];
    sW2[threadIdx.x + 256] = ((const ulonglong2*)W2)[threadIdx.x + 256];
    __syncthreads();

    int node = blockIdx.x * XF_THREADS + threadIdx.x;
    if (node >= NN) return;
    const float* xrow = g_z1 + (size_t)node * CM;

    ull acc[16];
    #pragma unroll
    for (int i = 0; i < 16; i++) acc[i] = 0ull;

    #pragma unroll
    for (int kb = 0; kb < CM; kb += 16) {
        float x[16];
        #pragma unroll
        for (int q = 0; q < 4; q++) {
            float4 v = ((const float4*)(xrow + kb))[q];
            x[4 * q] = v.x; x[4 * q + 1] = v.y; x[4 * q + 2] = v.z; x[4 * q + 3] = v.w;
        }
        #pragma unroll
        for (int k = 0; k < 16; k++) {
            ull bk; PACK2(bk, x[k]);
            #pragma unroll
            for (int c4 = 0; c4 < 8; c4++) {
                ulonglong2 w = sW2[(kb + k) * 8 + c4];
                FMA2(acc[2 * c4],     bk, w.x, acc[2 * c4]);
                FMA2(acc[2 * c4 + 1], bk, w.y, acc[2 * c4 + 1]);
            }
        }
    }
    float4* orow = (float4*)(g_h2 + (size_t)node * OD);
    #pragma unroll
    for (int c4 = 0; c4 < 8; c4++) {
        float a, b, c, d;
        UNPACK2(a, b, acc[2 * c4]);
        UNPACK2(c, d, acc[2 * c4 + 1]);
        float4 ov; ov.x = a; ov.y = b; ov.z = c; ov.w = d;
        orow[c4] = ov;
    }
}

// ---------------- gather2: aggregate h2 + b2 -> out (dual half-warp, f32x2) ----------------
__global__ void k_gather2(const float* __restrict__ b2, float* __restrict__ out) {
    int t = threadIdx.x;
    int node = blockIdx.x * (blockDim.x >> 5) + (t >> 5);
    int lane = t & 31;
    if (node >= NN) return;
    int half = lane >> 4;
    int c = lane & 15;

    const ull* h = (const ull*)g_h2;
    ull acc = 0ull;
    if (half == 0) {
        float dv = g_dinv[node];
        ull sw; PACK2(sw, dv * dv);
        ull zero = 0ull;
        FMA2(acc, sw, h[(size_t)node * 16 + c], zero);
    }
    int beg = g_rowstart[node], end = g_rowstart[node + 1];
    int e = beg + half;
    for (; e + 2 < end; e += 4) {
        ull p0 = g_csr[e], p1 = g_csr[e + 2];
        int s0 = (int)(unsigned)p0, s1 = (int)(unsigned)p1;
        ull v0 = h[(size_t)s0 * 16 + c];
        ull v1 = h[(size_t)s1 * 16 + c];
        float w0 = __uint_as_float((unsigned)(p0 >> 32));
        float w1 = __uint_as_float((unsigned)(p1 >> 32));
        ull q0, q1; PACK2(q0, w0); PACK2(q1, w1);
        FMA2(acc, q0, v0, acc);
        FMA2(acc, q1, v1, acc);
    }
    if (e < end) {
        ull p = g_csr[e];
        int s = (int)(unsigned)p;
        float w = __uint_as_float((unsigned)(p >> 32));
        ull q; PACK2(q, w);
        FMA2(acc, q, h[(size_t)s * 16 + c], acc);
    }
    float ax, ay; UNPACK2(ax, ay, acc);
    ax += __shfl_xor_sync(0xffffffffu, ax, 16);
    ay += __shfl_xor_sync(0xffffffffu, ay, 16);
    if (half == 0) {
        float2 bb = ((const float2*)b2)[c];
        float2 ov; ov.x = ax + bb.x; ov.y = ay + bb.y;
        ((float2*)(out + (size_t)node * OD))[c] = ov;
    }
}

// ---------------- launch ----------------
extern "C" void kernel_launch(void* const* d_in, const int* in_sizes, int n_in,
                              void* d_out, int out_size) {
    const float* ut = (const float*)d_in[0];
    const float* it = (const float*)d_in[1];
    const int*   ei = (const int*)d_in[2];
    const float* ew = (const float*)d_in[3];
    const float* Wu = (const float*)d_in[4];
    const float* bu = (const float*)d_in[5];
    const float* Wi = (const float*)d_in[6];
    const float* bi = (const float*)d_in[7];
    const float* W1 = (const float*)d_in[8];
    const float* b1 = (const float*)d_in[9];
    const float* W2 = (const float*)d_in[10];
    const float* b2 = (const float*)d_in[11];
    float*       out = (float*)d_out;

    cudaFuncSetAttribute(k_embed, cudaFuncAttributeMaxDynamicSharedMemorySize, EB_SMEM);

    int userBlocks = (NU + EB_NODES - 1) / EB_NODES;    // 391
    int itemBlocks = (NI + EB_NODES - 1) / EB_NODES;    // 391

    // launch order arranged so k_embed is the 4th launch (ncu capture slot)
    k_detect<<<1, 256>>>(ei);                                              // 1
    k_init<<<(NN + 255) / 256, 256>>>();                                   // 2
    k_wcomb<<<(UD * CM + ID * CM + 2 * CM + 127) / 128, 128>>>(Wu, bu, Wi, bi, W1); // 3
    k_embed<<<userBlocks + itemBlocks, EB_THREADS, EB_SMEM>>>(ut, it, userBlocks);  // 4 <- profiled
    k_edge1<<<(NE / 2 + 255) / 256, 256>>>(ei, ew);                        // 5
    k_scan1<<<NSCAN_BLKS, SCAN_BLK>>>();                                   // 6
    k_scan2<<<1, SCAN_BLK>>>();                                            // 7
    k_scan3<<<(NN + 255) / 256, 256>>>();                                  // 8
    k_scatter<<<(NE + 255) / 256, 256>>>(ei, ew);                          // 9
    k_gather1<<<NN / 8, 256>>>(b1);                                        // 10
    k_xform<<<(NN + XF_THREADS - 1) / XF_THREADS, XF_THREADS>>>(W2);       // 11
    k_gather2<<<NN / 8, 256>>>(b2, out);                                   // 12
}

// round 12
// speedup vs baseline: 1.3837x; 1.0592x over previous
#include <cuda_runtime.h>
#include <cuda_bf16.h>
#include <cuda_fp16.h>
#include <stdint.h>

typedef unsigned long long ull;

#define NU 100000
#define NI 100000
#define NN 200000
#define NE 4000000
#define UD 256
#define ID 128
#define CM 64
#define OD 32
#define SCAN_BLK 1024
#define NSCAN_BLKS ((NN + SCAN_BLK - 1) / SCAN_BLK)

// f32x2 packed helpers
#define FMA2(d, a, b, c) asm("fma.rn.f32x2 %0, %1, %2, %3;" : "=l"(d) : "l"(a), "l"(b), "l"(c))
#define PACK2(d, x)      asm("mov.b64 %0, {%1, %1};" : "=l"(d) : "f"(x))
#define PACKF2(d, lo, hi) asm("mov.b64 %0, {%1, %2};" : "=l"(d) : "f"(lo), "f"(hi))
#define UNPACK2(lo, hi, v) asm("mov.b64 {%0, %1}, %2;" : "=f"(lo), "=f"(hi) : "l"(v))

// ---------------- scratch ----------------
__device__ ull   g_pack[NN];              // hi24: count<<40 | lo40: deg fixed-point (2^-20)
__device__ float g_dinv[NN];
__device__ int   g_rowstart[NN + 1];
__device__ int   g_cursor[NN];
__device__ int   g_bsum[SCAN_BLK];
__device__ ull   g_csr[NE];               // packed: lo32 = src, hi32 = norm bits
__device__ float g_WuW1[UD * CM];
__device__ float g_WiW1[ID * CM];
__device__ float g_cu[CM];
__device__ float g_ci[CM];
__device__ __half g_h1h[(size_t)NN * CM]; // 25.6 MB  embed output (fp16)
__device__ float  g_z1[(size_t)NN * CM];  // 51.2 MB  relu(agg1+b1) (fp32)
__device__ __half g_h2h[(size_t)NN * OD]; // 12.8 MB  z1 @ W2 (fp16)
__device__ int   g_is64;

// ---------------- dtype detection ----------------
__global__ void k_detect(const int* __restrict__ ei32) {
    __shared__ int any_nonzero;
    if (threadIdx.x == 0) any_nonzero = 0;
    __syncthreads();
    for (int i = 2 * threadIdx.x + 1; i < 4096; i += 2 * blockDim.x)
        if (ei32[i] != 0) any_nonzero = 1;
    __syncthreads();
    if (threadIdx.x == 0) g_is64 = any_nonzero ? 0 : 1;
}

__global__ void k_init() {
    int i = blockIdx.x * blockDim.x + threadIdx.x;
    if (i < NN) g_pack[i] = 0ull;
}

// ---------------- weight folding ----------------
__global__ void k_wcomb(const float* __restrict__ Wu, const float* __restrict__ bu,
                        const float* __restrict__ Wi, const float* __restrict__ bi,
                        const float* __restrict__ W1) {
    int idx = blockIdx.x * blockDim.x + threadIdx.x;
    const int TOT_U = UD * CM, TOT_I = ID * CM;
    if (idx < TOT_U) {
        int k = idx / CM, c = idx % CM;
        float a = 0.f;
        #pragma unroll
        for (int j = 0; j < CM; j++) a += Wu[k * CM + j] * W1[j * CM + c];
        g_WuW1[idx] = a;
    } else if (idx < TOT_U + TOT_I) {
        int r = idx - TOT_U;
        int k = r / CM, c = r % CM;
        float a = 0.f;
        #pragma unroll
        for (int j = 0; j < CM; j++) a += Wi[k * CM + j] * W1[j * CM + c];
        g_WiW1[r] = a;
    } else if (idx < TOT_U + TOT_I + 2 * CM) {
        int r = idx - TOT_U - TOT_I;
        if (r < CM) {
            float a = 0.f;
            #pragma unroll
            for (int j = 0; j < CM; j++) a += bu[j] * W1[j * CM + r];
            g_cu[r] = a;
        } else {
            int c = r - CM;
            float a = 0.f;
            #pragma unroll
            for (int j = 0; j < CM; j++) a += bi[j] * W1[j * CM + c];
            g_ci[c] = a;
        }
    }
}

// ---------------- embed: whole-W smem, barrier-free, 2 nodes/thread, fp16 output ----------------
#define EB_THREADS 256
#define EB_NODES   256
#define EB_SMEM    (UD * CM * 4)   // 64 KB
__global__ __launch_bounds__(EB_THREADS, 2)
void k_embed(const float* __restrict__ ut, const float* __restrict__ it, int userBlocks) {
    extern __shared__ ulonglong2 sW[];
    bool isUser = (int)blockIdx.x < userBlocks;
    int blockLocal = isUser ? blockIdx.x : blockIdx.x - userBlocks;
    int wid = threadIdx.x >> 5;
    int lane = threadIdx.x & 31;
    int half = wid & 1;
    int pairBase = blockLocal * EB_NODES + (wid >> 1) * 64;
    int n0 = pairBase + lane;
    int n1 = pairBase + 32 + lane;
    int K = isUser ? UD : ID;
    int Ncnt = isUser ? NU : NI;
    const float* W = isUser ? g_WuW1 : g_WiW1;
    const float* cvec = isUser ? g_cu : g_ci;
    const float* inp = isUser ? ut : it;
    bool act0 = n0 < Ncnt, act1 = n1 < Ncnt;
    const float* xrow0 = inp + (size_t)(act0 ? n0 : 0) * K;
    const float* xrow1 = inp + (size_t)(act1 ? n1 : 0) * K;

    {
        const ulonglong2* Wv = (const ulonglong2*)W;
        int nW = K * CM / 4;
        for (int i = threadIdx.x; i < nW; i += EB_THREADS) sW[i] = Wv[i];
    }
    __syncthreads();

    ull a0[16], a1[16];
    #pragma unroll
    for (int i = 0; i < 16; i++) { a0[i] = 0ull; a1[i] = 0ull; }

    #pragma unroll 2
    for (int kb = 0; kb < K; kb += 4) {
        float4 v0 = *(const float4*)(xrow0 + kb);
        float4 v1 = *(const float4*)(xrow1 + kb);
        float x0[4] = {v0.x, v0.y, v0.z, v0.w};
        float x1[4] = {v1.x, v1.y, v1.z, v1.w};
        #pragma unroll
        for (int k = 0; k < 4; k++) {
            ull b0, b1;
            PACK2(b0, x0[k]);
            PACK2(b1, x1[k]);
            #pragma unroll
            for (int c4 = 0; c4 < 8; c4++) {
                ulonglong2 w = sW[(kb + k) * 16 + half * 8 + c4];   // warp-uniform
                FMA2(a0[2 * c4],     b0, w.x, a0[2 * c4]);
                FMA2(a0[2 * c4 + 1], b0, w.y, a0[2 * c4 + 1]);
                FMA2(a1[2 * c4],     b1, w.x, a1[2 * c4]);
                FMA2(a1[2 * c4 + 1], b1, w.y, a1[2 * c4 + 1]);
            }
        }
    }

    int nodeBase = isUser ? 0 : NU;
    const float4* cv4 = (const float4*)(cvec + half * 32);
    if (act0) {
        uint2* orow = (uint2*)(g_h1h + (size_t)(nodeBase + n0) * CM + half * 32);
        #pragma unroll
        for (int c4 = 0; c4 < 8; c4++) {
            float a, b, c, d;
            UNPACK2(a, b, a0[2 * c4]);
            UNPACK2(c, d, a0[2 * c4 + 1]);
            float4 cv = cv4[c4];
            __half2 p0 = __floats2half2_rn(a + cv.x, b + cv.y);
            __half2 p1 = __floats2half2_rn(c + cv.z, d + cv.w);
            uint2 ov; ov.x = *(unsigned*)&p0; ov.y = *(unsigned*)&p1;
            orow[c4] = ov;
        }
    }
    if (act1) {
        uint2* orow = (uint2*)(g_h1h + (size_t)(nodeBase + n1) * CM + half * 32);
        #pragma unroll
        for (int c4 = 0; c4 < 8; c4++) {
            float a, b, c, d;
            UNPACK2(a, b, a1[2 * c4]);
            UNPACK2(c, d, a1[2 * c4 + 1]);
            float4 cv = cv4[c4];
            __half2 p0 = __floats2half2_rn(a + cv.x, b + cv.y);
            __half2 p1 = __floats2half2_rn(c + cv.z, d + cv.w);
            uint2 ov; ov.x = *(unsigned*)&p0; ov.y = *(unsigned*)&p1;
            orow[c4] = ov;
        }
    }
}

// ---------------- graph preprocessing ----------------
// single packed ull atomic per edge: (1<<40) | round(ew * 2^20)
__global__ void k_edge1(const int* __restrict__ ei32, const float* __restrict__ ew) {
    int t = blockIdx.x * blockDim.x + threadIdx.x;
    int e = 2 * t;
    if (e >= NE) return;
    int d0, d1;
    if (g_is64) {
        int4 v = *(const int4*)(ei32 + 2 * (NE + e));
        d0 = v.x; d1 = v.z;
    } else {
        int2 v = *(const int2*)(ei32 + NE + e);
        d0 = v.x; d1 = v.y;
    }
    float2 w = *(const float2*)(ew + e);
    ull add0 = (1ull << 40) | (ull)__float2uint_rn(w.x * 1048576.0f);
    ull add1 = (1ull << 40) | (ull)__float2uint_rn(w.y * 1048576.0f);
    atomicAdd(&g_pack[d0], add0);
    atomicAdd(&g_pack[d1], add1);
}

__global__ void k_scan1() {
    __shared__ int sh[SCAN_BLK];
    int t = threadIdx.x;
    int gid = blockIdx.x * SCAN_BLK + t;
    int v = 0;
    float deg = 1.0f;
    if (gid < NN) {
        ull p = g_pack[gid];
        v = (int)(p >> 40);
        deg = 1.0f + (float)(p & 0xFFFFFFFFFFull) * (1.0f / 1048576.0f);
    }
    sh[t] = v;
    __syncthreads();
    for (int off = 1; off < SCAN_BLK; off <<= 1) {
        int x = (t >= off) ? sh[t - off] : 0;
        __syncthreads();
        sh[t] += x;
        __syncthreads();
    }
    if (gid < NN) {
        g_rowstart[gid] = sh[t] - v;
        g_dinv[gid] = (deg > 0.0f) ? rsqrtf(deg) : 0.0f;
    }
    if (t == SCAN_BLK - 1) g_bsum[blockIdx.x] = sh[t];
}

__global__ void k_scan2() {
    __shared__ int sh[SCAN_BLK];
    int t = threadIdx.x;
    int v = (t < NSCAN_BLKS) ? g_bsum[t] : 0;
    sh[t] = v;
    __syncthreads();
    for (int off = 1; off < SCAN_BLK; off <<= 1) {
        int x = (t >= off) ? sh[t - off] : 0;
        __syncthreads();
        sh[t] += x;
        __syncthreads();
    }
    if (t < NSCAN_BLKS) g_bsum[t] = sh[t] - v;
}

__global__ void k_scan3() {
    int i = blockIdx.x * blockDim.x + threadIdx.x;
    if (i < NN) {
        int rs = g_rowstart[i] + g_bsum[i >> 10];
        g_rowstart[i] = rs;
        g_cursor[i] = rs;
    }
    if (i == 0) g_rowstart[NN] = NE;
}

__global__ void k_scatter(const int* __restrict__ ei32, const float* __restrict__ ew) {
    int e = blockIdx.x * blockDim.x + threadIdx.x;
    if (e >= NE) return;
    int s, d;
    if (g_is64) { s = ei32[2 * e]; d = ei32[2 * (NE + e)]; }
    else        { s = ei32[e];     d = ei32[NE + e]; }
    float nrm = g_dinv[s] * ew[e] * g_dinv[d];
    int pos = atomicAdd(&g_cursor[d], 1);
    g_csr[pos] = (ull)(unsigned)s | ((ull)__float_as_uint(nrm) << 32);
}

// ---------------- gather1: aggregate fp16 h1 + bias + relu -> z1 (warp/node) ----------------
__global__ void k_gather1(const float* __restrict__ b1) {
    int t = threadIdx.x;
    int node = blockIdx.x * (blockDim.x >> 5) + (t >> 5);
    int lane = t & 31;
    if (node >= NN) return;

    const unsigned* h = (const unsigned*)g_h1h;    // half2 per entry; 32 per row
    float dv = g_dinv[node];
    float sw = dv * dv;
    unsigned us = h[(size_t)node * 32 + lane];
    float2 fs = __half22float2(*(const __half2*)&us);
    ull acc; PACKF2(acc, sw * fs.x, sw * fs.y);

    int e = g_rowstart[node], end = g_rowstart[node + 1];
    for (; e + 4 <= end; e += 4) {
        ull p0 = g_csr[e], p1 = g_csr[e + 1], p2 = g_csr[e + 2], p3 = g_csr[e + 3];
        unsigned u0 = h[(size_t)(unsigned)p0 * 32 + lane];
        unsigned u1 = h[(size_t)(unsigned)p1 * 32 + lane];
        unsigned u2 = h[(size_t)(unsigned)p2 * 32 + lane];
        unsigned u3 = h[(size_t)(unsigned)p3 * 32 + lane];
        float2 f0 = __half22float2(*(const __half2*)&u0);
        float2 f1 = __half22float2(*(const __half2*)&u1);
        float2 f2 = __half22float2(*(const __half2*)&u2);
        float2 f3 = __half22float2(*(const __half2*)&u3);
        ull v0, v1, v2, v3;
        PACKF2(v0, f0.x, f0.y); PACKF2(v1, f1.x, f1.y);
        PACKF2(v2, f2.x, f2.y); PACKF2(v3, f3.x, f3.y);
        ull q0, q1, q2, q3;
        PACK2(q0, __uint_as_float((unsigned)(p0 >> 32)));
        PACK2(q1, __uint_as_float((unsigned)(p1 >> 32)));
        PACK2(q2, __uint_as_float((unsigned)(p2 >> 32)));
        PACK2(q3, __uint_as_float((unsigned)(p3 >> 32)));
        FMA2(acc, q0, v0, acc);
        FMA2(acc, q1, v1, acc);
        FMA2(acc, q2, v2, acc);
        FMA2(acc, q3, v3, acc);
    }
    for (; e < end; e++) {
        ull p = g_csr[e];
        unsigned u = h[(size_t)(unsigned)p * 32 + lane];
        float2 f = __half22float2(*(const __half2*)&u);
        ull v; PACKF2(v, f.x, f.y);
        ull q; PACK2(q, __uint_as_float((unsigned)(p >> 32)));
        FMA2(acc, q, v, acc);
    }
    float ax, ay; UNPACK2(ax, ay, acc);
    float2 bb = ((const float2*)b1)[lane];
    float2 z;
    z.x = fmaxf(ax + bb.x, 0.0f);
    z.y = fmaxf(ay + bb.y, 0.0f);
    ((float2*)(g_z1 + (size_t)node * CM))[lane] = z;
}

// ---------------- xform: h2 = z1 @ W2 (per-thread node, f32x2, fp16 output) ----------------
#define XF_THREADS 256
__global__ __launch_bounds__(XF_THREADS)
void k_xform(const float* __restrict__ W2) {
    __shared__ ulonglong2 sW2[CM * 8];   // 8 KB
    sW2[threadIdx.x]       = ((const ulonglong2*)W2)[threadIdx.x];
    sW2[threadIdx.x + 256] = ((const ulonglong2*)W2)[threadIdx.x + 256];
    __syncthreads();

    int node = blockIdx.x * XF_THREADS + threadIdx.x;
    if (node >= NN) return;
    const float* xrow = g_z1 + (size_t)node * CM;

    ull acc[16];
    #pragma unroll
    for (int i = 0; i < 16; i++) acc[i] = 0ull;

    #pragma unroll
    for (int kb = 0; kb < CM; kb += 16) {
        float x[16];
        #pragma unroll
        for (int q = 0; q < 4; q++) {
            float4 v = ((const float4*)(xrow + kb))[q];
            x[4 * q] = v.x; x[4 * q + 1] = v.y; x[4 * q + 2] = v.z; x[4 * q + 3] = v.w;
        }
        #pragma unroll
        for (int k = 0; k < 16; k++) {
            ull bk; PACK2(bk, x[k]);
            #pragma unroll
            for (int c4 = 0; c4 < 8; c4++) {
                ulonglong2 w = sW2[(kb + k) * 8 + c4];
                FMA2(acc[2 * c4],     bk, w.x, acc[2 * c4]);
                FMA2(acc[2 * c4 + 1], bk, w.y, acc[2 * c4 + 1]);
            }
        }
    }
    uint2* orow = (uint2*)(g_h2h + (size_t)node * OD);
    #pragma unroll
    for (int c4 = 0; c4 < 8; c4++) {
        float a, b, c, d;
        UNPACK2(a, b, acc[2 * c4]);
        UNPACK2(c, d, acc[2 * c4 + 1]);
        __half2 p0 = __floats2half2_rn(a, b);
        __half2 p1 = __floats2half2_rn(c, d);
        uint2 ov; ov.x = *(unsigned*)&p0; ov.y = *(unsigned*)&p1;
        orow[c4] = ov;
    }
}

// ---------------- gather2: aggregate fp16 h2 + b2 -> out (dual half-warp) ----------------
__global__ void k_gather2(const float* __restrict__ b2, float* __restrict__ out) {
    int t = threadIdx.x;
    int node = blockIdx.x * (blockDim.x >> 5) + (t >> 5);
    int lane = t & 31;
    if (node >= NN) return;
    int half = lane >> 4;
    int c = lane & 15;

    const unsigned* h = (const unsigned*)g_h2h;    // half2 per entry; 16 per row
    ull acc = 0ull;
    if (half == 0) {
        float dv = g_dinv[node];
        float sw = dv * dv;
        unsigned us = h[(size_t)node * 16 + c];
        float2 fs = __half22float2(*(const __half2*)&us);
        PACKF2(acc, sw * fs.x, sw * fs.y);
    }
    int beg = g_rowstart[node], end = g_rowstart[node + 1];
    int e = beg + half;
    for (; e + 2 < end; e += 4) {
        ull p0 = g_csr[e], p1 = g_csr[e + 2];
        unsigned u0 = h[(size_t)(unsigned)p0 * 16 + c];
        unsigned u1 = h[(size_t)(unsigned)p1 * 16 + c];
        float2 f0 = __half22float2(*(const __half2*)&u0);
        float2 f1 = __half22float2(*(const __half2*)&u1);
        ull v0, v1;
        PACKF2(v0, f0.x, f0.y); PACKF2(v1, f1.x, f1.y);
        ull q0, q1;
        PACK2(q0, __uint_as_float((unsigned)(p0 >> 32)));
        PACK2(q1, __uint_as_float((unsigned)(p1 >> 32)));
        FMA2(acc, q0, v0, acc);
        FMA2(acc, q1, v1, acc);
    }
    if (e < end) {
        ull p = g_csr[e];
        unsigned u = h[(size_t)(unsigned)p * 16 + c];
        float2 f = __half22float2(*(const __half2*)&u);
        ull v; PACKF2(v, f.x, f.y);
        ull q; PACK2(q, __uint_as_float((unsigned)(p >> 32)));
        FMA2(acc, q, v, acc);
    }
    float ax, ay; UNPACK2(ax, ay, acc);
    ax += __shfl_xor_sync(0xffffffffu, ax, 16);
    ay += __shfl_xor_sync(0xffffffffu, ay, 16);
    if (half == 0) {
        float2 bb = ((const float2*)b2)[c];
        float2 ov; ov.x = ax + bb.x; ov.y = ay + bb.y;
        ((float2*)(out + (size_t)node * OD))[c] = ov;
    }
}

// ---------------- launch ----------------
extern "C" void kernel_launch(void* const* d_in, const int* in_sizes, int n_in,
                              void* d_out, int out_size) {
    const float* ut = (const float*)d_in[0];
    const float* it = (const float*)d_in[1];
    const int*   ei = (const int*)d_in[2];
    const float* ew = (const float*)d_in[3];
    const float* Wu = (const float*)d_in[4];
    const float* bu = (const float*)d_in[5];
    const float* Wi = (const float*)d_in[6];
    const float* bi = (const float*)d_in[7];
    const float* W1 = (const float*)d_in[8];
    const float* b1 = (const float*)d_in[9];
    const float* W2 = (const float*)d_in[10];
    const float* b2 = (const float*)d_in[11];
    float*       out = (float*)d_out;

    cudaFuncSetAttribute(k_embed, cudaFuncAttributeMaxDynamicSharedMemorySize, EB_SMEM);

    int userBlocks = (NU + EB_NODES - 1) / EB_NODES;    // 391
    int itemBlocks = (NI + EB_NODES - 1) / EB_NODES;    // 391

    // launch order arranged so k_embed is the 4th launch (ncu capture slot)
    k_detect<<<1, 256>>>(ei);                                              // 1
    k_init<<<(NN + 255) / 256, 256>>>();                                   // 2
    k_wcomb<<<(UD * CM + ID * CM + 2 * CM + 127) / 128, 128>>>(Wu, bu, Wi, bi, W1); // 3
    k_embed<<<userBlocks + itemBlocks, EB_THREADS, EB_SMEM>>>(ut, it, userBlocks);  // 4 <- profiled
    k_edge1<<<(NE / 2 + 255) / 256, 256>>>(ei, ew);                        // 5
    k_scan1<<<NSCAN_BLKS, SCAN_BLK>>>();                                   // 6
    k_scan2<<<1, SCAN_BLK>>>();                                            // 7
    k_scan3<<<(NN + 255) / 256, 256>>>();                                  // 8
    k_scatter<<<(NE + 255) / 256, 256>>>(ei, ew);                          // 9
    k_gather1<<<NN / 8, 256>>>(b1);                                        // 10
    k_xform<<<(NN + XF_THREADS - 1) / XF_THREADS, XF_THREADS>>>(W2);       // 11
    k_gather2<<<NN / 8, 256>>>(b2, out);                                   // 12
}

// round 13
// speedup vs baseline: 1.3875x; 1.0027x over previous
#include <cuda_runtime.h>
#include <cuda_bf16.h>
#include <cuda_fp16.h>
#include <stdint.h>

typedef unsigned long long ull;

#define NU 100000
#define NI 100000
#define NN 200000
#define NE 4000000
#define UD 256
#define ID 128
#define CM 64
#define OD 32
#define SCAN_BLK 1024
#define NSCAN_BLKS ((NN + SCAN_BLK - 1) / SCAN_BLK)

// f32x2 packed helpers
#define FMA2(d, a, b, c) asm("fma.rn.f32x2 %0, %1, %2, %3;" : "=l"(d) : "l"(a), "l"(b), "l"(c))
#define PACK2(d, x)      asm("mov.b64 %0, {%1, %1};" : "=l"(d) : "f"(x))
#define PACKF2(d, lo, hi) asm("mov.b64 %0, {%1, %2};" : "=l"(d) : "f"(lo), "f"(hi))
#define UNPACK2(lo, hi, v) asm("mov.b64 {%0, %1}, %2;" : "=f"(lo), "=f"(hi) : "l"(v))

// ---------------- scratch ----------------
__device__ ull   g_pack[NN];              // count<<40 | deg fixed-point (2^-20)
__device__ float g_dinv[NN];
__device__ int   g_rowstart[NN + 1];
__device__ int   g_cursor[NN];
__device__ int   g_bsum[SCAN_BLK];
__device__ ull   g_csr[NE];               // packed: lo32 = src, hi32 = ew bits
__device__ float g_WuW1[UD * CM];
__device__ float g_WiW1[ID * CM];
__device__ float g_cu[CM];
__device__ float g_ci[CM];
__device__ __half g_h1h[(size_t)NN * CM]; // 25.6 MB  dinv-scaled embed output (fp16)
__device__ float  g_z1[(size_t)NN * CM];  // 51.2 MB  dinv-scaled relu(agg1+b1) (fp32)
__device__ __half g_h2h[(size_t)NN * OD]; // 12.8 MB  z1' @ W2 (fp16, dinv-scaled)
__device__ int   g_is64;

// ---------------- dtype detection ----------------
__global__ void k_detect(const int* __restrict__ ei32) {
    __shared__ int any_nonzero;
    if (threadIdx.x == 0) any_nonzero = 0;
    __syncthreads();
    for (int i = 2 * threadIdx.x + 1; i < 4096; i += 2 * blockDim.x)
        if (ei32[i] != 0) any_nonzero = 1;
    __syncthreads();
    if (threadIdx.x == 0) g_is64 = any_nonzero ? 0 : 1;
}

__global__ void k_init() {
    int i = blockIdx.x * blockDim.x + threadIdx.x;
    if (i < NN) g_pack[i] = 0ull;
}

// ---------------- weight folding ----------------
__global__ void k_wcomb(const float* __restrict__ Wu, const float* __restrict__ bu,
                        const float* __restrict__ Wi, const float* __restrict__ bi,
                        const float* __restrict__ W1) {
    int idx = blockIdx.x * blockDim.x + threadIdx.x;
    const int TOT_U = UD * CM, TOT_I = ID * CM;
    if (idx < TOT_U) {
        int k = idx / CM, c = idx % CM;
        float a = 0.f;
        #pragma unroll
        for (int j = 0; j < CM; j++) a += Wu[k * CM + j] * W1[j * CM + c];
        g_WuW1[idx] = a;
    } else if (idx < TOT_U + TOT_I) {
        int r = idx - TOT_U;
        int k = r / CM, c = r % CM;
        float a = 0.f;
        #pragma unroll
        for (int j = 0; j < CM; j++) a += Wi[k * CM + j] * W1[j * CM + c];
        g_WiW1[r] = a;
    } else if (idx < TOT_U + TOT_I + 2 * CM) {
        int r = idx - TOT_U - TOT_I;
        if (r < CM) {
            float a = 0.f;
            #pragma unroll
            for (int j = 0; j < CM; j++) a += bu[j] * W1[j * CM + r];
            g_cu[r] = a;
        } else {
            int c = r - CM;
            float a = 0.f;
            #pragma unroll
            for (int j = 0; j < CM; j++) a += bi[j] * W1[j * CM + c];
            g_ci[c] = a;
        }
    }
}

// ---------------- edge pass: packed count+deg atomic (PROFILED SLOT) ----------------
__global__ void k_edge1(const int* __restrict__ ei32, const float* __restrict__ ew) {
    int t = blockIdx.x * blockDim.x + threadIdx.x;
    int e = 2 * t;
    if (e >= NE) return;
    int d0, d1;
    if (g_is64) {
        int4 v = *(const int4*)(ei32 + 2 * (NE + e));
        d0 = v.x; d1 = v.z;
    } else {
        int2 v = *(const int2*)(ei32 + NE + e);
        d0 = v.x; d1 = v.y;
    }
    float2 w = *(const float2*)(ew + e);
    ull add0 = (1ull << 40) | (ull)__float2uint_rn(w.x * 1048576.0f);
    ull add1 = (1ull << 40) | (ull)__float2uint_rn(w.y * 1048576.0f);
    atomicAdd(&g_pack[d0], add0);
    atomicAdd(&g_pack[d1], add1);
}

__global__ void k_scan1() {
    __shared__ int sh[SCAN_BLK];
    int t = threadIdx.x;
    int gid = blockIdx.x * SCAN_BLK + t;
    int v = 0;
    float deg = 1.0f;
    if (gid < NN) {
        ull p = g_pack[gid];
        v = (int)(p >> 40);
        deg = 1.0f + (float)(p & 0xFFFFFFFFFFull) * (1.0f / 1048576.0f);
    }
    sh[t] = v;
    __syncthreads();
    for (int off = 1; off < SCAN_BLK; off <<= 1) {
        int x = (t >= off) ? sh[t - off] : 0;
        __syncthreads();
        sh[t] += x;
        __syncthreads();
    }
    if (gid < NN) {
        g_rowstart[gid] = sh[t] - v;
        g_dinv[gid] = (deg > 0.0f) ? rsqrtf(deg) : 0.0f;
    }
    if (t == SCAN_BLK - 1) g_bsum[blockIdx.x] = sh[t];
}

__global__ void k_scan2() {
    __shared__ int sh[SCAN_BLK];
    int t = threadIdx.x;
    int v = (t < NSCAN_BLKS) ? g_bsum[t] : 0;
    sh[t] = v;
    __syncthreads();
    for (int off = 1; off < SCAN_BLK; off <<= 1) {
        int x = (t >= off) ? sh[t - off] : 0;
        __syncthreads();
        sh[t] += x;
        __syncthreads();
    }
    if (t < NSCAN_BLKS) g_bsum[t] = sh[t] - v;
}

__global__ void k_scan3() {
    int i = blockIdx.x * blockDim.x + threadIdx.x;
    if (i < NN) {
        int rs = g_rowstart[i] + g_bsum[i >> 10];
        g_rowstart[i] = rs;
        g_cursor[i] = rs;
    }
    if (i == 0) g_rowstart[NN] = NE;
}

// ---------------- embed: whole-W smem, barrier-free, 2 nodes/thread, dinv-scaled fp16 out ----------------
#define EB_THREADS 256
#define EB_NODES   256
#define EB_SMEM    (UD * CM * 4)   // 64 KB
__global__ __launch_bounds__(EB_THREADS, 2)
void k_embed(const float* __restrict__ ut, const float* __restrict__ it, int userBlocks) {
    extern __shared__ ulonglong2 sW[];
    bool isUser = (int)blockIdx.x < userBlocks;
    int blockLocal = isUser ? blockIdx.x : blockIdx.x - userBlocks;
    int wid = threadIdx.x >> 5;
    int lane = threadIdx.x & 31;
    int half = wid & 1;
    int pairBase = blockLocal * EB_NODES + (wid >> 1) * 64;
    int n0 = pairBase + lane;
    int n1 = pairBase + 32 + lane;
    int K = isUser ? UD : ID;
    int Ncnt = isUser ? NU : NI;
    const float* W = isUser ? g_WuW1 : g_WiW1;
    const float* cvec = isUser ? g_cu : g_ci;
    const float* inp = isUser ? ut : it;
    bool act0 = n0 < Ncnt, act1 = n1 < Ncnt;
    const float* xrow0 = inp + (size_t)(act0 ? n0 : 0) * K;
    const float* xrow1 = inp + (size_t)(act1 ? n1 : 0) * K;

    {
        const ulonglong2* Wv = (const ulonglong2*)W;
        int nW = K * CM / 4;
        for (int i = threadIdx.x; i < nW; i += EB_THREADS) sW[i] = Wv[i];
    }
    __syncthreads();

    ull a0[16], a1[16];
    #pragma unroll
    for (int i = 0; i < 16; i++) { a0[i] = 0ull; a1[i] = 0ull; }

    #pragma unroll 2
    for (int kb = 0; kb < K; kb += 4) {
        float4 v0 = *(const float4*)(xrow0 + kb);
        float4 v1 = *(const float4*)(xrow1 + kb);
        float x0[4] = {v0.x, v0.y, v0.z, v0.w};
        float x1[4] = {v1.x, v1.y, v1.z, v1.w};
        #pragma unroll
        for (int k = 0; k < 4; k++) {
            ull b0, b1;
            PACK2(b0, x0[k]);
            PACK2(b1, x1[k]);
            #pragma unroll
            for (int c4 = 0; c4 < 8; c4++) {
                ulonglong2 w = sW[(kb + k) * 16 + half * 8 + c4];   // warp-uniform
                FMA2(a0[2 * c4],     b0, w.x, a0[2 * c4]);
                FMA2(a0[2 * c4 + 1], b0, w.y, a0[2 * c4 + 1]);
                FMA2(a1[2 * c4],     b1, w.x, a1[2 * c4]);
                FMA2(a1[2 * c4 + 1], b1, w.y, a1[2 * c4 + 1]);
            }
        }
    }

    int nodeBase = isUser ? 0 : NU;
    const float4* cv4 = (const float4*)(cvec + half * 32);
    if (act0) {
        float dv = g_dinv[nodeBase + n0];
        uint2* orow = (uint2*)(g_h1h + (size_t)(nodeBase + n0) * CM + half * 32);
        #pragma unroll
        for (int c4 = 0; c4 < 8; c4++) {
            float a, b, c, d;
            UNPACK2(a, b, a0[2 * c4]);
            UNPACK2(c, d, a0[2 * c4 + 1]);
            float4 cv = cv4[c4];
            __half2 p0 = __floats2half2_rn(dv * (a + cv.x), dv * (b + cv.y));
            __half2 p1 = __floats2half2_rn(dv * (c + cv.z), dv * (d + cv.w));
            uint2 ov; ov.x = *(unsigned*)&p0; ov.y = *(unsigned*)&p1;
            orow[c4] = ov;
        }
    }
    if (act1) {
        float dv = g_dinv[nodeBase + n1];
        uint2* orow = (uint2*)(g_h1h + (size_t)(nodeBase + n1) * CM + half * 32);
        #pragma unroll
        for (int c4 = 0; c4 < 8; c4++) {
            float a, b, c, d;
            UNPACK2(a, b, a1[2 * c4]);
            UNPACK2(c, d, a1[2 * c4 + 1]);
            float4 cv = cv4[c4];
            __half2 p0 = __floats2half2_rn(dv * (a + cv.x), dv * (b + cv.y));
            __half2 p1 = __floats2half2_rn(dv * (c + cv.z), dv * (d + cv.w));
            uint2 ov; ov.x = *(unsigned*)&p0; ov.y = *(unsigned*)&p1;
            orow[c4] = ov;
        }
    }
}

// ---------------- scatter: CSR (src, ew) -- NO dinv loads ----------------
__global__ void k_scatter(const int* __restrict__ ei32, const float* __restrict__ ew) {
    int e = blockIdx.x * blockDim.x + threadIdx.x;
    if (e >= NE) return;
    int s, d;
    if (g_is64) { s = ei32[2 * e]; d = ei32[2 * (NE + e)]; }
    else        { s = ei32[e];     d = ei32[NE + e]; }
    int pos = atomicAdd(&g_cursor[d], 1);
    g_csr[pos] = (ull)(unsigned)s | ((ull)__float_as_uint(ew[e]) << 32);
}

// ---------------- gather1: acc = h1'[d] + sum ew*h1'[s]; z1' = dv*relu(dv*acc + b1) ----------------
__global__ void k_gather1(const float* __restrict__ b1) {
    int t = threadIdx.x;
    int node = blockIdx.x * (blockDim.x >> 5) + (t >> 5);
    int lane = t & 31;
    if (node >= NN) return;

    const unsigned* h = (const unsigned*)g_h1h;    // half2 per entry; 32 per row
    float dv = g_dinv[node];
    unsigned us = h[(size_t)node * 32 + lane];
    float2 fs = __half22float2(*(const __half2*)&us);
    ull acc; PACKF2(acc, fs.x, fs.y);              // self term = h1'[d]

    int e = g_rowstart[node], end = g_rowstart[node + 1];
    for (; e + 4 <= end; e += 4) {
        ull p0 = g_csr[e], p1 = g_csr[e + 1], p2 = g_csr[e + 2], p3 = g_csr[e + 3];
        unsigned u0 = h[(size_t)(unsigned)p0 * 32 + lane];
        unsigned u1 = h[(size_t)(unsigned)p1 * 32 + lane];
        unsigned u2 = h[(size_t)(unsigned)p2 * 32 + lane];
        unsigned u3 = h[(size_t)(unsigned)p3 * 32 + lane];
        float2 f0 = __half22float2(*(const __half2*)&u0);
        float2 f1 = __half22float2(*(const __half2*)&u1);
        float2 f2 = __half22float2(*(const __half2*)&u2);
        float2 f3 = __half22float2(*(const __half2*)&u3);
        ull v0, v1, v2, v3;
        PACKF2(v0, f0.x, f0.y); PACKF2(v1, f1.x, f1.y);
        PACKF2(v2, f2.x, f2.y); PACKF2(v3, f3.x, f3.y);
        ull q0, q1, q2, q3;
        PACK2(q0, __uint_as_float((unsigned)(p0 >> 32)));
        PACK2(q1, __uint_as_float((unsigned)(p1 >> 32)));
        PACK2(q2, __uint_as_float((unsigned)(p2 >> 32)));
        PACK2(q3, __uint_as_float((unsigned)(p3 >> 32)));
        FMA2(acc, q0, v0, acc);
        FMA2(acc, q1, v1, acc);
        FMA2(acc, q2, v2, acc);
        FMA2(acc, q3, v3, acc);
    }
    for (; e < end; e++) {
        ull p = g_csr[e];
        unsigned u = h[(size_t)(unsigned)p * 32 + lane];
        float2 f = __half22float2(*(const __half2*)&u);
        ull v; PACKF2(v, f.x, f.y);
        ull q; PACK2(q, __uint_as_float((unsigned)(p >> 32)));
        FMA2(acc, q, v, acc);
    }
    float ax, ay; UNPACK2(ax, ay, acc);
    float2 bb = ((const float2*)b1)[lane];
    float2 z;
    z.x = dv * fmaxf(fmaf(dv, ax, bb.x), 0.0f);
    z.y = dv * fmaxf(fmaf(dv, ay, bb.y), 0.0f);
    ((float2*)(g_z1 + (size_t)node * CM))[lane] = z;   // z1' (dinv-scaled)
}

// ---------------- xform: h2' = z1' @ W2 (per-thread node, f32x2, fp16 output) ----------------
#define XF_THREADS 256
__global__ __launch_bounds__(XF_THREADS)
void k_xform(const float* __restrict__ W2) {
    __shared__ ulonglong2 sW2[CM * 8];   // 8 KB
    sW2[threadIdx.x]       = ((const ulonglong2*)W2)[threadIdx.x];
    sW2[threadIdx.x + 256] = ((const ulonglong2*)W2)[threadIdx.x + 256];
    __syncthreads();

    int node = blockIdx.x * XF_THREADS + threadIdx.x;
    if (node >= NN) return;
    const float* xrow = g_z1 + (size_t)node * CM;

    ull acc[16];
    #pragma unroll
    for (int i = 0; i < 16; i++) acc[i] = 0ull;

    #pragma unroll
    for (int kb = 0; kb < CM; kb += 16) {
        float x[16];
        #pragma unroll
        for (int q = 0; q < 4; q++) {
            float4 v = ((const float4*)(xrow + kb))[q];
            x[4 * q] = v.x; x[4 * q + 1] = v.y; x[4 * q + 2] = v.z; x[4 * q + 3] = v.w;
        }
        #pragma unroll
        for (int k = 0; k < 16; k++) {
            ull bk; PACK2(bk, x[k]);
            #pragma unroll
            for (int c4 = 0; c4 < 8; c4++) {
                ulonglong2 w = sW2[(kb + k) * 8 + c4];
                FMA2(acc[2 * c4],     bk, w.x, acc[2 * c4]);
                FMA2(acc[2 * c4 + 1], bk, w.y, acc[2 * c4 + 1]);
            }
        }
    }
    uint2* orow = (uint2*)(g_h2h + (size_t)node * OD);
    #pragma unroll
    for (int c4 = 0; c4 < 8; c4++) {
        float a, b, c, d;
        UNPACK2(a, b, acc[2 * c4]);
        UNPACK2(c, d, acc[2 * c4 + 1]);
        __half2 p0 = __floats2half2_rn(a, b);
        __half2 p1 = __floats2half2_rn(c, d);
        uint2 ov; ov.x = *(unsigned*)&p0; ov.y = *(unsigned*)&p1;
        orow[c4] = ov;
    }
}

// ---------------- gather2: out = dv*(h2'[d] + sum ew*h2'[s]) + b2 ----------------
__global__ void k_gather2(const float* __restrict__ b2, float* __restrict__ out) {
    int t = threadIdx.x;
    int node = blockIdx.x * (blockDim.x >> 5) + (t >> 5);
    int lane = t & 31;
    if (node >= NN) return;
    int half = lane >> 4;
    int c = lane & 15;

    const unsigned* h = (const unsigned*)g_h2h;    // half2 per entry; 16 per row
    float dv = g_dinv[node];
    ull acc = 0ull;
    if (half == 0) {
        unsigned us = h[(size_t)node * 16 + c];
        float2 fs = __half22float2(*(const __half2*)&us);
        PACKF2(acc, fs.x, fs.y);                   // self term = h2'[d]
    }
    int beg = g_rowstart[node], end = g_rowstart[node + 1];
    int e = beg + half;
    for (; e + 2 < end; e += 4) {
        ull p0 = g_csr[e], p1 = g_csr[e + 2];
        unsigned u0 = h[(size_t)(unsigned)p0 * 16 + c];
        unsigned u1 = h[(size_t)(unsigned)p1 * 16 + c];
        float2 f0 = __half22float2(*(const __half2*)&u0);
        float2 f1 = __half22float2(*(const __half2*)&u1);
        ull v0, v1;
        PACKF2(v0, f0.x, f0.y); PACKF2(v1, f1.x, f1.y);
        ull q0, q1;
        PACK2(q0, __uint_as_float((unsigned)(p0 >> 32)));
        PACK2(q1, __uint_as_float((unsigned)(p1 >> 32)));
        FMA2(acc, q0, v0, acc);
        FMA2(acc, q1, v1, acc);
    }
    if (e < end) {
        ull p = g_csr[e];
        unsigned u = h[(size_t)(unsigned)p * 16 + c];
        float2 f = __half22float2(*(const __half2*)&u);
        ull v; PACKF2(v, f.x, f.y);
        ull q; PACK2(q, __uint_as_float((unsigned)(p >> 32)));
        FMA2(acc, q, v, acc);
    }
    float ax, ay; UNPACK2(ax, ay, acc);
    ax += __shfl_xor_sync(0xffffffffu, ax, 16);
    ay += __shfl_xor_sync(0xffffffffu, ay, 16);
    if (half == 0) {
        float2 bb = ((const float2*)b2)[c];
        float2 ov;
        ov.x = fmaf(dv, ax, bb.x);
        ov.y = fmaf(dv, ay, bb.y);
        ((float2*)(out + (size_t)node * OD))[c] = ov;
    }
}

// ---------------- launch ----------------
extern "C" void kernel_launch(void* const* d_in, const int* in_sizes, int n_in,
                              void* d_out, int out_size) {
    const float* ut = (const float*)d_in[0];
    const float* it = (const float*)d_in[1];
    const int*   ei = (const int*)d_in[2];
    const float* ew = (const float*)d_in[3];
    const float* Wu = (const float*)d_in[4];
    const float* bu = (const float*)d_in[5];
    const float* Wi = (const float*)d_in[6];
    const float* bi = (const float*)d_in[7];
    const float* W1 = (const float*)d_in[8];
    const float* b1 = (const float*)d_in[9];
    const float* W2 = (const float*)d_in[10];
    const float* b2 = (const float*)d_in[11];
    float*       out = (float*)d_out;

    cudaFuncSetAttribute(k_embed, cudaFuncAttributeMaxDynamicSharedMemorySize, EB_SMEM);

    int userBlocks = (NU + EB_NODES - 1) / EB_NODES;    // 391
    int itemBlocks = (NI + EB_NODES - 1) / EB_NODES;    // 391

    // embed needs dinv now (dinv-folded features) => scans before embed.
    // Launch #4 (ncu capture slot) = k_edge1.
    k_detect<<<1, 256>>>(ei);                                              // 1
    k_init<<<(NN + 255) / 256, 256>>>();                                   // 2
    k_wcomb<<<(UD * CM + ID * CM + 2 * CM + 127) / 128, 128>>>(Wu, bu, Wi, bi, W1); // 3
    k_edge1<<<(NE / 2 + 255) / 256, 256>>>(ei, ew);                        // 4 <- profiled
    k_scan1<<<NSCAN_BLKS, SCAN_BLK>>>();                                   // 5
    k_scan2<<<1, SCAN_BLK>>>();                                            // 6
    k_scan3<<<(NN + 255) / 256, 256>>>();                                  // 7
    k_embed<<<userBlocks + itemBlocks, EB_THREADS, EB_SMEM>>>(ut, it, userBlocks);  // 8
    k_scatter<<<(NE + 255) / 256, 256>>>(ei, ew);                          // 9
    k_gather1<<<NN / 8, 256>>>(b1);                                        // 10
    k_xform<<<(NN + XF_THREADS - 1) / XF_THREADS, XF_THREADS>>>(W2);       // 11
    k_gather2<<<NN / 8, 256>>>(b2, out);                                   // 12
}

// round 14
// speedup vs baseline: 1.5251x; 1.0992x over previous
#include <cuda_runtime.h>
#include <cuda_bf16.h>
#include <cuda_fp16.h>
#include <stdint.h>

typedef unsigned long long ull;

#define NU 100000
#define NI 100000
#define NN 200000
#define NE 4000000
#define UD 256
#define ID 128
#define CM 64
#define OD 32
#define SCAN_BLK 1024
#define NSCAN_BLKS ((NN + SCAN_BLK - 1) / SCAN_BLK)

// f32x2 packed helpers
#define FMA2(d, a, b, c) asm("fma.rn.f32x2 %0, %1, %2, %3;" : "=l"(d) : "l"(a), "l"(b), "l"(c))
#define PACK2(d, x)      asm("mov.b64 %0, {%1, %1};" : "=l"(d) : "f"(x))
#define PACKF2(d, lo, hi) asm("mov.b64 %0, {%1, %2};" : "=l"(d) : "f"(lo), "f"(hi))
#define UNPACK2(lo, hi, v) asm("mov.b64 {%0, %1}, %2;" : "=f"(lo), "=f"(hi) : "l"(v))

// ---------------- scratch ----------------
__device__ ull   g_pack[NN];              // count<<40 | deg fixed-point (2^-20)
__device__ float g_dinv[NN];
__device__ int   g_rowstart[NN + 1];
__device__ int   g_cursor[NN];
__device__ int   g_bsum[SCAN_BLK];
__device__ ull   g_csr[NE];               // packed: lo32 = src, hi32 = norm bits
__device__ float g_WuW1[UD * CM];         // tf32-rounded
__device__ float g_WiW1[ID * CM];         // tf32-rounded
__device__ float g_cu[CM];
__device__ float g_ci[CM];
__device__ __half g_h1h[(size_t)NN * CM]; // 25.6 MB embed output (fp16)
__device__ float  g_z1[(size_t)NN * CM];  // 51.2 MB relu(agg1+b1) (fp32)
__device__ __half g_h2h[(size_t)NN * OD]; // 12.8 MB z1 @ W2 (fp16)
__device__ int   g_is64;

// ---------------- dtype detection ----------------
__global__ void k_detect(const int* __restrict__ ei32) {
    __shared__ int any_nonzero;
    if (threadIdx.x == 0) any_nonzero = 0;
    __syncthreads();
    for (int i = 2 * threadIdx.x + 1; i < 4096; i += 2 * blockDim.x)
        if (ei32[i] != 0) any_nonzero = 1;
    __syncthreads();
    if (threadIdx.x == 0) g_is64 = any_nonzero ? 0 : 1;
}

__global__ void k_init() {
    int i = blockIdx.x * blockDim.x + threadIdx.x;
    if (i < NN) g_pack[i] = 0ull;
}

// ---------------- weight folding (W outputs rounded to tf32) ----------------
__global__ void k_wcomb(const float* __restrict__ Wu, const float* __restrict__ bu,
                        const float* __restrict__ Wi, const float* __restrict__ bi,
                        const float* __restrict__ W1) {
    int idx = blockIdx.x * blockDim.x + threadIdx.x;
    const int TOT_U = UD * CM, TOT_I = ID * CM;
    if (idx < TOT_U) {
        int k = idx / CM, c = idx % CM;
        float a = 0.f;
        #pragma unroll
        for (int j = 0; j < CM; j++) a += Wu[k * CM + j] * W1[j * CM + c];
        unsigned u; asm("cvt.rna.tf32.f32 %0, %1;" : "=r"(u) : "f"(a));
        g_WuW1[idx] = __uint_as_float(u);
    } else if (idx < TOT_U + TOT_I) {
        int r = idx - TOT_U;
        int k = r / CM, c = r % CM;
        float a = 0.f;
        #pragma unroll
        for (int j = 0; j < CM; j++) a += Wi[k * CM + j] * W1[j * CM + c];
        unsigned u; asm("cvt.rna.tf32.f32 %0, %1;" : "=r"(u) : "f"(a));
        g_WiW1[r] = __uint_as_float(u);
    } else if (idx < TOT_U + TOT_I + 2 * CM) {
        int r = idx - TOT_U - TOT_I;
        if (r < CM) {
            float a = 0.f;
            #pragma unroll
            for (int j = 0; j < CM; j++) a += bu[j] * W1[j * CM + r];
            g_cu[r] = a;
        } else {
            int c = r - CM;
            float a = 0.f;
            #pragma unroll
            for (int j = 0; j < CM; j++) a += bi[j] * W1[j * CM + c];
            g_ci[c] = a;
        }
    }
}

// ---------------- embed: tf32 tensor-core GEMM ----------------
// Block: 256 threads = 8 warps, 128 nodes (16 per warp). Whole W in smem
// (stride 72 floats: B-frag bank = 8*tig+gid, conflict-free). x staged in
// 128x32 chunks (stride 36: A-frag bank = 4*gid+tig, conflict-free).
// Each warp: m16n8k8 tf32 mma over 8 n-tiles. Output fp16 h1 (+ cvec).
#define EB_THREADS 256
#define EB_NODES   128
#define KCH 32
#define SWS 72
#define XS  36
#define EB_SMEM ((UD * SWS + EB_NODES * XS) * 4)   // 92160 B
__global__ __launch_bounds__(EB_THREADS)
void k_embed(const float* __restrict__ ut, const float* __restrict__ it, int userBlocks) {
    extern __shared__ float sm[];
    bool isUser = (int)blockIdx.x < userBlocks;
    int blockLocal = isUser ? blockIdx.x : blockIdx.x - userBlocks;
    int K = isUser ? UD : ID;
    int Ncnt = isUser ? NU : NI;
    const float* W = isUser ? g_WuW1 : g_WiW1;
    const float* cvec = isUser ? g_cu : g_ci;
    const float* inp = isUser ? ut : it;
    int nodeBase0 = blockLocal * EB_NODES;       // block's first local node
    float* sW = sm;                              // [K][SWS]
    float* sX = sm + K * SWS;                    // [128][XS]

    int tid = threadIdx.x;
    // stage W (K x 64 floats, padded rows)
    for (int i = tid; i < K * (CM / 4); i += EB_THREADS) {
        int r = i >> 4, q = i & 15;              // 16 float4 per 64-col row
        float4 v = ((const float4*)(W + r * CM))[q];
        *((float4*)(sW + r * SWS + q * 4)) = v;
    }

    int wid = tid >> 5, lane = tid & 31;
    int gid = lane >> 2, tig = lane & 3;
    int warpNode = wid * 16;

    float acc[32];                               // 8 ntiles x 4
    #pragma unroll
    for (int i = 0; i < 32; i++) acc[i] = 0.f;

    for (int kb = 0; kb < K; kb += KCH) {
        __syncthreads();                         // protect sX reuse (and first-iter sW)
        // stage x chunk: 128 nodes x 32 k
        #pragma unroll
        for (int i = 0; i < 4; i++) {
            int idx = tid + i * EB_THREADS;      // 0..1023
            int nd = idx >> 3, q = idx & 7;
            int gn = nodeBase0 + nd;
            float4 v = make_float4(0.f, 0.f, 0.f, 0.f);
            if (gn < Ncnt) v = *((const float4*)(inp + (size_t)gn * K + kb + q * 4));
            *((float4*)(sX + nd * XS + q * 4)) = v;
        }
        __syncthreads();
        #pragma unroll
        for (int ks = 0; ks < 4; ks++) {
            int klo = ks * 8;
            float a0f = sX[(warpNode + gid) * XS + klo + tig];
            float a1f = sX[(warpNode + gid + 8) * XS + klo + tig];
            float a2f = sX[(warpNode + gid) * XS + klo + tig + 4];
            float a3f = sX[(warpNode + gid + 8) * XS + klo + tig + 4];
            unsigned A0, A1, A2, A3;
            asm("cvt.rna.tf32.f32 %0, %1;" : "=r"(A0) : "f"(a0f));
            asm("cvt.rna.tf32.f32 %0, %1;" : "=r"(A1) : "f"(a1f));
            asm("cvt.rna.tf32.f32 %0, %1;" : "=r"(A2) : "f"(a2f));
            asm("cvt.rna.tf32.f32 %0, %1;" : "=r"(A3) : "f"(a3f));
            const float* wk0 = sW + (size_t)(kb + klo + tig) * SWS;
            const float* wk1 = sW + (size_t)(kb + klo + tig + 4) * SWS;
            #pragma unroll
            for (int nt = 0; nt < 8; nt++) {
                unsigned B0 = __float_as_uint(wk0[nt * 8 + gid]);
                unsigned B1 = __float_as_uint(wk1[nt * 8 + gid]);
                float* c = acc + nt * 4;
                asm volatile(
                    "mma.sync.aligned.m16n8k8.row.col.f32.tf32.tf32.f32 "
                    "{%0,%1,%2,%3}, {%4,%5,%6,%7}, {%8,%9}, {%0,%1,%2,%3};"
                    : "+f"(c[0]), "+f"(c[1]), "+f"(c[2]), "+f"(c[3])
                    : "r"(A0), "r"(A1), "r"(A2), "r"(A3), "r"(B0), "r"(B1));
            }
        }
    }

    // epilogue: D rows = {gid, gid+8}; col = nt*8 + 2*tig (+1)
    int base = isUser ? 0 : NU;
    int n0 = nodeBase0 + warpNode + gid;
    int n1 = n0 + 8;
    if (n0 < Ncnt) {
        __half* orow = g_h1h + (size_t)(base + n0) * CM;
        #pragma unroll
        for (int nt = 0; nt < 8; nt++) {
            int col = nt * 8 + 2 * tig;
            __half2 p = __floats2half2_rn(acc[nt * 4 + 0] + cvec[col],
                                          acc[nt * 4 + 1] + cvec[col + 1]);
            *((__half2*)(orow + col)) = p;
        }
    }
    if (n1 < Ncnt) {
        __half* orow = g_h1h + (size_t)(base + n1) * CM;
        #pragma unroll
        for (int nt = 0; nt < 8; nt++) {
            int col = nt * 8 + 2 * tig;
            __half2 p = __floats2half2_rn(acc[nt * 4 + 2] + cvec[col],
                                          acc[nt * 4 + 3] + cvec[col + 1]);
            *((__half2*)(orow + col)) = p;
        }
    }
}

// ---------------- graph preprocessing ----------------
__global__ void k_edge1(const int* __restrict__ ei32, const float* __restrict__ ew) {
    int t = blockIdx.x * blockDim.x + threadIdx.x;
    int e = 2 * t;
    if (e >= NE) return;
    int d0, d1;
    if (g_is64) {
        int4 v = *(const int4*)(ei32 + 2 * (NE + e));
        d0 = v.x; d1 = v.z;
    } else {
        int2 v = *(const int2*)(ei32 + NE + e);
        d0 = v.x; d1 = v.y;
    }
    float2 w = *(const float2*)(ew + e);
    ull add0 = (1ull << 40) | (ull)__float2uint_rn(w.x * 1048576.0f);
    ull add1 = (1ull << 40) | (ull)__float2uint_rn(w.y * 1048576.0f);
    atomicAdd(&g_pack[d0], add0);
    atomicAdd(&g_pack[d1], add1);
}

__global__ void k_scan1() {
    __shared__ int sh[SCAN_BLK];
    int t = threadIdx.x;
    int gid = blockIdx.x * SCAN_BLK + t;
    int v = 0;
    float deg = 1.0f;
    if (gid < NN) {
        ull p = g_pack[gid];
        v = (int)(p >> 40);
        deg = 1.0f + (float)(p & 0xFFFFFFFFFFull) * (1.0f / 1048576.0f);
    }
    sh[t] = v;
    __syncthreads();
    for (int off = 1; off < SCAN_BLK; off <<= 1) {
        int x = (t >= off) ? sh[t - off] : 0;
        __syncthreads();
        sh[t] += x;
        __syncthreads();
    }
    if (gid < NN) {
        g_rowstart[gid] = sh[t] - v;
        g_dinv[gid] = (deg > 0.0f) ? rsqrtf(deg) : 0.0f;
    }
    if (t == SCAN_BLK - 1) g_bsum[blockIdx.x] = sh[t];
}

__global__ void k_scan2() {
    __shared__ int sh[SCAN_BLK];
    int t = threadIdx.x;
    int v = (t < NSCAN_BLKS) ? g_bsum[t] : 0;
    sh[t] = v;
    __syncthreads();
    for (int off = 1; off < SCAN_BLK; off <<= 1) {
        int x = (t >= off) ? sh[t - off] : 0;
        __syncthreads();
        sh[t] += x;
        __syncthreads();
    }
    if (t < NSCAN_BLKS) g_bsum[t] = sh[t] - v;
}

__global__ void k_scan3() {
    int i = blockIdx.x * blockDim.x + threadIdx.x;
    if (i < NN) {
        int rs = g_rowstart[i] + g_bsum[i >> 10];
        g_rowstart[i] = rs;
        g_cursor[i] = rs;
    }
    if (i == 0) g_rowstart[NN] = NE;
}

// ---------------- scatter: CSR (src, norm) ----------------
__global__ void k_scatter(const int* __restrict__ ei32, const float* __restrict__ ew) {
    int e = blockIdx.x * blockDim.x + threadIdx.x;
    if (e >= NE) return;
    int s, d;
    if (g_is64) { s = ei32[2 * e]; d = ei32[2 * (NE + e)]; }
    else        { s = ei32[e];     d = ei32[NE + e]; }
    float nrm = g_dinv[s] * ew[e] * g_dinv[d];
    int pos = atomicAdd(&g_cursor[d], 1);
    g_csr[pos] = (ull)(unsigned)s | ((ull)__float_as_uint(nrm) << 32);
}

// ---------------- gather1: aggregate fp16 h1 + bias + relu -> z1 (warp/node) ----------------
__global__ void k_gather1(const float* __restrict__ b1) {
    int t = threadIdx.x;
    int node = blockIdx.x * (blockDim.x >> 5) + (t >> 5);
    int lane = t & 31;
    if (node >= NN) return;

    const unsigned* h = (const unsigned*)g_h1h;    // half2 per entry; 32 per row
    float dv = g_dinv[node];
    float sw = dv * dv;
    unsigned us = h[(size_t)node * 32 + lane];
    float2 fs = __half22float2(*(const __half2*)&us);
    ull acc; PACKF2(acc, sw * fs.x, sw * fs.y);

    int e = g_rowstart[node], end = g_rowstart[node + 1];
    for (; e + 4 <= end; e += 4) {
        ull p0 = g_csr[e], p1 = g_csr[e + 1], p2 = g_csr[e + 2], p3 = g_csr[e + 3];
        unsigned u0 = h[(size_t)(unsigned)p0 * 32 + lane];
        unsigned u1 = h[(size_t)(unsigned)p1 * 32 + lane];
        unsigned u2 = h[(size_t)(unsigned)p2 * 32 + lane];
        unsigned u3 = h[(size_t)(unsigned)p3 * 32 + lane];
        float2 f0 = __half22float2(*(const __half2*)&u0);
        float2 f1 = __half22float2(*(const __half2*)&u1);
        float2 f2 = __half22float2(*(const __half2*)&u2);
        float2 f3 = __half22float2(*(const __half2*)&u3);
        ull v0, v1, v2, v3;
        PACKF2(v0, f0.x, f0.y); PACKF2(v1, f1.x, f1.y);
        PACKF2(v2, f2.x, f2.y); PACKF2(v3, f3.x, f3.y);
        ull q0, q1, q2, q3;
        PACK2(q0, __uint_as_float((unsigned)(p0 >> 32)));
        PACK2(q1, __uint_as_float((unsigned)(p1 >> 32)));
        PACK2(q2, __uint_as_float((unsigned)(p2 >> 32)));
        PACK2(q3, __uint_as_float((unsigned)(p3 >> 32)));
        FMA2(acc, q0, v0, acc);
        FMA2(acc, q1, v1, acc);
        FMA2(acc, q2, v2, acc);
        FMA2(acc, q3, v3, acc);
    }
    for (; e < end; e++) {
        ull p = g_csr[e];
        unsigned u = h[(size_t)(unsigned)p * 32 + lane];
        float2 f = __half22float2(*(const __half2*)&u);
        ull v; PACKF2(v, f.x, f.y);
        ull q; PACK2(q, __uint_as_float((unsigned)(p >> 32)));
        FMA2(acc, q, v, acc);
    }
    float ax, ay; UNPACK2(ax, ay, acc);
    float2 bb = ((const float2*)b1)[lane];
    float2 z;
    z.x = fmaxf(ax + bb.x, 0.0f);
    z.y = fmaxf(ay + bb.y, 0.0f);
    ((float2*)(g_z1 + (size_t)node * CM))[lane] = z;
}

// ---------------- xform: h2 = z1 @ W2 (per-thread node, f32x2, fp16 output) ----------------
#define XF_THREADS 256
__global__ __launch_bounds__(XF_THREADS)
void k_xform(const float* __restrict__ W2) {
    __shared__ ulonglong2 sW2[CM * 8];   // 8 KB
    sW2[threadIdx.x]       = ((const ulonglong2*)W2)[threadIdx.x];
    sW2[threadIdx.x + 256] = ((const ulonglong2*)W2)[threadIdx.x + 256];
    __syncthreads();

    int node = blockIdx.x * XF_THREADS + threadIdx.x;
    if (node >= NN) return;
    const float* xrow = g_z1 + (size_t)node * CM;

    ull acc[16];
    #pragma unroll
    for (int i = 0; i < 16; i++) acc[i] = 0ull;

    #pragma unroll
    for (int kb = 0; kb < CM; kb += 16) {
        float x[16];
        #pragma unroll
        for (int q = 0; q < 4; q++) {
            float4 v = ((const float4*)(xrow + kb))[q];
            x[4 * q] = v.x; x[4 * q + 1] = v.y; x[4 * q + 2] = v.z; x[4 * q + 3] = v.w;
        }
        #pragma unroll
        for (int k = 0; k < 16; k++) {
            ull bk; PACK2(bk, x[k]);
            #pragma unroll
            for (int c4 = 0; c4 < 8; c4++) {
                ulonglong2 w = sW2[(kb + k) * 8 + c4];
                FMA2(acc[2 * c4],     bk, w.x, acc[2 * c4]);
                FMA2(acc[2 * c4 + 1], bk, w.y, acc[2 * c4 + 1]);
            }
        }
    }
    uint2* orow = (uint2*)(g_h2h + (size_t)node * OD);
    #pragma unroll
    for (int c4 = 0; c4 < 8; c4++) {
        float a, b, c, d;
        UNPACK2(a, b, acc[2 * c4]);
        UNPACK2(c, d, acc[2 * c4 + 1]);
        __half2 p0 = __floats2half2_rn(a, b);
        __half2 p1 = __floats2half2_rn(c, d);
        uint2 ov; ov.x = *(unsigned*)&p0; ov.y = *(unsigned*)&p1;
        orow[c4] = ov;
    }
}

// ---------------- gather2: aggregate fp16 h2 + b2 -> out (dual half-warp) ----------------
__global__ void k_gather2(const float* __restrict__ b2, float* __restrict__ out) {
    int t = threadIdx.x;
    int node = blockIdx.x * (blockDim.x >> 5) + (t >> 5);
    int lane = t & 31;
    if (node >= NN) return;
    int half = lane >> 4;
    int c = lane & 15;

    const unsigned* h = (const unsigned*)g_h2h;    // half2 per entry; 16 per row
    ull acc = 0ull;
    if (half == 0) {
        float dv = g_dinv[node];
        float sw = dv * dv;
        unsigned us = h[(size_t)node * 16 + c];
        float2 fs = __half22float2(*(const __half2*)&us);
        PACKF2(acc, sw * fs.x, sw * fs.y);
    }
    int beg = g_rowstart[node], end = g_rowstart[node + 1];
    int e = beg + half;
    for (; e + 2 < end; e += 4) {
        ull p0 = g_csr[e], p1 = g_csr[e + 2];
        unsigned u0 = h[(size_t)(unsigned)p0 * 16 + c];
        unsigned u1 = h[(size_t)(unsigned)p1 * 16 + c];
        float2 f0 = __half22float2(*(const __half2*)&u0);
        float2 f1 = __half22float2(*(const __half2*)&u1);
        ull v0, v1;
        PACKF2(v0, f0.x, f0.y); PACKF2(v1, f1.x, f1.y);
        ull q0, q1;
        PACK2(q0, __uint_as_float((unsigned)(p0 >> 32)));
        PACK2(q1, __uint_as_float((unsigned)(p1 >> 32)));
        FMA2(acc, q0, v0, acc);
        FMA2(acc, q1, v1, acc);
    }
    if (e < end) {
        ull p = g_csr[e];
        unsigned u = h[(size_t)(unsigned)p * 16 + c];
        float2 f = __half22float2(*(const __half2*)&u);
        ull v; PACKF2(v, f.x, f.y);
        ull q; PACK2(q, __uint_as_float((unsigned)(p >> 32)));
        FMA2(acc, q, v, acc);
    }
    float ax, ay; UNPACK2(ax, ay, acc);
    ax += __shfl_xor_sync(0xffffffffu, ax, 16);
    ay += __shfl_xor_sync(0xffffffffu, ay, 16);
    if (half == 0) {
        float2 bb = ((const float2*)b2)[c];
        float2 ov; ov.x = ax + bb.x; ov.y = ay + bb.y;
        ((float2*)(out + (size_t)node * OD))[c] = ov;
    }
}

// ---------------- launch ----------------
extern "C" void kernel_launch(void* const* d_in, const int* in_sizes, int n_in,
                              void* d_out, int out_size) {
    const float* ut = (const float*)d_in[0];
    const float* it = (const float*)d_in[1];
    const int*   ei = (const int*)d_in[2];
    const float* ew = (const float*)d_in[3];
    const float* Wu = (const float*)d_in[4];
    const float* bu = (const float*)d_in[5];
    const float* Wi = (const float*)d_in[6];
    const float* bi = (const float*)d_in[7];
    const float* W1 = (const float*)d_in[8];
    const float* b1 = (const float*)d_in[9];
    const float* W2 = (const float*)d_in[10];
    const float* b2 = (const float*)d_in[11];
    float*       out = (float*)d_out;

    cudaFuncSetAttribute(k_embed, cudaFuncAttributeMaxDynamicSharedMemorySize, EB_SMEM);

    int userBlocks = (NU + EB_NODES - 1) / EB_NODES;    // 782
    int itemBlocks = (NI + EB_NODES - 1) / EB_NODES;    // 782

    // embed only needs W (wcomb) -> back at profiled slot #4
    k_detect<<<1, 256>>>(ei);                                              // 1
    k_init<<<(NN + 255) / 256, 256>>>();                                   // 2
    k_wcomb<<<(UD * CM + ID * CM + 2 * CM + 127) / 128, 128>>>(Wu, bu, Wi, bi, W1); // 3
    k_embed<<<userBlocks + itemBlocks, EB_THREADS, EB_SMEM>>>(ut, it, userBlocks);  // 4 <- profiled
    k_edge1<<<(NE / 2 + 255) / 256, 256>>>(ei, ew);                        // 5
    k_scan1<<<NSCAN_BLKS, SCAN_BLK>>>();                                   // 6
    k_scan2<<<1, SCAN_BLK>>>();                                            // 7
    k_scan3<<<(NN + 255) / 256, 256>>>();                                  // 8
    k_scatter<<<(NE + 255) / 256, 256>>>(ei, ew);                          // 9
    k_gather1<<<NN / 8, 256>>>(b1);                                        // 10
    k_xform<<<(NN + XF_THREADS - 1) / XF_THREADS, XF_THREADS>>>(W2);       // 11
    k_gather2<<<NN / 8, 256>>>(b2, out);                                   // 12
}

// round 15
// speedup vs baseline: 1.8226x; 1.1950x over previous
#include <cuda_runtime.h>
#include <cuda_bf16.h>
#include <cuda_fp16.h>
#include <stdint.h>

typedef unsigned long long ull;

#define NU 100000
#define NI 100000
#define NN 200000
#define NE 4000000
#define UD 256
#define ID 128
#define CM 64
#define OD 32
#define SCAN_BLK 1024
#define NSCAN_BLKS ((NN + SCAN_BLK - 1) / SCAN_BLK)

// f32x2 packed helpers
#define FMA2(d, a, b, c) asm("fma.rn.f32x2 %0, %1, %2, %3;" : "=l"(d) : "l"(a), "l"(b), "l"(c))
#define PACK2(d, x)      asm("mov.b64 %0, {%1, %1};" : "=l"(d) : "f"(x))
#define PACKF2(d, lo, hi) asm("mov.b64 %0, {%1, %2};" : "=l"(d) : "f"(lo), "f"(hi))
#define UNPACK2(lo, hi, v) asm("mov.b64 {%0, %1}, %2;" : "=f"(lo), "=f"(hi) : "l"(v))

// ---------------- scratch ----------------
__device__ ull   g_pack[NN];              // count<<40 | deg fixed-point (2^-20)
__device__ float g_dinv[NN];
__device__ int   g_rowstart[NN + 1];
__device__ int   g_cursor[NN];
__device__ int   g_bsum[SCAN_BLK];
__device__ ull   g_csr[NE];               // packed: lo32 = src, hi32 = norm bits
__device__ float g_WuW1[UD * CM];         // tf32-rounded
__device__ float g_WiW1[ID * CM];         // tf32-rounded
__device__ float g_cu[CM];
__device__ float g_ci[CM];
__device__ __half g_h1h[(size_t)NN * CM]; // 25.6 MB embed output (fp16)
__device__ __half g_z1h[(size_t)NN * CM]; // 25.6 MB relu(agg1+b1) (fp16)
__device__ __half g_h2h[(size_t)NN * OD]; // 12.8 MB z1 @ W2 (fp16)
__device__ int   g_is64;

// ---------------- dtype detection ----------------
__global__ void k_detect(const int* __restrict__ ei32) {
    __shared__ int any_nonzero;
    if (threadIdx.x == 0) any_nonzero = 0;
    __syncthreads();
    for (int i = 2 * threadIdx.x + 1; i < 4096; i += 2 * blockDim.x)
        if (ei32[i] != 0) any_nonzero = 1;
    __syncthreads();
    if (threadIdx.x == 0) g_is64 = any_nonzero ? 0 : 1;
}

__global__ void k_init() {
    int i = blockIdx.x * blockDim.x + threadIdx.x;
    if (i < NN) g_pack[i] = 0ull;
}

// ---------------- weight folding (W outputs rounded to tf32) ----------------
__global__ void k_wcomb(const float* __restrict__ Wu, const float* __restrict__ bu,
                        const float* __restrict__ Wi, const float* __restrict__ bi,
                        const float* __restrict__ W1) {
    int idx = blockIdx.x * blockDim.x + threadIdx.x;
    const int TOT_U = UD * CM, TOT_I = ID * CM;
    if (idx < TOT_U) {
        int k = idx / CM, c = idx % CM;
        float a = 0.f;
        #pragma unroll
        for (int j = 0; j < CM; j++) a += Wu[k * CM + j] * W1[j * CM + c];
        unsigned u; asm("cvt.rna.tf32.f32 %0, %1;" : "=r"(u) : "f"(a));
        g_WuW1[idx] = __uint_as_float(u);
    } else if (idx < TOT_U + TOT_I) {
        int r = idx - TOT_U;
        int k = r / CM, c = r % CM;
        float a = 0.f;
        #pragma unroll
        for (int j = 0; j < CM; j++) a += Wi[k * CM + j] * W1[j * CM + c];
        unsigned u; asm("cvt.rna.tf32.f32 %0, %1;" : "=r"(u) : "f"(a));
        g_WiW1[r] = __uint_as_float(u);
    } else if (idx < TOT_U + TOT_I + 2 * CM) {
        int r = idx - TOT_U - TOT_I;
        if (r < CM) {
            float a = 0.f;
            #pragma unroll
            for (int j = 0; j < CM; j++) a += bu[j] * W1[j * CM + r];
            g_cu[r] = a;
        } else {
            int c = r - CM;
            float a = 0.f;
            #pragma unroll
            for (int j = 0; j < CM; j++) a += bi[j] * W1[j * CM + c];
            g_ci[c] = a;
        }
    }
}

// ---------------- embed: tf32 MMA + cp.async double-buffered X staging ----------------
#define EB_THREADS 256
#define EB_NODES   128
#define KCH 32
#define SWS 72
#define XS  36
#define XBUF (EB_NODES * XS)                       // floats per X buffer (4608)
#define EB_SMEM ((UD * SWS + 2 * XBUF) * 4)        // 110592 B
__device__ __forceinline__ void cpasync16(uint32_t dst, const void* src) {
    asm volatile("cp.async.cg.shared.global [%0], [%1], 16;" :: "r"(dst), "l"(src));
}
__global__ __launch_bounds__(EB_THREADS)
void k_embed(const float* __restrict__ ut, const float* __restrict__ it, int userBlocks) {
    extern __shared__ float sm[];
    bool isUser = (int)blockIdx.x < userBlocks;
    int blockLocal = isUser ? blockIdx.x : blockIdx.x - userBlocks;
    int K = isUser ? UD : ID;
    int Ncnt = isUser ? NU : NI;
    const float* W = isUser ? g_WuW1 : g_WiW1;
    const float* cvec = isUser ? g_cu : g_ci;
    const float* inp = isUser ? ut : it;
    int nodeBase0 = blockLocal * EB_NODES;
    float* sW = sm;                                // [K][SWS]
    float* sX = sm + K * SWS;                      // 2 buffers of [128][XS]
    uint32_t sXaddr = (uint32_t)__cvta_generic_to_shared(sX);

    int tid = threadIdx.x;
    // stage W (K x 64 floats, padded rows)
    for (int i = tid; i < K * (CM / 4); i += EB_THREADS) {
        int r = i >> 4, q = i & 15;
        float4 v = ((const float4*)(W + r * CM))[q];
        *((float4*)(sW + r * SWS + q * 4)) = v;
    }

    int wid = tid >> 5, lane = tid & 31;
    int gid = lane >> 2, tig = lane & 3;
    int warpNode = wid * 16;

    // prefetch chunk 0 into buffer 0
    {
        #pragma unroll
        for (int i = 0; i < 4; i++) {
            int idx = tid + i * EB_THREADS;
            int nd = idx >> 3, q = idx & 7;
            int gn = nodeBase0 + nd; if (gn >= Ncnt) gn = Ncnt - 1;
            cpasync16(sXaddr + (nd * XS + q * 4) * 4,
                      inp + (size_t)gn * K + q * 4);
        }
        asm volatile("cp.async.commit_group;");
    }

    float acc[32];
    #pragma unroll
    for (int i = 0; i < 32; i++) acc[i] = 0.f;

    int nCh = K / KCH;
    for (int ci = 0; ci < nCh; ci++) {
        int kb = ci * KCH;
        __syncthreads();   // all warps done with the buffer we're about to overwrite
        if (ci + 1 < nCh) {
            uint32_t dstBase = sXaddr + ((ci + 1) & 1) * XBUF * 4;
            #pragma unroll
            for (int i = 0; i < 4; i++) {
                int idx = tid + i * EB_THREADS;
                int nd = idx >> 3, q = idx & 7;
                int gn = nodeBase0 + nd; if (gn >= Ncnt) gn = Ncnt - 1;
                cpasync16(dstBase + (nd * XS + q * 4) * 4,
                          inp + (size_t)gn * K + kb + KCH + q * 4);
            }
            asm volatile("cp.async.commit_group;");
            asm volatile("cp.async.wait_group 1;");
        } else {
            asm volatile("cp.async.wait_group 0;");
        }
        __syncthreads();   // staged data (and W on first iter) visible

        const float* sXc = sX + (ci & 1) * XBUF;
        #pragma unroll
        for (int ks = 0; ks < 4; ks++) {
            int klo = ks * 8;
            float a0f = sXc[(warpNode + gid) * XS + klo + tig];
            float a1f = sXc[(warpNode + gid + 8) * XS + klo + tig];
            float a2f = sXc[(warpNode + gid) * XS + klo + tig + 4];
            float a3f = sXc[(warpNode + gid + 8) * XS + klo + tig + 4];
            unsigned A0, A1, A2, A3;
            asm("cvt.rna.tf32.f32 %0, %1;" : "=r"(A0) : "f"(a0f));
            asm("cvt.rna.tf32.f32 %0, %1;" : "=r"(A1) : "f"(a1f));
            asm("cvt.rna.tf32.f32 %0, %1;" : "=r"(A2) : "f"(a2f));
            asm("cvt.rna.tf32.f32 %0, %1;" : "=r"(A3) : "f"(a3f));
            const float* wk0 = sW + (size_t)(kb + klo + tig) * SWS;
            const float* wk1 = sW + (size_t)(kb + klo + tig + 4) * SWS;
            #pragma unroll
            for (int nt = 0; nt < 8; nt++) {
                unsigned B0 = __float_as_uint(wk0[nt * 8 + gid]);
                unsigned B1 = __float_as_uint(wk1[nt * 8 + gid]);
                float* c = acc + nt * 4;
                asm volatile(
                    "mma.sync.aligned.m16n8k8.row.col.f32.tf32.tf32.f32 "
                    "{%0,%1,%2,%3}, {%4,%5,%6,%7}, {%8,%9}, {%0,%1,%2,%3};"
                    : "+f"(c[0]), "+f"(c[1]), "+f"(c[2]), "+f"(c[3])
                    : "r"(A0), "r"(A1), "r"(A2), "r"(A3), "r"(B0), "r"(B1));
            }
        }
    }

    int base = isUser ? 0 : NU;
    int n0 = nodeBase0 + warpNode + gid;
    int n1 = n0 + 8;
    if (n0 < Ncnt) {
        __half* orow = g_h1h + (size_t)(base + n0) * CM;
        #pragma unroll
        for (int nt = 0; nt < 8; nt++) {
            int col = nt * 8 + 2 * tig;
            __half2 p = __floats2half2_rn(acc[nt * 4 + 0] + cvec[col],
                                          acc[nt * 4 + 1] + cvec[col + 1]);
            *((__half2*)(orow + col)) = p;
        }
    }
    if (n1 < Ncnt) {
        __half* orow = g_h1h + (size_t)(base + n1) * CM;
        #pragma unroll
        for (int nt = 0; nt < 8; nt++) {
            int col = nt * 8 + 2 * tig;
            __half2 p = __floats2half2_rn(acc[nt * 4 + 2] + cvec[col],
                                          acc[nt * 4 + 3] + cvec[col + 1]);
            *((__half2*)(orow + col)) = p;
        }
    }
}

// ---------------- graph preprocessing ----------------
__global__ void k_edge1(const int* __restrict__ ei32, const float* __restrict__ ew) {
    int t = blockIdx.x * blockDim.x + threadIdx.x;
    int e = 2 * t;
    if (e >= NE) return;
    int d0, d1;
    if (g_is64) {
        int4 v = *(const int4*)(ei32 + 2 * (NE + e));
        d0 = v.x; d1 = v.z;
    } else {
        int2 v = *(const int2*)(ei32 + NE + e);
        d0 = v.x; d1 = v.y;
    }
    float2 w = *(const float2*)(ew + e);
    ull add0 = (1ull << 40) | (ull)__float2uint_rn(w.x * 1048576.0f);
    ull add1 = (1ull << 40) | (ull)__float2uint_rn(w.y * 1048576.0f);
    atomicAdd(&g_pack[d0], add0);
    atomicAdd(&g_pack[d1], add1);
}

__global__ void k_scan1() {
    __shared__ int sh[SCAN_BLK];
    int t = threadIdx.x;
    int gid = blockIdx.x * SCAN_BLK + t;
    int v = 0;
    float deg = 1.0f;
    if (gid < NN) {
        ull p = g_pack[gid];
        v = (int)(p >> 40);
        deg = 1.0f + (float)(p & 0xFFFFFFFFFFull) * (1.0f / 1048576.0f);
    }
    sh[t] = v;
    __syncthreads();
    for (int off = 1; off < SCAN_BLK; off <<= 1) {
        int x = (t >= off) ? sh[t - off] : 0;
        __syncthreads();
        sh[t] += x;
        __syncthreads();
    }
    if (gid < NN) {
        g_rowstart[gid] = sh[t] - v;
        g_dinv[gid] = (deg > 0.0f) ? rsqrtf(deg) : 0.0f;
    }
    if (t == SCAN_BLK - 1) g_bsum[blockIdx.x] = sh[t];
}

__global__ void k_scan2() {
    __shared__ int sh[SCAN_BLK];
    int t = threadIdx.x;
    int v = (t < NSCAN_BLKS) ? g_bsum[t] : 0;
    sh[t] = v;
    __syncthreads();
    for (int off = 1; off < SCAN_BLK; off <<= 1) {
        int x = (t >= off) ? sh[t - off] : 0;
        __syncthreads();
        sh[t] += x;
        __syncthreads();
    }
    if (t < NSCAN_BLKS) g_bsum[t] = sh[t] - v;
}

__global__ void k_scan3() {
    int i = blockIdx.x * blockDim.x + threadIdx.x;
    if (i < NN) {
        int rs = g_rowstart[i] + g_bsum[i >> 10];
        g_rowstart[i] = rs;
        g_cursor[i] = rs;
    }
    if (i == 0) g_rowstart[NN] = NE;
}

// ---------------- scatter: CSR (src, norm) ----------------
__global__ void k_scatter(const int* __restrict__ ei32, const float* __restrict__ ew) {
    int e = blockIdx.x * blockDim.x + threadIdx.x;
    if (e >= NE) return;
    int s, d;
    if (g_is64) { s = ei32[2 * e]; d = ei32[2 * (NE + e)]; }
    else        { s = ei32[e];     d = ei32[NE + e]; }
    float nrm = g_dinv[s] * ew[e] * g_dinv[d];
    int pos = atomicAdd(&g_cursor[d], 1);
    g_csr[pos] = (ull)(unsigned)s | ((ull)__float_as_uint(nrm) << 32);
}

// ---------------- gather1: aggregate fp16 h1 + bias + relu -> z1 fp16 (warp/node) ----------------
__global__ void k_gather1(const float* __restrict__ b1) {
    int t = threadIdx.x;
    int node = blockIdx.x * (blockDim.x >> 5) + (t >> 5);
    int lane = t & 31;
    if (node >= NN) return;

    const unsigned* h = (const unsigned*)g_h1h;    // half2 per entry; 32 per row
    float dv = g_dinv[node];
    float sw = dv * dv;
    unsigned us = h[(size_t)node * 32 + lane];
    float2 fs = __half22float2(*(const __half2*)&us);
    ull acc; PACKF2(acc, sw * fs.x, sw * fs.y);

    int e = g_rowstart[node], end = g_rowstart[node + 1];
    for (; e + 4 <= end; e += 4) {
        ull p0 = g_csr[e], p1 = g_csr[e + 1], p2 = g_csr[e + 2], p3 = g_csr[e + 3];
        unsigned u0 = h[(size_t)(unsigned)p0 * 32 + lane];
        unsigned u1 = h[(size_t)(unsigned)p1 * 32 + lane];
        unsigned u2 = h[(size_t)(unsigned)p2 * 32 + lane];
        unsigned u3 = h[(size_t)(unsigned)p3 * 32 + lane];
        float2 f0 = __half22float2(*(const __half2*)&u0);
        float2 f1 = __half22float2(*(const __half2*)&u1);
        float2 f2 = __half22float2(*(const __half2*)&u2);
        float2 f3 = __half22float2(*(const __half2*)&u3);
        ull v0, v1, v2, v3;
        PACKF2(v0, f0.x, f0.y); PACKF2(v1, f1.x, f1.y);
        PACKF2(v2, f2.x, f2.y); PACKF2(v3, f3.x, f3.y);
        ull q0, q1, q2, q3;
        PACK2(q0, __uint_as_float((unsigned)(p0 >> 32)));
        PACK2(q1, __uint_as_float((unsigned)(p1 >> 32)));
        PACK2(q2, __uint_as_float((unsigned)(p2 >> 32)));
        PACK2(q3, __uint_as_float((unsigned)(p3 >> 32)));
        FMA2(acc, q0, v0, acc);
        FMA2(acc, q1, v1, acc);
        FMA2(acc, q2, v2, acc);
        FMA2(acc, q3, v3, acc);
    }
    for (; e < end; e++) {
        ull p = g_csr[e];
        unsigned u = h[(size_t)(unsigned)p * 32 + lane];
        float2 f = __half22float2(*(const __half2*)&u);
        ull v; PACKF2(v, f.x, f.y);
        ull q; PACK2(q, __uint_as_float((unsigned)(p >> 32)));
        FMA2(acc, q, v, acc);
    }
    float ax, ay; UNPACK2(ax, ay, acc);
    float2 bb = ((const float2*)b1)[lane];
    __half2 hz = __floats2half2_rn(fmaxf(ax + bb.x, 0.0f), fmaxf(ay + bb.y, 0.0f));
    ((__half2*)(g_z1h + (size_t)node * CM))[lane] = hz;
}

// ---------------- xform: h2 = z1(fp16) @ W2 (per-thread node, f32x2, fp16 output) ----------------
#define XF_THREADS 256
__global__ __launch_bounds__(XF_THREADS)
void k_xform(const float* __restrict__ W2) {
    __shared__ ulonglong2 sW2[CM * 8];   // 8 KB
    sW2[threadIdx.x]       = ((const ulonglong2*)W2)[threadIdx.x];
    sW2[threadIdx.x + 256] = ((const ulonglong2*)W2)[threadIdx.x + 256];
    __syncthreads();

    int node = blockIdx.x * XF_THREADS + threadIdx.x;
    if (node >= NN) return;
    const uint4* xr = (const uint4*)(g_z1h + (size_t)node * CM);   // 8 uint4 = 64 halves

    ull acc[16];
    #pragma unroll
    for (int i = 0; i < 16; i++) acc[i] = 0ull;

    #pragma unroll
    for (int kb = 0; kb < CM; kb += 16) {
        uint4 ra = xr[kb >> 3];
        uint4 rb = xr[(kb >> 3) + 1];
        unsigned uu[8] = {ra.x, ra.y, ra.z, ra.w, rb.x, rb.y, rb.z, rb.w};
        float x[16];
        #pragma unroll
        for (int j = 0; j < 8; j++) {
            float2 f = __half22float2(*(const __half2*)&uu[j]);
            x[2 * j] = f.x; x[2 * j + 1] = f.y;
        }
        #pragma unroll
        for (int k = 0; k < 16; k++) {
            ull bk; PACK2(bk, x[k]);
            #pragma unroll
            for (int c4 = 0; c4 < 8; c4++) {
                ulonglong2 w = sW2[(kb + k) * 8 + c4];
                FMA2(acc[2 * c4],     bk, w.x, acc[2 * c4]);
                FMA2(acc[2 * c4 + 1], bk, w.y, acc[2 * c4 + 1]);
            }
        }
    }
    uint2* orow = (uint2*)(g_h2h + (size_t)node * OD);
    #pragma unroll
    for (int c4 = 0; c4 < 8; c4++) {
        float a, b, c, d;
        UNPACK2(a, b, acc[2 * c4]);
        UNPACK2(c, d, acc[2 * c4 + 1]);
        __half2 p0 = __floats2half2_rn(a, b);
        __half2 p1 = __floats2half2_rn(c, d);
        uint2 ov; ov.x = *(unsigned*)&p0; ov.y = *(unsigned*)&p1;
        orow[c4] = ov;
    }
}

// ---------------- gather2: aggregate fp16 h2 + b2 -> out (dual half-warp) ----------------
__global__ void k_gather2(const float* __restrict__ b2, float* __restrict__ out) {
    int t = threadIdx.x;
    int node = blockIdx.x * (blockDim.x >> 5) + (t >> 5);
    int lane = t & 31;
    if (node >= NN) return;
    int half = lane >> 4;
    int c = lane & 15;

    const unsigned* h = (const unsigned*)g_h2h;    // half2 per entry; 16 per row
    ull acc = 0ull;
    if (half == 0) {
        float dv = g_dinv[node];
        float sw = dv * dv;
        unsigned us = h[(size_t)node * 16 + c];
        float2 fs = __half22float2(*(const __half2*)&us);
        PACKF2(acc, sw * fs.x, sw * fs.y);
    }
    int beg = g_rowstart[node], end = g_rowstart[node + 1];
    int e = beg + half;
    for (; e + 2 < end; e += 4) {
        ull p0 = g_csr[e], p1 = g_csr[e + 2];
        unsigned u0 = h[(size_t)(unsigned)p0 * 16 + c];
        unsigned u1 = h[(size_t)(unsigned)p1 * 16 + c];
        float2 f0 = __half22float2(*(const __half2*)&u0);
        float2 f1 = __half22float2(*(const __half2*)&u1);
        ull v0, v1;
        PACKF2(v0, f0.x, f0.y); PACKF2(v1, f1.x, f1.y);
        ull q0, q1;
        PACK2(q0, __uint_as_float((unsigned)(p0 >> 32)));
        PACK2(q1, __uint_as_float((unsigned)(p1 >> 32)));
        FMA2(acc, q0, v0, acc);
        FMA2(acc, q1, v1, acc);
    }
    if (e < end) {
        ull p = g_csr[e];
        unsigned u = h[(size_t)(unsigned)p * 16 + c];
        float2 f = __half22float2(*(const __half2*)&u);
        ull v; PACKF2(v, f.x, f.y);
        ull q; PACK2(q, __uint_as_float((unsigned)(p >> 32)));
        FMA2(acc, q, v, acc);
    }
    float ax, ay; UNPACK2(ax, ay, acc);
    ax += __shfl_xor_sync(0xffffffffu, ax, 16);
    ay += __shfl_xor_sync(0xffffffffu, ay, 16);
    if (half == 0) {
        float2 bb = ((const float2*)b2)[c];
        float2 ov; ov.x = ax + bb.x; ov.y = ay + bb.y;
        ((float2*)(out + (size_t)node * OD))[c] = ov;
    }
}

// ---------------- launch ----------------
extern "C" void kernel_launch(void* const* d_in, const int* in_sizes, int n_in,
                              void* d_out, int out_size) {
    const float* ut = (const float*)d_in[0];
    const float* it = (const float*)d_in[1];
    const int*   ei = (const int*)d_in[2];
    const float* ew = (const float*)d_in[3];
    const float* Wu = (const float*)d_in[4];
    const float* bu = (const float*)d_in[5];
    const float* Wi = (const float*)d_in[6];
    const float* bi = (const float*)d_in[7];
    const float* W1 = (const float*)d_in[8];
    const float* b1 = (const float*)d_in[9];
    const float* W2 = (const float*)d_in[10];
    const float* b2 = (const float*)d_in[11];
    float*       out = (float*)d_out;

    cudaFuncSetAttribute(k_embed, cudaFuncAttributeMaxDynamicSharedMemorySize, EB_SMEM);

    int userBlocks = (NU + EB_NODES - 1) / EB_NODES;    // 782
    int itemBlocks = (NI + EB_NODES - 1) / EB_NODES;    // 782

    k_detect<<<1, 256>>>(ei);                                              // 1
    k_init<<<(NN + 255) / 256, 256>>>();                                   // 2
    k_wcomb<<<(UD * CM + ID * CM + 2 * CM + 127) / 128, 128>>>(Wu, bu, Wi, bi, W1); // 3
    k_embed<<<userBlocks + itemBlocks, EB_THREADS, EB_SMEM>>>(ut, it, userBlocks);  // 4 <- profiled
    k_edge1<<<(NE / 2 + 255) / 256, 256>>>(ei, ew);                        // 5
    k_scan1<<<NSCAN_BLKS, SCAN_BLK>>>();                                   // 6
    k_scan2<<<1, SCAN_BLK>>>();                                            // 7
    k_scan3<<<(NN + 255) / 256, 256>>>();                                  // 8
    k_scatter<<<(NE + 255) / 256, 256>>>(ei, ew);                          // 9
    k_gather1<<<NN / 8, 256>>>(b1);                                        // 10
    k_xform<<<(NN + XF_THREADS - 1) / XF_THREADS, XF_THREADS>>>(W2);       // 11
    k_gather2<<<NN / 8, 256>>>(b2, out);                                   // 12
}

// round 16
// speedup vs baseline: 1.8754x; 1.0290x over previous
#include <cuda_runtime.h>
#include <cuda_bf16.h>
#include <cuda_fp16.h>
#include <stdint.h>

typedef unsigned long long ull;

#define NU 100000
#define NI 100000
#define NN 200000
#define NE 4000000
#define UD 256
#define ID 128
#define CM 64
#define OD 32
#define SCAN_BLK 1024
#define NSCAN_BLKS ((NN + SCAN_BLK - 1) / SCAN_BLK)

// f32x2 packed helpers
#define FMA2(d, a, b, c) asm("fma.rn.f32x2 %0, %1, %2, %3;" : "=l"(d) : "l"(a), "l"(b), "l"(c))
#define PACK2(d, x)      asm("mov.b64 %0, {%1, %1};" : "=l"(d) : "f"(x))
#define PACKF2(d, lo, hi) asm("mov.b64 %0, {%1, %2};" : "=l"(d) : "f"(lo), "f"(hi))
#define UNPACK2(lo, hi, v) asm("mov.b64 {%0, %1}, %2;" : "=f"(lo), "=f"(hi) : "l"(v))

// ---------------- scratch ----------------
__device__ ull   g_pack[NN];              // count<<40 | deg fixed-point (2^-20)
__device__ float g_dinv[NN];
__device__ int   g_rowstart[NN + 1];
__device__ int   g_cursor[NN];
__device__ int   g_bsum[SCAN_BLK];
__device__ ull   g_csr[NE];               // packed: lo32 = src, hi32 = norm bits
__device__ float g_WuW1[UD * CM];         // tf32-rounded
__device__ float g_WiW1[ID * CM];         // tf32-rounded
__device__ float g_cu[CM];
__device__ float g_ci[CM];
__device__ __half g_h1h[(size_t)NN * CM]; // 25.6 MB embed output (fp16)
__device__ __half g_z1h[(size_t)NN * CM]; // 25.6 MB relu(agg1+b1) (fp16)
__device__ __half g_h2h[(size_t)NN * OD]; // 12.8 MB z1 @ W2 (fp16)
__device__ int   g_is64;

// ---------------- dtype detection ----------------
__global__ void k_detect(const int* __restrict__ ei32) {
    __shared__ int any_nonzero;
    if (threadIdx.x == 0) any_nonzero = 0;
    __syncthreads();
    for (int i = 2 * threadIdx.x + 1; i < 4096; i += 2 * blockDim.x)
        if (ei32[i] != 0) any_nonzero = 1;
    __syncthreads();
    if (threadIdx.x == 0) g_is64 = any_nonzero ? 0 : 1;
}

__global__ void k_init() {
    int i = blockIdx.x * blockDim.x + threadIdx.x;
    if (i < NN) g_pack[i] = 0ull;
}

// ---------------- weight folding (W outputs rounded to tf32) ----------------
__global__ void k_wcomb(const float* __restrict__ Wu, const float* __restrict__ bu,
                        const float* __restrict__ Wi, const float* __restrict__ bi,
                        const float* __restrict__ W1) {
    int idx = blockIdx.x * blockDim.x + threadIdx.x;
    const int TOT_U = UD * CM, TOT_I = ID * CM;
    if (idx < TOT_U) {
        int k = idx / CM, c = idx % CM;
        float a = 0.f;
        #pragma unroll
        for (int j = 0; j < CM; j++) a += Wu[k * CM + j] * W1[j * CM + c];
        unsigned u; asm("cvt.rna.tf32.f32 %0, %1;" : "=r"(u) : "f"(a));
        g_WuW1[idx] = __uint_as_float(u);
    } else if (idx < TOT_U + TOT_I) {
        int r = idx - TOT_U;
        int k = r / CM, c = r % CM;
        float a = 0.f;
        #pragma unroll
        for (int j = 0; j < CM; j++) a += Wi[k * CM + j] * W1[j * CM + c];
        unsigned u; asm("cvt.rna.tf32.f32 %0, %1;" : "=r"(u) : "f"(a));
        g_WiW1[r] = __uint_as_float(u);
    } else if (idx < TOT_U + TOT_I + 2 * CM) {
        int r = idx - TOT_U - TOT_I;
        if (r < CM) {
            float a = 0.f;
            #pragma unroll
            for (int j = 0; j < CM; j++) a += bu[j] * W1[j * CM + r];
            g_cu[r] = a;
        } else {
            int c = r - CM;
            float a = 0.f;
            #pragma unroll
            for (int j = 0; j < CM; j++) a += bi[j] * W1[j * CM + c];
            g_ci[c] = a;
        }
    }
}

// ---------------- embed: tf32 MMA + cp.async double-buffered X staging ----------------
#define EB_THREADS 256
#define EB_NODES   128
#define KCH 32
#define SWS 72
#define XS  36
#define XBUF (EB_NODES * XS)                       // floats per X buffer (4608)
#define EB_SMEM ((UD * SWS + 2 * XBUF) * 4)        // 110592 B
__device__ __forceinline__ void cpasync16(uint32_t dst, const void* src) {
    asm volatile("cp.async.cg.shared.global [%0], [%1], 16;" :: "r"(dst), "l"(src));
}
__global__ __launch_bounds__(EB_THREADS)
void k_embed(const float* __restrict__ ut, const float* __restrict__ it, int userBlocks) {
    extern __shared__ float sm[];
    bool isUser = (int)blockIdx.x < userBlocks;
    int blockLocal = isUser ? blockIdx.x : blockIdx.x - userBlocks;
    int K = isUser ? UD : ID;
    int Ncnt = isUser ? NU : NI;
    const float* W = isUser ? g_WuW1 : g_WiW1;
    const float* cvec = isUser ? g_cu : g_ci;
    const float* inp = isUser ? ut : it;
    int nodeBase0 = blockLocal * EB_NODES;
    float* sW = sm;                                // [K][SWS]
    float* sX = sm + K * SWS;                      // 2 buffers of [128][XS]
    uint32_t sXaddr = (uint32_t)__cvta_generic_to_shared(sX);

    int tid = threadIdx.x;
    for (int i = tid; i < K * (CM / 4); i += EB_THREADS) {
        int r = i >> 4, q = i & 15;
        float4 v = ((const float4*)(W + r * CM))[q];
        *((float4*)(sW + r * SWS + q * 4)) = v;
    }

    int wid = tid >> 5, lane = tid & 31;
    int gid = lane >> 2, tig = lane & 3;
    int warpNode = wid * 16;

    {
        #pragma unroll
        for (int i = 0; i < 4; i++) {
            int idx = tid + i * EB_THREADS;
            int nd = idx >> 3, q = idx & 7;
            int gn = nodeBase0 + nd; if (gn >= Ncnt) gn = Ncnt - 1;
            cpasync16(sXaddr + (nd * XS + q * 4) * 4,
                      inp + (size_t)gn * K + q * 4);
        }
        asm volatile("cp.async.commit_group;");
    }

    float acc[32];
    #pragma unroll
    for (int i = 0; i < 32; i++) acc[i] = 0.f;

    int nCh = K / KCH;
    for (int ci = 0; ci < nCh; ci++) {
        int kb = ci * KCH;
        __syncthreads();
        if (ci + 1 < nCh) {
            uint32_t dstBase = sXaddr + ((ci + 1) & 1) * XBUF * 4;
            #pragma unroll
            for (int i = 0; i < 4; i++) {
                int idx = tid + i * EB_THREADS;
                int nd = idx >> 3, q = idx & 7;
                int gn = nodeBase0 + nd; if (gn >= Ncnt) gn = Ncnt - 1;
                cpasync16(dstBase + (nd * XS + q * 4) * 4,
                          inp + (size_t)gn * K + kb + KCH + q * 4);
            }
            asm volatile("cp.async.commit_group;");
            asm volatile("cp.async.wait_group 1;");
        } else {
            asm volatile("cp.async.wait_group 0;");
        }
        __syncthreads();

        const float* sXc = sX + (ci & 1) * XBUF;
        #pragma unroll
        for (int ks = 0; ks < 4; ks++) {
            int klo = ks * 8;
            float a0f = sXc[(warpNode + gid) * XS + klo + tig];
            float a1f = sXc[(warpNode + gid + 8) * XS + klo + tig];
            float a2f = sXc[(warpNode + gid) * XS + klo + tig + 4];
            float a3f = sXc[(warpNode + gid + 8) * XS + klo + tig + 4];
            unsigned A0, A1, A2, A3;
            asm("cvt.rna.tf32.f32 %0, %1;" : "=r"(A0) : "f"(a0f));
            asm("cvt.rna.tf32.f32 %0, %1;" : "=r"(A1) : "f"(a1f));
            asm("cvt.rna.tf32.f32 %0, %1;" : "=r"(A2) : "f"(a2f));
            asm("cvt.rna.tf32.f32 %0, %1;" : "=r"(A3) : "f"(a3f));
            const float* wk0 = sW + (size_t)(kb + klo + tig) * SWS;
            const float* wk1 = sW + (size_t)(kb + klo + tig + 4) * SWS;
            #pragma unroll
            for (int nt = 0; nt < 8; nt++) {
                unsigned B0 = __float_as_uint(wk0[nt * 8 + gid]);
                unsigned B1 = __float_as_uint(wk1[nt * 8 + gid]);
                float* c = acc + nt * 4;
                asm volatile(
                    "mma.sync.aligned.m16n8k8.row.col.f32.tf32.tf32.f32 "
                    "{%0,%1,%2,%3}, {%4,%5,%6,%7}, {%8,%9}, {%0,%1,%2,%3};"
                    : "+f"(c[0]), "+f"(c[1]), "+f"(c[2]), "+f"(c[3])
                    : "r"(A0), "r"(A1), "r"(A2), "r"(A3), "r"(B0), "r"(B1));
            }
        }
    }

    int base = isUser ? 0 : NU;
    int n0 = nodeBase0 + warpNode + gid;
    int n1 = n0 + 8;
    if (n0 < Ncnt) {
        __half* orow = g_h1h + (size_t)(base + n0) * CM;
        #pragma unroll
        for (int nt = 0; nt < 8; nt++) {
            int col = nt * 8 + 2 * tig;
            __half2 p = __floats2half2_rn(acc[nt * 4 + 0] + cvec[col],
                                          acc[nt * 4 + 1] + cvec[col + 1]);
            *((__half2*)(orow + col)) = p;
        }
    }
    if (n1 < Ncnt) {
        __half* orow = g_h1h + (size_t)(base + n1) * CM;
        #pragma unroll
        for (int nt = 0; nt < 8; nt++) {
            int col = nt * 8 + 2 * tig;
            __half2 p = __floats2half2_rn(acc[nt * 4 + 2] + cvec[col],
                                          acc[nt * 4 + 3] + cvec[col + 1]);
            *((__half2*)(orow + col)) = p;
        }
    }
}

// ---------------- graph preprocessing ----------------
__global__ void k_edge1(const int* __restrict__ ei32, const float* __restrict__ ew) {
    int t = blockIdx.x * blockDim.x + threadIdx.x;
    int e = 2 * t;
    if (e >= NE) return;
    int d0, d1;
    if (g_is64) {
        int4 v = *(const int4*)(ei32 + 2 * (NE + e));
        d0 = v.x; d1 = v.z;
    } else {
        int2 v = *(const int2*)(ei32 + NE + e);
        d0 = v.x; d1 = v.y;
    }
    float2 w = *(const float2*)(ew + e);
    ull add0 = (1ull << 40) | (ull)__float2uint_rn(w.x * 1048576.0f);
    ull add1 = (1ull << 40) | (ull)__float2uint_rn(w.y * 1048576.0f);
    atomicAdd(&g_pack[d0], add0);
    atomicAdd(&g_pack[d1], add1);
}

__global__ void k_scan1() {
    __shared__ int sh[SCAN_BLK];
    int t = threadIdx.x;
    int gid = blockIdx.x * SCAN_BLK + t;
    int v = 0;
    float deg = 1.0f;
    if (gid < NN) {
        ull p = g_pack[gid];
        v = (int)(p >> 40);
        deg = 1.0f + (float)(p & 0xFFFFFFFFFFull) * (1.0f / 1048576.0f);
    }
    sh[t] = v;
    __syncthreads();
    for (int off = 1; off < SCAN_BLK; off <<= 1) {
        int x = (t >= off) ? sh[t - off] : 0;
        __syncthreads();
        sh[t] += x;
        __syncthreads();
    }
    if (gid < NN) {
        g_rowstart[gid] = sh[t] - v;
        g_dinv[gid] = (deg > 0.0f) ? rsqrtf(deg) : 0.0f;
    }
    if (t == SCAN_BLK - 1) g_bsum[blockIdx.x] = sh[t];
}

__global__ void k_scan2() {
    __shared__ int sh[SCAN_BLK];
    int t = threadIdx.x;
    int v = (t < NSCAN_BLKS) ? g_bsum[t] : 0;
    sh[t] = v;
    __syncthreads();
    for (int off = 1; off < SCAN_BLK; off <<= 1) {
        int x = (t >= off) ? sh[t - off] : 0;
        __syncthreads();
        sh[t] += x;
        __syncthreads();
    }
    if (t < NSCAN_BLKS) g_bsum[t] = sh[t] - v;
}

__global__ void k_scan3() {
    int i = blockIdx.x * blockDim.x + threadIdx.x;
    if (i < NN) {
        int rs = g_rowstart[i] + g_bsum[i >> 10];
        g_rowstart[i] = rs;
        g_cursor[i] = rs;
    }
    if (i == 0) g_rowstart[NN] = NE;
}

// ---------------- scatter: CSR (src, norm) ----------------
__global__ void k_scatter(const int* __restrict__ ei32, const float* __restrict__ ew) {
    int e = blockIdx.x * blockDim.x + threadIdx.x;
    if (e >= NE) return;
    int s, d;
    if (g_is64) { s = ei32[2 * e]; d = ei32[2 * (NE + e)]; }
    else        { s = ei32[e];     d = ei32[NE + e]; }
    float nrm = g_dinv[s] * ew[e] * g_dinv[d];
    int pos = atomicAdd(&g_cursor[d], 1);
    g_csr[pos] = (ull)(unsigned)s | ((ull)__float_as_uint(nrm) << 32);
}

// ---------------- gather1: 8-edge-deep pipeline, fp16 h1 -> fp16 z1 ----------------
__global__ void k_gather1(const float* __restrict__ b1) {
    int t = threadIdx.x;
    int node = blockIdx.x * (blockDim.x >> 5) + (t >> 5);
    int lane = t & 31;
    if (node >= NN) return;

    const unsigned* h = (const unsigned*)g_h1h;    // half2 per entry; 32 per row
    float dv = g_dinv[node];
    float sw = dv * dv;
    unsigned us = h[(size_t)node * 32 + lane];
    float2 fs = __half22float2(*(const __half2*)&us);
    ull acc; PACKF2(acc, sw * fs.x, sw * fs.y);

    int e = g_rowstart[node], end = g_rowstart[node + 1];
    for (; e + 8 <= end; e += 8) {
        ull p[8];
        #pragma unroll
        for (int j = 0; j < 8; j++) p[j] = g_csr[e + j];
        unsigned u[8];
        #pragma unroll
        for (int j = 0; j < 8; j++) u[j] = h[(size_t)(unsigned)p[j] * 32 + lane];
        #pragma unroll
        for (int j = 0; j < 8; j++) {
            float2 f = __half22float2(*(const __half2*)&u[j]);
            ull v; PACKF2(v, f.x, f.y);
            ull q; PACK2(q, __uint_as_float((unsigned)(p[j] >> 32)));
            FMA2(acc, q, v, acc);
        }
    }
    if (e + 4 <= end) {
        ull p[4];
        #pragma unroll
        for (int j = 0; j < 4; j++) p[j] = g_csr[e + j];
        unsigned u[4];
        #pragma unroll
        for (int j = 0; j < 4; j++) u[j] = h[(size_t)(unsigned)p[j] * 32 + lane];
        #pragma unroll
        for (int j = 0; j < 4; j++) {
            float2 f = __half22float2(*(const __half2*)&u[j]);
            ull v; PACKF2(v, f.x, f.y);
            ull q; PACK2(q, __uint_as_float((unsigned)(p[j] >> 32)));
            FMA2(acc, q, v, acc);
        }
        e += 4;
    }
    for (; e < end; e++) {
        ull p = g_csr[e];
        unsigned u = h[(size_t)(unsigned)p * 32 + lane];
        float2 f = __half22float2(*(const __half2*)&u);
        ull v; PACKF2(v, f.x, f.y);
        ull q; PACK2(q, __uint_as_float((unsigned)(p >> 32)));
        FMA2(acc, q, v, acc);
    }
    float ax, ay; UNPACK2(ax, ay, acc);
    float2 bb = ((const float2*)b1)[lane];
    __half2 hz = __floats2half2_rn(fmaxf(ax + bb.x, 0.0f), fmaxf(ay + bb.y, 0.0f));
    ((__half2*)(g_z1h + (size_t)node * CM))[lane] = hz;
}

// ---------------- xform: h2 = z1(fp16) @ W2 (per-thread node, f32x2, fp16 output) ----------------
#define XF_THREADS 256
__global__ __launch_bounds__(XF_THREADS)
void k_xform(const float* __restrict__ W2) {
    __shared__ ulonglong2 sW2[CM * 8];   // 8 KB
    sW2[threadIdx.x]       = ((const ulonglong2*)W2)[threadIdx.x];
    sW2[threadIdx.x + 256] = ((const ulonglong2*)W2)[threadIdx.x + 256];
    __syncthreads();

    int node = blockIdx.x * XF_THREADS + threadIdx.x;
    if (node >= NN) return;
    const uint4* xr = (const uint4*)(g_z1h + (size_t)node * CM);

    ull acc[16];
    #pragma unroll
    for (int i = 0; i < 16; i++) acc[i] = 0ull;

    #pragma unroll
    for (int kb = 0; kb < CM; kb += 16) {
        uint4 ra = xr[kb >> 3];
        uint4 rb = xr[(kb >> 3) + 1];
        unsigned uu[8] = {ra.x, ra.y, ra.z, ra.w, rb.x, rb.y, rb.z, rb.w};
        float x[16];
        #pragma unroll
        for (int j = 0; j < 8; j++) {
            float2 f = __half22float2(*(const __half2*)&uu[j]);
            x[2 * j] = f.x; x[2 * j + 1] = f.y;
        }
        #pragma unroll
        for (int k = 0; k < 16; k++) {
            ull bk; PACK2(bk, x[k]);
            #pragma unroll
            for (int c4 = 0; c4 < 8; c4++) {
                ulonglong2 w = sW2[(kb + k) * 8 + c4];
                FMA2(acc[2 * c4],     bk, w.x, acc[2 * c4]);
                FMA2(acc[2 * c4 + 1], bk, w.y, acc[2 * c4 + 1]);
            }
        }
    }
    uint2* orow = (uint2*)(g_h2h + (size_t)node * OD);
    #pragma unroll
    for (int c4 = 0; c4 < 8; c4++) {
        float a, b, c, d;
        UNPACK2(a, b, acc[2 * c4]);
        UNPACK2(c, d, acc[2 * c4 + 1]);
        __half2 p0 = __floats2half2_rn(a, b);
        __half2 p1 = __floats2half2_rn(c, d);
        uint2 ov; ov.x = *(unsigned*)&p0; ov.y = *(unsigned*)&p1;
        orow[c4] = ov;
    }
}

// ---------------- gather2: dual half-warp, 4 edges per half in flight ----------------
__global__ void k_gather2(const float* __restrict__ b2, float* __restrict__ out) {
    int t = threadIdx.x;
    int node = blockIdx.x * (blockDim.x >> 5) + (t >> 5);
    int lane = t & 31;
    if (node >= NN) return;
    int half = lane >> 4;
    int c = lane & 15;

    const unsigned* h = (const unsigned*)g_h2h;    // half2 per entry; 16 per row
    ull acc = 0ull;
    if (half == 0) {
        float dv = g_dinv[node];
        float sw = dv * dv;
        unsigned us = h[(size_t)node * 16 + c];
        float2 fs = __half22float2(*(const __half2*)&us);
        PACKF2(acc, sw * fs.x, sw * fs.y);
    }
    int beg = g_rowstart[node], end = g_rowstart[node + 1];
    int e = beg + half;
    for (; e + 6 < end; e += 8) {               // 4 edges per half in flight
        ull p[4];
        #pragma unroll
        for (int j = 0; j < 4; j++) p[j] = g_csr[e + 2 * j];
        unsigned u[4];
        #pragma unroll
        for (int j = 0; j < 4; j++) u[j] = h[(size_t)(unsigned)p[j] * 16 + c];
        #pragma unroll
        for (int j = 0; j < 4; j++) {
            float2 f = __half22float2(*(const __half2*)&u[j]);
            ull v; PACKF2(v, f.x, f.y);
            ull q; PACK2(q, __uint_as_float((unsigned)(p[j] >> 32)));
            FMA2(acc, q, v, acc);
        }
    }
    for (; e < end; e += 2) {
        ull p = g_csr[e];
        unsigned u = h[(size_t)(unsigned)p * 16 + c];
        float2 f = __half22float2(*(const __half2*)&u);
        ull v; PACKF2(v, f.x, f.y);
        ull q; PACK2(q, __uint_as_float((unsigned)(p >> 32)));
        FMA2(acc, q, v, acc);
    }
    float ax, ay; UNPACK2(ax, ay, acc);
    ax += __shfl_xor_sync(0xffffffffu, ax, 16);
    ay += __shfl_xor_sync(0xffffffffu, ay, 16);
    if (half == 0) {
        float2 bb = ((const float2*)b2)[c];
        float2 ov; ov.x = ax + bb.x; ov.y = ay + bb.y;
        ((float2*)(out + (size_t)node * OD))[c] = ov;
    }
}

// ---------------- launch ----------------
extern "C" void kernel_launch(void* const* d_in, const int* in_sizes, int n_in,
                              void* d_out, int out_size) {
    const float* ut = (const float*)d_in[0];
    const float* it = (const float*)d_in[1];
    const int*   ei = (const int*)d_in[2];
    const float* ew = (const float*)d_in[3];
    const float* Wu = (const float*)d_in[4];
    const float* bu = (const float*)d_in[5];
    const float* Wi = (const float*)d_in[6];
    const float* bi = (const float*)d_in[7];
    const float* W1 = (const float*)d_in[8];
    const float* b1 = (const float*)d_in[9];
    const float* W2 = (const float*)d_in[10];
    const float* b2 = (const float*)d_in[11];
    float*       out = (float*)d_out;

    cudaFuncSetAttribute(k_embed, cudaFuncAttributeMaxDynamicSharedMemorySize, EB_SMEM);

    int userBlocks = (NU + EB_NODES - 1) / EB_NODES;    // 782
    int itemBlocks = (NI + EB_NODES - 1) / EB_NODES;    // 782

    k_detect<<<1, 256>>>(ei);                                              // 1
    k_init<<<(NN + 255) / 256, 256>>>();                                   // 2
    k_wcomb<<<(UD * CM + ID * CM + 2 * CM + 127) / 128, 128>>>(Wu, bu, Wi, bi, W1); // 3
    k_embed<<<userBlocks + itemBlocks, EB_THREADS, EB_SMEM>>>(ut, it, userBlocks);  // 4 <- profiled
    k_edge1<<<(NE / 2 + 255) / 256, 256>>>(ei, ew);                        // 5
    k_scan1<<<NSCAN_BLKS, SCAN_BLK>>>();                                   // 6
    k_scan2<<<1, SCAN_BLK>>>();                                            // 7
    k_scan3<<<(NN + 255) / 256, 256>>>();                                  // 8
    k_scatter<<<(NE + 255) / 256, 256>>>(ei, ew);                          // 9
    k_gather1<<<NN / 8, 256>>>(b1);                                        // 10
    k_xform<<<(NN + XF_THREADS - 1) / XF_THREADS, XF_THREADS>>>(W2);       // 11
    k_gather2<<<NN / 8, 256>>>(b2, out);                                   // 12
}

// round 17
// speedup vs baseline: 1.9236x; 1.0257x over previous
#include <cuda_runtime.h>
#include <cuda_bf16.h>
#include <cuda_fp16.h>
#include <stdint.h>

typedef unsigned long long ull;

#define NU 100000
#define NI 100000
#define NN 200000
#define NE 4000000
#define UD 256
#define ID 128
#define CM 64
#define OD 32
#define SCAN_BLK 1024
#define NSCAN_BLKS ((NN + SCAN_BLK - 1) / SCAN_BLK)

// f32x2 packed helpers
#define FMA2(d, a, b, c) asm("fma.rn.f32x2 %0, %1, %2, %3;" : "=l"(d) : "l"(a), "l"(b), "l"(c))
#define PACK2(d, x)      asm("mov.b64 %0, {%1, %1};" : "=l"(d) : "f"(x))
#define PACKF2(d, lo, hi) asm("mov.b64 %0, {%1, %2};" : "=l"(d) : "f"(lo), "f"(hi))
#define UNPACK2(lo, hi, v) asm("mov.b64 {%0, %1}, %2;" : "=f"(lo), "=f"(hi) : "l"(v))

// ---------------- scratch ----------------
__device__ ull   g_pack[NN];              // count<<40 | deg fixed-point (2^-20)
__device__ float g_dinv[NN];
__device__ int   g_rowstart[NN + 1];
__device__ int   g_cursor[NN];
__device__ int   g_bsum[SCAN_BLK];
__device__ ull   g_csr[NE];               // packed: lo32 = src, hi32 = norm bits
__device__ float g_WuW1[UD * CM];         // tf32-rounded
__device__ float g_WiW1[ID * CM];         // tf32-rounded
__device__ float g_cu[CM];
__device__ float g_ci[CM];
__device__ __half g_h1h[(size_t)NN * CM]; // 25.6 MB embed output (fp16)
__device__ __half g_z1h[(size_t)NN * CM]; // 25.6 MB relu(agg1+b1) (fp16)
__device__ __half g_h2h[(size_t)NN * OD]; // 12.8 MB z1 @ W2 (fp16)
__device__ int   g_is64;

// ---------------- dtype detection ----------------
__global__ void k_detect(const int* __restrict__ ei32) {
    __shared__ int any_nonzero;
    if (threadIdx.x == 0) any_nonzero = 0;
    __syncthreads();
    for (int i = 2 * threadIdx.x + 1; i < 4096; i += 2 * blockDim.x)
        if (ei32[i] != 0) any_nonzero = 1;
    __syncthreads();
    if (threadIdx.x == 0) g_is64 = any_nonzero ? 0 : 1;
}

__global__ void k_init() {
    int i = blockIdx.x * blockDim.x + threadIdx.x;
    if (i < NN) g_pack[i] = 0ull;
}

// ---------------- weight folding (W outputs rounded to tf32) ----------------
__global__ void k_wcomb(const float* __restrict__ Wu, const float* __restrict__ bu,
                        const float* __restrict__ Wi, const float* __restrict__ bi,
                        const float* __restrict__ W1) {
    int idx = blockIdx.x * blockDim.x + threadIdx.x;
    const int TOT_U = UD * CM, TOT_I = ID * CM;
    if (idx < TOT_U) {
        int k = idx / CM, c = idx % CM;
        float a = 0.f;
        #pragma unroll
        for (int j = 0; j < CM; j++) a += Wu[k * CM + j] * W1[j * CM + c];
        unsigned u; asm("cvt.rna.tf32.f32 %0, %1;" : "=r"(u) : "f"(a));
        g_WuW1[idx] = __uint_as_float(u);
    } else if (idx < TOT_U + TOT_I) {
        int r = idx - TOT_U;
        int k = r / CM, c = r % CM;
        float a = 0.f;
        #pragma unroll
        for (int j = 0; j < CM; j++) a += Wi[k * CM + j] * W1[j * CM + c];
        unsigned u; asm("cvt.rna.tf32.f32 %0, %1;" : "=r"(u) : "f"(a));
        g_WiW1[r] = __uint_as_float(u);
    } else if (idx < TOT_U + TOT_I + 2 * CM) {
        int r = idx - TOT_U - TOT_I;
        if (r < CM) {
            float a = 0.f;
            #pragma unroll
            for (int j = 0; j < CM; j++) a += bu[j] * W1[j * CM + r];
            g_cu[r] = a;
        } else {
            int c = r - CM;
            float a = 0.f;
            #pragma unroll
            for (int j = 0; j < CM; j++) a += bi[j] * W1[j * CM + c];
            g_ci[c] = a;
        }
    }
}

// ---------------- embed: tf32 MMA + cp.async double-buffered X staging ----------------
#define EB_THREADS 256
#define EB_NODES   128
#define KCH 32
#define SWS 72
#define XS  36
#define XBUF (EB_NODES * XS)                       // floats per X buffer (4608)
#define EB_SMEM ((UD * SWS + 2 * XBUF) * 4)        // 110592 B
__device__ __forceinline__ void cpasync16(uint32_t dst, const void* src) {
    asm volatile("cp.async.cg.shared.global [%0], [%1], 16;" :: "r"(dst), "l"(src));
}
__global__ __launch_bounds__(EB_THREADS)
void k_embed(const float* __restrict__ ut, const float* __restrict__ it, int userBlocks) {
    extern __shared__ float sm[];
    bool isUser = (int)blockIdx.x < userBlocks;
    int blockLocal = isUser ? blockIdx.x : blockIdx.x - userBlocks;
    int K = isUser ? UD : ID;
    int Ncnt = isUser ? NU : NI;
    const float* W = isUser ? g_WuW1 : g_WiW1;
    const float* cvec = isUser ? g_cu : g_ci;
    const float* inp = isUser ? ut : it;
    int nodeBase0 = blockLocal * EB_NODES;
    float* sW = sm;                                // [K][SWS]
    float* sX = sm + K * SWS;                      // 2 buffers of [128][XS]
    uint32_t sXaddr = (uint32_t)__cvta_generic_to_shared(sX);

    int tid = threadIdx.x;
    for (int i = tid; i < K * (CM / 4); i += EB_THREADS) {
        int r = i >> 4, q = i & 15;
        float4 v = ((const float4*)(W + r * CM))[q];
        *((float4*)(sW + r * SWS + q * 4)) = v;
    }

    int wid = tid >> 5, lane = tid & 31;
    int gid = lane >> 2, tig = lane & 3;
    int warpNode = wid * 16;

    {
        #pragma unroll
        for (int i = 0; i < 4; i++) {
            int idx = tid + i * EB_THREADS;
            int nd = idx >> 3, q = idx & 7;
            int gn = nodeBase0 + nd; if (gn >= Ncnt) gn = Ncnt - 1;
            cpasync16(sXaddr + (nd * XS + q * 4) * 4,
                      inp + (size_t)gn * K + q * 4);
        }
        asm volatile("cp.async.commit_group;");
    }

    float acc[32];
    #pragma unroll
    for (int i = 0; i < 32; i++) acc[i] = 0.f;

    int nCh = K / KCH;
    for (int ci = 0; ci < nCh; ci++) {
        int kb = ci * KCH;
        __syncthreads();
        if (ci + 1 < nCh) {
            uint32_t dstBase = sXaddr + ((ci + 1) & 1) * XBUF * 4;
            #pragma unroll
            for (int i = 0; i < 4; i++) {
                int idx = tid + i * EB_THREADS;
                int nd = idx >> 3, q = idx & 7;
                int gn = nodeBase0 + nd; if (gn >= Ncnt) gn = Ncnt - 1;
                cpasync16(dstBase + (nd * XS + q * 4) * 4,
                          inp + (size_t)gn * K + kb + KCH + q * 4);
            }
            asm volatile("cp.async.commit_group;");
            asm volatile("cp.async.wait_group 1;");
        } else {
            asm volatile("cp.async.wait_group 0;");
        }
        __syncthreads();

        const float* sXc = sX + (ci & 1) * XBUF;
        #pragma unroll
        for (int ks = 0; ks < 4; ks++) {
            int klo = ks * 8;
            float a0f = sXc[(warpNode + gid) * XS + klo + tig];
            float a1f = sXc[(warpNode + gid + 8) * XS + klo + tig];
            float a2f = sXc[(warpNode + gid) * XS + klo + tig + 4];
            float a3f = sXc[(warpNode + gid + 8) * XS + klo + tig + 4];
            unsigned A0, A1, A2, A3;
            asm("cvt.rna.tf32.f32 %0, %1;" : "=r"(A0) : "f"(a0f));
            asm("cvt.rna.tf32.f32 %0, %1;" : "=r"(A1) : "f"(a1f));
            asm("cvt.rna.tf32.f32 %0, %1;" : "=r"(A2) : "f"(a2f));
            asm("cvt.rna.tf32.f32 %0, %1;" : "=r"(A3) : "f"(a3f));
            const float* wk0 = sW + (size_t)(kb + klo + tig) * SWS;
            const float* wk1 = sW + (size_t)(kb + klo + tig + 4) * SWS;
            #pragma unroll
            for (int nt = 0; nt < 8; nt++) {
                unsigned B0 = __float_as_uint(wk0[nt * 8 + gid]);
                unsigned B1 = __float_as_uint(wk1[nt * 8 + gid]);
                float* c = acc + nt * 4;
                asm volatile(
                    "mma.sync.aligned.m16n8k8.row.col.f32.tf32.tf32.f32 "
                    "{%0,%1,%2,%3}, {%4,%5,%6,%7}, {%8,%9}, {%0,%1,%2,%3};"
                    : "+f"(c[0]), "+f"(c[1]), "+f"(c[2]), "+f"(c[3])
                    : "r"(A0), "r"(A1), "r"(A2), "r"(A3), "r"(B0), "r"(B1));
            }
        }
    }

    int base = isUser ? 0 : NU;
    int n0 = nodeBase0 + warpNode + gid;
    int n1 = n0 + 8;
    if (n0 < Ncnt) {
        __half* orow = g_h1h + (size_t)(base + n0) * CM;
        #pragma unroll
        for (int nt = 0; nt < 8; nt++) {
            int col = nt * 8 + 2 * tig;
            __half2 p = __floats2half2_rn(acc[nt * 4 + 0] + cvec[col],
                                          acc[nt * 4 + 1] + cvec[col + 1]);
            *((__half2*)(orow + col)) = p;
        }
    }
    if (n1 < Ncnt) {
        __half* orow = g_h1h + (size_t)(base + n1) * CM;
        #pragma unroll
        for (int nt = 0; nt < 8; nt++) {
            int col = nt * 8 + 2 * tig;
            __half2 p = __floats2half2_rn(acc[nt * 4 + 2] + cvec[col],
                                          acc[nt * 4 + 3] + cvec[col + 1]);
            *((__half2*)(orow + col)) = p;
        }
    }
}

// ---------------- graph preprocessing ----------------
__global__ void k_edge1(const int* __restrict__ ei32, const float* __restrict__ ew) {
    int t = blockIdx.x * blockDim.x + threadIdx.x;
    int e = 2 * t;
    if (e >= NE) return;
    int d0, d1;
    if (g_is64) {
        int4 v = *(const int4*)(ei32 + 2 * (NE + e));
        d0 = v.x; d1 = v.z;
    } else {
        int2 v = *(const int2*)(ei32 + NE + e);
        d0 = v.x; d1 = v.y;
    }
    float2 w = *(const float2*)(ew + e);
    ull add0 = (1ull << 40) | (ull)__float2uint_rn(w.x * 1048576.0f);
    ull add1 = (1ull << 40) | (ull)__float2uint_rn(w.y * 1048576.0f);
    atomicAdd(&g_pack[d0], add0);
    atomicAdd(&g_pack[d1], add1);
}

__global__ void k_scan1() {
    __shared__ int sh[SCAN_BLK];
    int t = threadIdx.x;
    int gid = blockIdx.x * SCAN_BLK + t;
    int v = 0;
    float deg = 1.0f;
    if (gid < NN) {
        ull p = g_pack[gid];
        v = (int)(p >> 40);
        deg = 1.0f + (float)(p & 0xFFFFFFFFFFull) * (1.0f / 1048576.0f);
    }
    sh[t] = v;
    __syncthreads();
    for (int off = 1; off < SCAN_BLK; off <<= 1) {
        int x = (t >= off) ? sh[t - off] : 0;
        __syncthreads();
        sh[t] += x;
        __syncthreads();
    }
    if (gid < NN) {
        g_rowstart[gid] = sh[t] - v;
        g_dinv[gid] = (deg > 0.0f) ? rsqrtf(deg) : 0.0f;
    }
    if (t == SCAN_BLK - 1) g_bsum[blockIdx.x] = sh[t];
}

__global__ void k_scan2() {
    __shared__ int sh[SCAN_BLK];
    int t = threadIdx.x;
    int v = (t < NSCAN_BLKS) ? g_bsum[t] : 0;
    sh[t] = v;
    __syncthreads();
    for (int off = 1; off < SCAN_BLK; off <<= 1) {
        int x = (t >= off) ? sh[t - off] : 0;
        __syncthreads();
        sh[t] += x;
        __syncthreads();
    }
    if (t < NSCAN_BLKS) g_bsum[t] = sh[t] - v;
}

__global__ void k_scan3() {
    int i = blockIdx.x * blockDim.x + threadIdx.x;
    if (i < NN) {
        int rs = g_rowstart[i] + g_bsum[i >> 10];
        g_rowstart[i] = rs;
        g_cursor[i] = rs;
    }
    if (i == 0) g_rowstart[NN] = NE;
}

// ---------------- scatter: CSR (src, norm) ----------------
__global__ void k_scatter(const int* __restrict__ ei32, const float* __restrict__ ew) {
    int e = blockIdx.x * blockDim.x + threadIdx.x;
    if (e >= NE) return;
    int s, d;
    if (g_is64) { s = ei32[2 * e]; d = ei32[2 * (NE + e)]; }
    else        { s = ei32[e];     d = ei32[NE + e]; }
    float nrm = g_dinv[s] * ew[e] * g_dinv[d];
    int pos = atomicAdd(&g_cursor[d], 1);
    g_csr[pos] = (ull)(unsigned)s | ((ull)__float_as_uint(nrm) << 32);
}

// ---------------- gather1: 8-edge-deep pipeline, fp16 h1 -> fp16 z1 ----------------
__global__ void k_gather1(const float* __restrict__ b1) {
    int t = threadIdx.x;
    int node = blockIdx.x * (blockDim.x >> 5) + (t >> 5);
    int lane = t & 31;
    if (node >= NN) return;

    const unsigned* h = (const unsigned*)g_h1h;    // half2 per entry; 32 per row
    float dv = g_dinv[node];
    float sw = dv * dv;
    unsigned us = h[(size_t)node * 32 + lane];
    float2 fs = __half22float2(*(const __half2*)&us);
    ull acc; PACKF2(acc, sw * fs.x, sw * fs.y);

    int e = g_rowstart[node], end = g_rowstart[node + 1];
    for (; e + 8 <= end; e += 8) {
        ull p[8];
        #pragma unroll
        for (int j = 0; j < 8; j++) p[j] = g_csr[e + j];
        unsigned u[8];
        #pragma unroll
        for (int j = 0; j < 8; j++) u[j] = h[(size_t)(unsigned)p[j] * 32 + lane];
        #pragma unroll
        for (int j = 0; j < 8; j++) {
            float2 f = __half22float2(*(const __half2*)&u[j]);
            ull v; PACKF2(v, f.x, f.y);
            ull q; PACK2(q, __uint_as_float((unsigned)(p[j] >> 32)));
            FMA2(acc, q, v, acc);
        }
    }
    if (e + 4 <= end) {
        ull p[4];
        #pragma unroll
        for (int j = 0; j < 4; j++) p[j] = g_csr[e + j];
        unsigned u[4];
        #pragma unroll
        for (int j = 0; j < 4; j++) u[j] = h[(size_t)(unsigned)p[j] * 32 + lane];
        #pragma unroll
        for (int j = 0; j < 4; j++) {
            float2 f = __half22float2(*(const __half2*)&u[j]);
            ull v; PACKF2(v, f.x, f.y);
            ull q; PACK2(q, __uint_as_float((unsigned)(p[j] >> 32)));
            FMA2(acc, q, v, acc);
        }
        e += 4;
    }
    for (; e < end; e++) {
        ull p = g_csr[e];
        unsigned u = h[(size_t)(unsigned)p * 32 + lane];
        float2 f = __half22float2(*(const __half2*)&u);
        ull v; PACKF2(v, f.x, f.y);
        ull q; PACK2(q, __uint_as_float((unsigned)(p >> 32)));
        FMA2(acc, q, v, acc);
    }
    float ax, ay; UNPACK2(ax, ay, acc);
    float2 bb = ((const float2*)b1)[lane];
    __half2 hz = __floats2half2_rn(fmaxf(ax + bb.x, 0.0f), fmaxf(ay + bb.y, 0.0f));
    ((__half2*)(g_z1h + (size_t)node * CM))[lane] = hz;
}

// ---------------- xform: h2 = z1(fp16) @ W2 (per-thread node, f32x2, fp16 output) ----------------
#define XF_THREADS 256
__global__ __launch_bounds__(XF_THREADS)
void k_xform(const float* __restrict__ W2) {
    __shared__ ulonglong2 sW2[CM * 8];   // 8 KB
    sW2[threadIdx.x]       = ((const ulonglong2*)W2)[threadIdx.x];
    sW2[threadIdx.x + 256] = ((const ulonglong2*)W2)[threadIdx.x + 256];
    __syncthreads();

    int node = blockIdx.x * XF_THREADS + threadIdx.x;
    if (node >= NN) return;
    const uint4* xr = (const uint4*)(g_z1h + (size_t)node * CM);

    ull acc[16];
    #pragma unroll
    for (int i = 0; i < 16; i++) acc[i] = 0ull;

    #pragma unroll
    for (int kb = 0; kb < CM; kb += 16) {
        uint4 ra = xr[kb >> 3];
        uint4 rb = xr[(kb >> 3) + 1];
        unsigned uu[8] = {ra.x, ra.y, ra.z, ra.w, rb.x, rb.y, rb.z, rb.w};
        float x[16];
        #pragma unroll
        for (int j = 0; j < 8; j++) {
            float2 f = __half22float2(*(const __half2*)&uu[j]);
            x[2 * j] = f.x; x[2 * j + 1] = f.y;
        }
        #pragma unroll
        for (int k = 0; k < 16; k++) {
            ull bk; PACK2(bk, x[k]);
            #pragma unroll
            for (int c4 = 0; c4 < 8; c4++) {
                ulonglong2 w = sW2[(kb + k) * 8 + c4];
                FMA2(acc[2 * c4],     bk, w.x, acc[2 * c4]);
                FMA2(acc[2 * c4 + 1], bk, w.y, acc[2 * c4 + 1]);
            }
        }
    }
    uint2* orow = (uint2*)(g_h2h + (size_t)node * OD);
    #pragma unroll
    for (int c4 = 0; c4 < 8; c4++) {
        float a, b, c, d;
        UNPACK2(a, b, acc[2 * c4]);
        UNPACK2(c, d, acc[2 * c4 + 1]);
        __half2 p0 = __floats2half2_rn(a, b);
        __half2 p1 = __floats2half2_rn(c, d);
        uint2 ov; ov.x = *(unsigned*)&p0; ov.y = *(unsigned*)&p1;
        orow[c4] = ov;
    }
}

// ---------------- gather2: dual half-warp, 4 edges per half in flight ----------------
__global__ void k_gather2(const float* __restrict__ b2, float* __restrict__ out) {
    int t = threadIdx.x;
    int node = blockIdx.x * (blockDim.x >> 5) + (t >> 5);
    int lane = t & 31;
    if (node >= NN) return;
    int half = lane >> 4;
    int c = lane & 15;

    const unsigned* h = (const unsigned*)g_h2h;    // half2 per entry; 16 per row
    ull acc = 0ull;
    if (half == 0) {
        float dv = g_dinv[node];
        float sw = dv * dv;
        unsigned us = h[(size_t)node * 16 + c];
        float2 fs = __half22float2(*(const __half2*)&us);
        PACKF2(acc, sw * fs.x, sw * fs.y);
    }
    int beg = g_rowstart[node], end = g_rowstart[node + 1];
    int e = beg + half;
    for (; e + 6 < end; e += 8) {
        ull p[4];
        #pragma unroll
        for (int j = 0; j < 4; j++) p[j] = g_csr[e + 2 * j];
        unsigned u[4];
        #pragma unroll
        for (int j = 0; j < 4; j++) u[j] = h[(size_t)(unsigned)p[j] * 16 + c];
        #pragma unroll
        for (int j = 0; j < 4; j++) {
            float2 f = __half22float2(*(const __half2*)&u[j]);
            ull v; PACKF2(v, f.x, f.y);
            ull q; PACK2(q, __uint_as_float((unsigned)(p[j] >> 32)));
            FMA2(acc, q, v, acc);
        }
    }
    for (; e < end; e += 2) {
        ull p = g_csr[e];
        unsigned u = h[(size_t)(unsigned)p * 16 + c];
        float2 f = __half22float2(*(const __half2*)&u);
        ull v; PACKF2(v, f.x, f.y);
        ull q; PACK2(q, __uint_as_float((unsigned)(p >> 32)));
        FMA2(acc, q, v, acc);
    }
    float ax, ay; UNPACK2(ax, ay, acc);
    ax += __shfl_xor_sync(0xffffffffu, ax, 16);
    ay += __shfl_xor_sync(0xffffffffu, ay, 16);
    if (half == 0) {
        float2 bb = ((const float2*)b2)[c];
        float2 ov; ov.x = ax + bb.x; ov.y = ay + bb.y;
        ((float2*)(out + (size_t)node * OD))[c] = ov;
    }
}

// ---------------- launch (stream-forked: embed overlaps edge chain) ----------------
extern "C" void kernel_launch(void* const* d_in, const int* in_sizes, int n_in,
                              void* d_out, int out_size) {
    const float* ut = (const float*)d_in[0];
    const float* it = (const float*)d_in[1];
    const int*   ei = (const int*)d_in[2];
    const float* ew = (const float*)d_in[3];
    const float* Wu = (const float*)d_in[4];
    const float* bu = (const float*)d_in[5];
    const float* Wi = (const float*)d_in[6];
    const float* bi = (const float*)d_in[7];
    const float* W1 = (const float*)d_in[8];
    const float* b1 = (const float*)d_in[9];
    const float* W2 = (const float*)d_in[10];
    const float* b2 = (const float*)d_in[11];
    float*       out = (float*)d_out;

    static cudaStream_t s2 = nullptr;
    static cudaEvent_t evFork = nullptr, evJoin = nullptr;
    if (!s2) {
        cudaStreamCreateWithFlags(&s2, cudaStreamNonBlocking);
        cudaEventCreateWithFlags(&evFork, cudaEventDisableTiming);
        cudaEventCreateWithFlags(&evJoin, cudaEventDisableTiming);
        cudaFuncSetAttribute(k_embed, cudaFuncAttributeMaxDynamicSharedMemorySize, EB_SMEM);
    }

    int userBlocks = (NU + EB_NODES - 1) / EB_NODES;    // 782
    int itemBlocks = (NI + EB_NODES - 1) / EB_NODES;    // 782

    // main stream (0): detect, init, then edge chain
    k_detect<<<1, 256>>>(ei);                                              // 1
    k_init<<<(NN + 255) / 256, 256>>>();                                   // 2

    // fork: branch A (wcomb -> embed) on s2, overlapping branch B on stream 0
    cudaEventRecord(evFork, 0);
    cudaStreamWaitEvent(s2, evFork, 0);
    k_wcomb<<<(UD * CM + ID * CM + 2 * CM + 127) / 128, 128, 0, s2>>>(Wu, bu, Wi, bi, W1); // 3
    k_embed<<<userBlocks + itemBlocks, EB_THREADS, EB_SMEM, s2>>>(ut, it, userBlocks);     // 4 <- profiled

    // branch B on stream 0
    k_edge1<<<(NE / 2 + 255) / 256, 256>>>(ei, ew);                        // 5
    k_scan1<<<NSCAN_BLKS, SCAN_BLK>>>();                                   // 6
    k_scan2<<<1, SCAN_BLK>>>();                                            // 7
    k_scan3<<<(NN + 255) / 256, 256>>>();                                  // 8
    k_scatter<<<(NE + 255) / 256, 256>>>(ei, ew);                          // 9

    // join: gather1 needs both branches
    cudaEventRecord(evJoin, s2);
    cudaStreamWaitEvent(0, evJoin, 0);
    k_gather1<<<NN / 8, 256>>>(b1);                                        // 10
    k_xform<<<(NN + XF_THREADS - 1) / XF_THREADS, XF_THREADS>>>(W2);       // 11
    k_gather2<<<NN / 8, 256>>>(b2, out);                                   // 12
}